// round 11
// baseline (speedup 1.0000x reference)
#include <cuda_runtime.h>
#include <cuda_fp16.h>
#include <math.h>
#include <stdint.h>

namespace cfg {
constexpr int B = 2, S = 1024, H = 1024;
constexpr int NH = 8, NKV = 2, D = 128, ROT = 64;
constexpr int E = 64, TK = 8, NG = 8, TG = 4;
constexpr int FI = 512, FSH = 512, CAP = 512;
constexpr int T = B * S;
constexpr int QKVW = (NH + 2 * NKV) * D;  // 1536
constexpr float EPS = 1e-5f;
constexpr float SCALE = 0.08838834764831843f;
constexpr float THETA = 10000.0f;
}  // namespace cfg
using namespace cfg;

// ---------------------------------------------------------------------------
// Static device scratch
// ---------------------------------------------------------------------------
constexpr size_t N_H    = (size_t)T * H;
constexpr size_t N_QKV  = (size_t)T * QKVW;
constexpr size_t N_Q    = (size_t)T * NH * D;
constexpr size_t N_K    = (size_t)T * NKV * D;
constexpr size_t N_SC   = (size_t)B * NH * S * S;
constexpr size_t N_AOUT = (size_t)T * NH * D;
constexpr size_t N_H2   = (size_t)T * H;
constexpr size_t N_XT   = (size_t)T * H;
constexpr size_t N_LOG  = (size_t)T * E;
constexpr size_t N_FW   = (size_t)T * TK;
constexpr size_t N_COMB = (size_t)T * H;

constexpr size_t OFF_H    = 0;
constexpr size_t OFF_QKV  = OFF_H + N_H;
constexpr size_t OFF_Q    = OFF_QKV + N_QKV;
constexpr size_t OFF_K    = OFF_Q + N_Q;
constexpr size_t OFF_SC   = OFF_K + N_K;
constexpr size_t OFF_AOUT = OFF_SC + N_SC;
constexpr size_t OFF_H2   = OFF_AOUT + N_AOUT;
constexpr size_t OFF_XT   = OFF_H2 + N_H2;
constexpr size_t OFF_LOG  = OFF_XT + N_XT;
constexpr size_t OFF_FW   = OFF_LOG + N_LOG;
constexpr size_t OFF_COMB = OFF_FW + N_FW;
constexpr size_t SCRATCH_F = OFF_COMB + N_COMB;

__device__ float g_scratch[SCRATCH_F];
__device__ __half g_xt16[(size_t)T * H];
__device__ __half g_bh16[(size_t)T * H];
__device__ __half g_aout16[(size_t)T * NH * D];
__device__ __half g_shact16[(size_t)T * FSH];
__device__ __half g_act16[(size_t)E * CAP * FI];
__device__ __half g_eo16[(size_t)E * CAP * H];

// packed fp16 weights: word[kp][n] = (w[2kp][n], w[2kp+1][n])
__device__ uint32_t g_wgu16[(size_t)E * (H / 2) * (2 * FI)];
__device__ uint32_t g_wdn16[(size_t)E * (FI / 2) * H];
__device__ uint32_t g_wqkv16[(size_t)(H / 2) * QKVW];      // transposed
__device__ uint32_t g_wo16[(size_t)(NH * D / 2) * H];      // transposed
__device__ uint32_t g_sgu16[(size_t)(H / 2) * (2 * FSH)];
__device__ uint32_t g_sdn16[(size_t)(FSH / 2) * H];

__device__ int g_topi[T * TK];
__device__ int g_slotpos[T * TK];
__device__ int g_cnt[E];
__device__ int g_tok[E * CAP];

// ---------------------------------------------------------------------------
// helpers
// ---------------------------------------------------------------------------
__device__ __forceinline__ uint32_t h2u(__half2 h) {
  return *reinterpret_cast<uint32_t*>(&h);
}

__device__ __forceinline__ void mma_tf32(float c[4], const uint32_t a[4],
                                         const uint32_t b[2]) {
  asm volatile(
      "mma.sync.aligned.m16n8k8.row.col.f32.tf32.tf32.f32 "
      "{%0,%1,%2,%3}, {%4,%5,%6,%7}, {%8,%9}, {%0,%1,%2,%3};\n"
      : "+f"(c[0]), "+f"(c[1]), "+f"(c[2]), "+f"(c[3])
      : "r"(a[0]), "r"(a[1]), "r"(a[2]), "r"(a[3]), "r"(b[0]), "r"(b[1]));
}

__device__ __forceinline__ void mma_f16(float c[4], const uint32_t a[4],
                                        const uint32_t b[2]) {
  asm volatile(
      "mma.sync.aligned.m16n8k16.row.col.f32.f16.f16.f32 "
      "{%0,%1,%2,%3}, {%4,%5,%6,%7}, {%8,%9}, {%0,%1,%2,%3};\n"
      : "+f"(c[0]), "+f"(c[1]), "+f"(c[2]), "+f"(c[3])
      : "r"(a[0]), "r"(a[1]), "r"(a[2]), "r"(a[3]), "r"(b[0]), "r"(b[1]));
}

__device__ __forceinline__ void ldsm4(uint32_t r[4], uint32_t saddr) {
  asm volatile(
      "ldmatrix.sync.aligned.m8n8.x4.shared.b16 {%0,%1,%2,%3}, [%4];"
      : "=r"(r[0]), "=r"(r[1]), "=r"(r[2]), "=r"(r[3])
      : "r"(saddr));
}

__device__ __forceinline__ void cp_async16(uint32_t dst, const void* src,
                                           bool pred) {
  int sz = pred ? 16 : 0;
  asm volatile("cp.async.cg.shared.global [%0], [%1], 16, %2;\n" ::"r"(dst),
               "l"(src), "r"(sz));
}
__device__ __forceinline__ void cp_commit() {
  asm volatile("cp.async.commit_group;\n");
}
template <int N>
__device__ __forceinline__ void cp_wait() {
  asm volatile("cp.async.wait_group %0;\n" ::"n"(N));
}

// ---------------------------------------------------------------------------
// Weight packing kernels (fp32 -> k-pair packed fp16 words)
// ---------------------------------------------------------------------------
__global__ void pack_nn(const float* __restrict__ in, uint32_t* __restrict__ out,
                        int N, int Ktot) {
  size_t zi = (size_t)blockIdx.z * Ktot * N;
  size_t zo = (size_t)blockIdx.z * (Ktot / 2) * N;
  int n = blockIdx.x * 256 + threadIdx.x;
  int kp = blockIdx.y;
  float a = in[zi + (size_t)(2 * kp) * N + n];
  float b = in[zi + (size_t)(2 * kp + 1) * N + n];
  out[zo + (size_t)kp * N + n] = h2u(__floats2half2_rn(a, b));
}

// TR: in [N][K] -> out [K/2][N]
__global__ void pack_tr(const float* __restrict__ in, uint32_t* __restrict__ out,
                        int N, int K) {
  __shared__ float s[32][65];
  int n0 = blockIdx.x * 32, k0 = blockIdx.y * 64;
  int tid = threadIdx.x;
#pragma unroll
  for (int l = 0; l < 8; l++) {
    int idx = tid + l * 256;
    int r = idx >> 6, c = idx & 63;
    s[r][c] = in[(size_t)(n0 + r) * K + k0 + c];
  }
  __syncthreads();
#pragma unroll
  for (int l = 0; l < 4; l++) {
    int idx = tid + l * 256;
    int i = idx >> 5, j = idx & 31;
    out[(size_t)(k0 / 2 + i) * N + n0 + j] =
        h2u(__floats2half2_rn(s[j][2 * i], s[j][2 * i + 1]));
  }
}

// ---------------------------------------------------------------------------
// RMSNorm (optional fp16 second output)
// ---------------------------------------------------------------------------
__global__ void rmsnorm_kernel(const float* __restrict__ in,
                               const float* __restrict__ w,
                               float* __restrict__ out,
                               __half* __restrict__ out16, int dim) {
  int t = blockIdx.x;
  const float* r = in + (size_t)t * dim;
  float s = 0.f;
  for (int i = threadIdx.x; i < dim; i += 256) {
    float v = r[i];
    s += v * v;
  }
  for (int o = 16; o; o >>= 1) s += __shfl_xor_sync(~0u, s, o);
  __shared__ float red[8];
  if ((threadIdx.x & 31) == 0) red[threadIdx.x >> 5] = s;
  __syncthreads();
  if (threadIdx.x == 0) {
    float tt = 0.f;
    for (int i = 0; i < 8; i++) tt += red[i];
    red[0] = tt;
  }
  __syncthreads();
  float inv = rsqrtf(red[0] / (float)dim + EPS);
  for (int i = threadIdx.x * 2; i < dim; i += 512) {
    float v0 = r[i] * inv * w[i];
    float v1 = r[i + 1] * inv * w[i + 1];
    out[(size_t)t * dim + i] = v0;
    out[(size_t)t * dim + i + 1] = v1;
    if (out16) {
      __half2 h = __floats2half2_rn(v0, v1);
      *(__half2*)&out16[(size_t)t * dim + i] = h;
    }
  }
}

// ---------------------------------------------------------------------------
// Per-head Q/K RMSNorm + RoPE
// ---------------------------------------------------------------------------
__global__ void qknorm_rope_kernel(const float* __restrict__ qkv,
                                   const int* __restrict__ positions,
                                   const float* __restrict__ qn,
                                   const float* __restrict__ kn,
                                   float* __restrict__ qout,
                                   float* __restrict__ kout) {
  int t = blockIdx.x, hh = blockIdx.y, d = threadIdx.x;
  const float* src;
  const float* w;
  float* dst;
  if (hh < NH) {
    src = qkv + (size_t)t * QKVW + hh * D;
    w = qn;
    dst = qout + ((size_t)t * NH + hh) * D;
  } else {
    int kv = hh - NH;
    src = qkv + (size_t)t * QKVW + NH * D + kv * D;
    w = kn;
    dst = kout + ((size_t)t * NKV + kv) * D;
  }
  float v = src[d];
  float s = v * v;
  for (int o = 16; o; o >>= 1) s += __shfl_xor_sync(~0u, s, o);
  __shared__ float red[4];
  if ((d & 31) == 0) red[d >> 5] = s;
  __syncthreads();
  float tot = red[0] + red[1] + red[2] + red[3];
  float nv = v * rsqrtf(tot / (float)D + EPS) * w[d];
  __shared__ float sh[128];
  sh[d] = nv;
  __syncthreads();
  int sidx = t & (S - 1);
  float pos = (float)positions[sidx];
  float res;
  if (d < ROT / 2) {
    float ang = pos * powf(THETA, -(float)d / (float)(ROT / 2));
    res = sh[d] * cosf(ang) - sh[d + ROT / 2] * sinf(ang);
  } else if (d < ROT) {
    int i2 = d - ROT / 2;
    float ang = pos * powf(THETA, -(float)i2 / (float)(ROT / 2));
    res = sh[d] * cosf(ang) + sh[d - ROT / 2] * sinf(ang);
  } else {
    res = nv;
  }
  dst[d] = res;
}

// ---------------------------------------------------------------------------
// tf32 GEMM (attention: scores + AV)
// ---------------------------------------------------------------------------
enum GemmMode { M_SCORES = 0, M_AV, M_GATE };

struct GemmP {
  int mode;
  const float* A;
  const float* Bm;
  float* C;
  __half* C16;
  int M, N, K, lda, ldb, ldc;
  int transB;
};

constexpr int APAD = 20;
constexpr int BPAD = 136;
constexpr int STAGES = 4;
constexpr int STW = 128 * APAD;
constexpr int GEMM_DSMEM = STAGES * 2 * STW * 4;

extern __shared__ uint32_t dynsmem[];

__global__ __launch_bounds__(256, 2) void gemm_tc(GemmP p) {
  int z = blockIdx.z;
  const float* Ab = p.A;
  const float* Bb = p.Bm;
  float* Cb = p.C;
  __half* Cb16 = p.C16;
  int Meff = p.M;

  if (p.mode == M_SCORES) {
    int b = z >> 3, h = z & 7;
    Ab = p.A + ((size_t)(b * S) * NH + h) * D;
    Bb = p.Bm + ((size_t)(b * S) * NKV + (h >> 2)) * D;
    Cb = p.C + (size_t)z * S * S;
  } else if (p.mode == M_AV) {
    int b = z >> 3, h = z & 7;
    Ab = p.A + (size_t)z * S * S;
    Bb = p.Bm + (size_t)(b * S) * QKVW + (size_t)(NH + NKV) * D + (h >> 2) * D;
    Cb = p.C + (size_t)(b * S) * (NH * D) + h * D;
    Cb16 = p.C16 + (size_t)(b * S) * (NH * D) + h * D;
  }

  int m0 = blockIdx.y * 128, n0 = blockIdx.x * 128;
  if (m0 >= Meff) return;
  if (p.mode == M_SCORES && n0 > m0 + 127) return;

  int kend = p.K;
  if (p.mode == M_AV) kend = min(p.K, m0 + 128);
  int nk = kend >> 4;

  uint32_t* Asm = dynsmem;
  uint32_t* Bsm = dynsmem + STAGES * STW;

  int tid = threadIdx.x;
  int lane = tid & 31, wid = tid >> 5;
  int warp_m = wid & 1, warp_n = wid >> 1;
  int gid = lane >> 2, tig = lane & 3;

  uint32_t as_base = (uint32_t)__cvta_generic_to_shared(Asm);
  uint32_t bs_base = (uint32_t)__cvta_generic_to_shared(Bsm);
  int lm_row = (lane & 15);
  int lm_col = (lane >> 4) << 2;

  float acc[4][4][4];
#pragma unroll
  for (int a = 0; a < 4; a++)
#pragma unroll
    for (int b = 0; b < 4; b++)
#pragma unroll
      for (int c = 0; c < 4; c++) acc[a][b][c] = 0.f;

  int a_row0 = tid >> 2, a_kq = (tid & 3) * 4;
  const float* a_src0;
  const float* a_src1;
  {
    int gm0 = m0 + a_row0, gm1 = m0 + a_row0 + 64;
    a_src0 = (gm0 < Meff) ? Ab + (size_t)gm0 * p.lda : Ab;
    a_src1 = (gm1 < Meff) ? Ab + (size_t)gm1 * p.lda : Ab;
  }
  bool a_v0 = (m0 + a_row0) < Meff;
  bool a_v1 = (m0 + a_row0 + 64) < Meff;

  auto issue = [&](int it, int st) {
    if (it < nk) {
      int k0 = it << 4;
      cp_async16(as_base + (uint32_t)(st * STW + a_row0 * APAD + a_kq) * 4u,
                 a_src0 + k0 + a_kq, a_v0);
      cp_async16(
          as_base + (uint32_t)(st * STW + (a_row0 + 64) * APAD + a_kq) * 4u,
          a_src1 + k0 + a_kq, a_v1);
      if (p.transB) {
        int n = tid >> 2, kq = (tid & 3) * 4;
        cp_async16(bs_base + (uint32_t)(st * STW + n * APAD + kq) * 4u,
                   Bb + (size_t)(n0 + n) * p.ldb + k0 + kq, true);
        cp_async16(bs_base + (uint32_t)(st * STW + (n + 64) * APAD + kq) * 4u,
                   Bb + (size_t)(n0 + n + 64) * p.ldb + k0 + kq, true);
      } else {
        int kk = tid >> 5, nq = (tid & 31) * 4;
        cp_async16(bs_base + (uint32_t)(st * STW + kk * BPAD + nq) * 4u,
                   Bb + (size_t)(k0 + kk) * p.ldb + n0 + nq, true);
        cp_async16(bs_base + (uint32_t)(st * STW + (kk + 8) * BPAD + nq) * 4u,
                   Bb + (size_t)(k0 + kk + 8) * p.ldb + n0 + nq, true);
      }
    }
    cp_commit();
  };

  issue(0, 0);
  issue(1, 1);
  issue(2, 2);

  int cur = 0;
  for (int it = 0; it < nk; it++) {
    cp_wait<STAGES - 2>();
    __syncthreads();
    issue(it + 3, (cur + 3) & (STAGES - 1));

    const uint32_t* Bsp = Bsm + cur * STW;
#pragma unroll
    for (int ks = 0; ks < 16; ks += 8) {
      uint32_t afr[4][4];
#pragma unroll
      for (int mt = 0; mt < 4; mt++) {
        int row = warp_m * 64 + mt * 16 + lm_row;
        uint32_t saddr =
            as_base + (uint32_t)(cur * STW + row * APAD + ks + lm_col) * 4u;
        ldsm4(afr[mt], saddr);
      }
      uint32_t bfr[4][2];
      if (p.transB) {
#pragma unroll
        for (int nt = 0; nt < 4; nt++) {
          int ncol = warp_n * 32 + nt * 8 + gid;
          bfr[nt][0] = Bsp[ncol * APAD + ks + tig];
          bfr[nt][1] = Bsp[ncol * APAD + ks + tig + 4];
        }
      } else {
#pragma unroll
        for (int nt = 0; nt < 4; nt++) {
          int ncol = warp_n * 32 + nt * 8 + gid;
          bfr[nt][0] = Bsp[(ks + tig) * BPAD + ncol];
          bfr[nt][1] = Bsp[(ks + tig + 4) * BPAD + ncol];
        }
      }
#pragma unroll
      for (int mt = 0; mt < 4; mt++)
#pragma unroll
        for (int nt = 0; nt < 4; nt++) mma_tf32(acc[mt][nt], afr[mt], bfr[nt]);
    }
    cur = (cur + 1) & (STAGES - 1);
  }

#pragma unroll
  for (int mt = 0; mt < 4; mt++) {
#pragma unroll
    for (int nt = 0; nt < 4; nt++) {
#pragma unroll
      for (int ee = 0; ee < 4; ee++) {
        int gm = m0 + warp_m * 64 + mt * 16 + gid + (ee >= 2 ? 8 : 0);
        int gn = n0 + warp_n * 32 + nt * 8 + tig * 2 + (ee & 1);
        if (gm >= Meff) continue;
        float v = acc[mt][nt][ee];
        if (p.mode == M_SCORES) {
          if (gn > gm) continue;
          v *= SCALE;
        }
        Cb[(size_t)gm * p.ldc + gn] = v;
        if (p.mode == M_AV) Cb16[(size_t)gm * p.ldc + gn] = __float2half(v);
      }
    }
  }
}

// ---------------------------------------------------------------------------
// Unified fp16 GEMM over PACKED weights, 4-stage cp.async pipeline.
// FM_GU: fused SiLU -> fp16 (interleaved gate/up); FM_DN: fp16 store to eo16;
// FM_QKV: +bias fp32; FM_WO: +resid fp32; FM_SDN: plain fp32.
// ---------------------------------------------------------------------------
enum F16Mode { FM_GU = 0, FM_DN, FM_QKV, FM_WO, FM_SDN };

struct F16P {
  int mode;
  const __half* A;
  const uint32_t* Bw;
  __half* Ch;
  float* Cf;
  const float* bias;
  const float* resid;
  const int* gidx;
  const int* cnt;
  int lda, ldbw, ldc, K, M;
  long long a_zs, b_zs, c_zs;  // b_zs in words
};

constexpr int HAPAD = 40;
constexpr int F16_ASTW = 128 * HAPAD;
constexpr int F16_BW = 16 * 136;
constexpr int F16_STAGES = 4;
constexpr int F16_DSMEM = F16_STAGES * (F16_ASTW * 2 + F16_BW * 4);

__global__ __launch_bounds__(256, 2) void gemm_f16(F16P p) {
  int z = blockIdx.z;
  int Meff = p.cnt ? min(p.cnt[z], CAP) : p.M;
  int m0 = blockIdx.y * 128;
  if (m0 >= Meff) return;

  const __half* Ab = p.A + (size_t)z * p.a_zs;
  const uint32_t* Bw = p.Bw + (size_t)z * p.b_zs;
  const int* gidx = (p.mode == FM_GU && p.gidx) ? p.gidx + z * CAP : nullptr;
  int n0 = blockIdx.x * 128;
  int n0g = blockIdx.x * 64;

  uint32_t* BsAll = dynsmem + (F16_STAGES * F16_ASTW / 2);

  int tid = threadIdx.x;
  int lane = tid & 31, wid = tid >> 5;
  int warp_m = wid & 1, warp_n = wid >> 1;
  int gid = lane >> 2, tig = lane & 3;

  uint32_t as_base = (uint32_t)__cvta_generic_to_shared(dynsmem);
  uint32_t bs_base = (uint32_t)__cvta_generic_to_shared(BsAll);

  int nk = p.K >> 5;

  float acc[4][4][4];
#pragma unroll
  for (int a = 0; a < 4; a++)
#pragma unroll
    for (int b = 0; b < 4; b++)
#pragma unroll
      for (int c = 0; c < 4; c++) acc[a][b][c] = 0.f;

  int a_row0 = tid >> 2, a_kq = (tid & 3) * 8;
  const __half* a_src0;
  const __half* a_src1;
  {
    int gm0 = m0 + a_row0, gm1 = m0 + a_row0 + 64;
    a_src0 = (gm0 < Meff)
                 ? (gidx ? Ab + (size_t)gidx[gm0] * p.lda
                         : Ab + (size_t)gm0 * p.lda)
                 : Ab;
    a_src1 = (gm1 < Meff)
                 ? (gidx ? Ab + (size_t)gidx[gm1] * p.lda
                         : Ab + (size_t)gm1 * p.lda)
                 : Ab;
  }
  bool a_v0 = (m0 + a_row0) < Meff;
  bool a_v1 = (m0 + a_row0 + 64) < Meff;

  int b_kp0 = tid >> 5, b_nq0 = (tid & 31) * 4;
  int b_kp1 = (tid + 256) >> 5, b_nq1 = ((tid + 256) & 31) * 4;
  auto bcol = [&](int n) -> int {
    if (p.mode == FM_GU) {
      int grp = n >> 4;
      int isup = (n >> 3) & 1;
      int cc = grp * 8 + (n & 7);
      return (isup ? FI : 0) + n0g + cc;  // FI == FSH
    }
    return n0 + n;
  };
  int b_c0 = bcol(b_nq0);
  int b_c1 = bcol(b_nq1);

  auto issue = [&](int it, int st) {
    if (it < nk) {
      int k0h = it << 5;
      cp_async16(
          as_base + (uint32_t)(st * F16_ASTW + a_row0 * HAPAD + a_kq) * 2u,
          a_src0 + k0h + a_kq, a_v0);
      cp_async16(
          as_base +
              (uint32_t)(st * F16_ASTW + (a_row0 + 64) * HAPAD + a_kq) * 2u,
          a_src1 + k0h + a_kq, a_v1);
      int kp0 = it << 4;
      cp_async16(bs_base + (uint32_t)(st * F16_BW + b_kp0 * 136 + b_nq0) * 4u,
                 Bw + (size_t)(kp0 + b_kp0) * p.ldbw + b_c0, true);
      cp_async16(bs_base + (uint32_t)(st * F16_BW + b_kp1 * 136 + b_nq1) * 4u,
                 Bw + (size_t)(kp0 + b_kp1) * p.ldbw + b_c1, true);
    }
    cp_commit();
  };

  issue(0, 0);
  issue(1, 1);
  issue(2, 2);

  int cur = 0;
  for (int it = 0; it < nk; it++) {
    cp_wait<F16_STAGES - 2>();
    __syncthreads();
    issue(it + 3, (cur + 3) & (F16_STAGES - 1));

    const uint32_t* Bsp = BsAll + cur * F16_BW;
#pragma unroll
    for (int ks = 0; ks < 2; ks++) {
      uint32_t afr[4][4];
#pragma unroll
      for (int mt = 0; mt < 4; mt++) {
        int row = warp_m * 64 + mt * 16 + (lane & 15);
        uint32_t saddr =
            as_base + (uint32_t)(cur * F16_ASTW + row * HAPAD + ks * 16 +
                                 ((lane >> 4) << 3)) *
                          2u;
        ldsm4(afr[mt], saddr);
      }
      uint32_t bfr[4][2];
      int kpb = ks * 8;
#pragma unroll
      for (int nt = 0; nt < 4; nt++) {
        int ncol = warp_n * 32 + nt * 8 + gid;
        bfr[nt][0] = Bsp[(kpb + tig) * 136 + ncol];
        bfr[nt][1] = Bsp[(kpb + 4 + tig) * 136 + ncol];
      }
#pragma unroll
      for (int mt = 0; mt < 4; mt++)
#pragma unroll
        for (int nt = 0; nt < 4; nt++) mma_f16(acc[mt][nt], afr[mt], bfr[nt]);
    }
    cur = (cur + 1) & (F16_STAGES - 1);
  }

  if (p.mode == FM_GU) {
    __half* Chb = p.Ch + (size_t)z * p.c_zs;
#pragma unroll
    for (int mt = 0; mt < 4; mt++) {
#pragma unroll
      for (int q = 0; q < 2; q++) {
#pragma unroll
        for (int half_e = 0; half_e < 2; half_e++) {
          int gm = m0 + warp_m * 64 + mt * 16 + gid + half_e * 8;
          if (gm >= Meff) continue;
          float g0 = acc[mt][2 * q][half_e * 2 + 0];
          float g1 = acc[mt][2 * q][half_e * 2 + 1];
          float u0 = acc[mt][2 * q + 1][half_e * 2 + 0];
          float u1 = acc[mt][2 * q + 1][half_e * 2 + 1];
          float a0 = (g0 / (1.f + expf(-g0))) * u0;
          float a1 = (g1 / (1.f + expf(-g1))) * u1;
          int cc = n0g + (2 * warp_n + q) * 8 + tig * 2;
          __half2 h = __floats2half2_rn(a0, a1);
          *(__half2*)&Chb[(size_t)gm * p.ldc + cc] = h;
        }
      }
    }
  } else if (p.mode == FM_DN) {
    // plain fp16 stores into eo16[e][slot][H] (no atomics)
    __half* Chb = p.Ch + (size_t)z * p.c_zs;
#pragma unroll
    for (int mt = 0; mt < 4; mt++) {
#pragma unroll
      for (int nt = 0; nt < 4; nt++) {
#pragma unroll
        for (int he = 0; he < 2; he++) {
          int gm = m0 + warp_m * 64 + mt * 16 + gid + he * 8;
          if (gm >= Meff) continue;
          int gn = n0 + warp_n * 32 + nt * 8 + tig * 2;
          __half2 h =
              __floats2half2_rn(acc[mt][nt][he * 2], acc[mt][nt][he * 2 + 1]);
          *(__half2*)&Chb[(size_t)gm * p.ldc + gn] = h;
        }
      }
    }
  } else {
#pragma unroll
    for (int mt = 0; mt < 4; mt++) {
#pragma unroll
      for (int nt = 0; nt < 4; nt++) {
#pragma unroll
        for (int ee = 0; ee < 4; ee++) {
          int gm = m0 + warp_m * 64 + mt * 16 + gid + (ee >= 2 ? 8 : 0);
          if (gm >= Meff) continue;
          int gn = n0 + warp_n * 32 + nt * 8 + tig * 2 + (ee & 1);
          float v = acc[mt][nt][ee];
          if (p.mode == FM_QKV)
            v += p.bias[gn];
          else if (p.mode == FM_WO)
            v += p.resid[(size_t)gm * p.ldc + gn];
          p.Cf[(size_t)gm * p.ldc + gn] = v;
        }
      }
    }
  }
}

// ---------------------------------------------------------------------------
// fp32 SIMT GEMM (tiny gate GEMM -> exact routing inputs)
// ---------------------------------------------------------------------------
__global__ __launch_bounds__(256) void gemm_kernel(GemmP p) {
  const float* Ab = p.A;
  const float* Bb = p.Bm;
  float* Cb = p.C;
  int Meff = p.M;

  int m0 = blockIdx.y * 64, n0 = blockIdx.x * 64;
  if (m0 >= Meff) return;

  __shared__ float As[16][68];
  __shared__ float Bs[16][68];
  int tid = threadIdx.x, tx = tid & 15, ty = tid >> 4;
  float acc[4][4] = {};

  for (int k0 = 0; k0 < p.K; k0 += 16) {
#pragma unroll
    for (int l = 0; l < 4; l++) {
      int i = tid + l * 256;
      int row = i >> 4, col = i & 15;
      int gm = m0 + row;
      float v = 0.f;
      if (gm < Meff) v = Ab[(size_t)gm * p.lda + k0 + col];
      As[col][row] = v;
    }
#pragma unroll
    for (int l = 0; l < 4; l++) {
      int i = tid + l * 256;
      if (p.transB) {
        int col = i >> 4, kk = i & 15;
        Bs[kk][col] = Bb[(size_t)(n0 + col) * p.ldb + (k0 + kk)];
      } else {
        int kk = i >> 6, col = i & 63;
        Bs[kk][col] = Bb[(size_t)(k0 + kk) * p.ldb + (n0 + col)];
      }
    }
    __syncthreads();
#pragma unroll
    for (int kk = 0; kk < 16; kk++) {
      float4 a4 = *(const float4*)(&As[kk][ty * 4]);
      float4 b4 = *(const float4*)(&Bs[kk][tx * 4]);
      float av[4] = {a4.x, a4.y, a4.z, a4.w};
      float bv[4] = {b4.x, b4.y, b4.z, b4.w};
#pragma unroll
      for (int i = 0; i < 4; i++)
#pragma unroll
        for (int j = 0; j < 4; j++) acc[i][j] += av[i] * bv[j];
    }
    __syncthreads();
  }

#pragma unroll
  for (int i = 0; i < 4; i++) {
    int gm = m0 + ty * 4 + i;
    if (gm >= Meff) continue;
#pragma unroll
    for (int j = 0; j < 4; j++) {
      int gn = n0 + tx * 4 + j;
      Cb[(size_t)gm * p.ldc + gn] = acc[i][j];
    }
  }
}

// ---------------------------------------------------------------------------
// Row softmax, causal-aware.
// ---------------------------------------------------------------------------
__global__ void softmax_kernel(float* __restrict__ sc) {
  size_t row = blockIdx.x;
  int q = (int)(row & (S - 1));
  int len = q + 1;
  int fill_end = ((q >> 7) + 1) << 7;
  float* p = sc + row * (size_t)S;
  __shared__ float red[8];
  float mx = -INFINITY;
  for (int i = threadIdx.x; i < len; i += 256) mx = fmaxf(mx, p[i]);
  for (int o = 16; o; o >>= 1) mx = fmaxf(mx, __shfl_xor_sync(~0u, mx, o));
  if ((threadIdx.x & 31) == 0) red[threadIdx.x >> 5] = mx;
  __syncthreads();
  if (threadIdx.x == 0) {
    float m = red[0];
    for (int i = 1; i < 8; i++) m = fmaxf(m, red[i]);
    red[0] = m;
  }
  __syncthreads();
  mx = red[0];
  __syncthreads();
  float sum = 0.f;
  for (int i = threadIdx.x; i < len; i += 256) {
    float e = expf(p[i] - mx);
    p[i] = e;
    sum += e;
  }
  for (int o = 16; o; o >>= 1) sum += __shfl_xor_sync(~0u, sum, o);
  if ((threadIdx.x & 31) == 0) red[threadIdx.x >> 5] = sum;
  __syncthreads();
  if (threadIdx.x == 0) {
    float t = 0.f;
    for (int i = 0; i < 8; i++) t += red[i];
    red[0] = t;
  }
  __syncthreads();
  float inv = 1.f / red[0];
  for (int i = threadIdx.x; i < len; i += 256) p[i] *= inv;
  for (int i = len + threadIdx.x; i < fill_end; i += 256) p[i] = 0.f;
}

// ---------------------------------------------------------------------------
// Routing
// ---------------------------------------------------------------------------
__global__ void route_kernel(const float* __restrict__ logits,
                             const float* __restrict__ gate_b,
                             int* __restrict__ topi, float* __restrict__ fw) {
  int t = blockIdx.x * blockDim.x + threadIdx.x;
  if (t >= T) return;
  float corr[E];
  const float* lg = logits + (size_t)t * E;
  for (int e = 0; e < E; e++) {
    float s = 1.f / (1.f + expf(-lg[e]));
    corr[e] = s + gate_b[e];
  }
  float grp[NG];
  for (int g = 0; g < NG; g++) {
    float m1 = -INFINITY, m2 = -INFINITY;
    for (int i = 0; i < E / NG; i++) {
      float v = corr[g * (E / NG) + i];
      if (v > m1) {
        m2 = m1;
        m1 = v;
      } else if (v > m2) {
        m2 = v;
      }
    }
    grp[g] = m1 + m2;
  }
  unsigned gsel = 0;
  for (int it = 0; it < TG; it++) {
    float best = -INFINITY;
    int bi = 0;
    for (int g = 0; g < NG; g++)
      if (!((gsel >> g) & 1u) && grp[g] > best) {
        best = grp[g];
        bi = g;
      }
    gsel |= 1u << bi;
  }
  unsigned long long esel = 0ull;
  int sel[TK];
  float ws[TK];
  float wsum = 0.f;
  for (int it = 0; it < TK; it++) {
    float best = -INFINITY;
    int bi = 0;
    for (int e = 0; e < E; e++) {
      if (!((gsel >> (e >> 3)) & 1u)) continue;
      if ((esel >> e) & 1ull) continue;
      if (corr[e] > best) {
        best = corr[e];
        bi = e;
      }
    }
    esel |= 1ull << bi;
    sel[it] = bi;
    float s = corr[bi] - gate_b[bi];
    ws[it] = s;
    wsum += s;
  }
  float inv = 1.f / wsum;
  for (int j = 0; j < TK; j++) {
    topi[t * TK + j] = sel[j];
    fw[t * TK + j] = ws[j] * inv;
  }
}

__global__ void zero_cnt_kernel(int* __restrict__ cnt) {
  if (threadIdx.x < E) cnt[threadIdx.x] = 0;
}

__global__ void assign_kernel(const int* __restrict__ topi,
                              int* __restrict__ cnt, int* __restrict__ tok,
                              int* __restrict__ slotpos) {
  int i = blockIdx.x * blockDim.x + threadIdx.x;
  if (i >= T * TK) return;
  int e = topi[i];
  int p = atomicAdd(&cnt[e], 1);
  if (p < CAP) {
    tok[e * CAP + p] = i / TK;
    slotpos[i] = p;
  } else {
    slotpos[i] = -1;
  }
}

// ---------------------------------------------------------------------------
// Final: out = h2 + comb(shared) + sum_j fw_j * eo16[e_j][p_j]
// ---------------------------------------------------------------------------
__global__ void final_kernel(const float* __restrict__ h2,
                             const float* __restrict__ comb,
                             const __half* __restrict__ eo,
                             const int* __restrict__ topi,
                             const int* __restrict__ slotpos,
                             const float* __restrict__ fw,
                             float* __restrict__ out) {
  int t = blockIdx.x;
  int sel_e[TK], sel_p[TK];
  float sel_w[TK];
#pragma unroll
  for (int j = 0; j < TK; j++) {
    sel_e[j] = topi[t * TK + j];
    sel_p[j] = slotpos[t * TK + j];
    sel_w[j] = fw[t * TK + j];
  }
  for (int c = threadIdx.x; c < H; c += 256) {
    float v = h2[(size_t)t * H + c] + comb[(size_t)t * H + c];
#pragma unroll
    for (int j = 0; j < TK; j++) {
      if (sel_p[j] >= 0)
        v += sel_w[j] *
             __half2float(
                 eo[((size_t)sel_e[j] * CAP + sel_p[j]) * H + c]);
    }
    out[(size_t)t * H + c] = v;
  }
}

// ---------------------------------------------------------------------------
// Host launcher
// ---------------------------------------------------------------------------
extern "C" void kernel_launch(void* const* d_in, const int* in_sizes, int n_in,
                              void* d_out, int out_size) {
  const float* x = (const float*)d_in[0];
  const int* positions = (const int*)d_in[1];
  const float* ln1_w = (const float*)d_in[2];
  const float* ln2_w = (const float*)d_in[3];
  const float* wqkv = (const float*)d_in[4];
  const float* bqkv = (const float*)d_in[5];
  const float* qn_w = (const float*)d_in[6];
  const float* kn_w = (const float*)d_in[7];
  const float* wo = (const float*)d_in[8];
  const float* gate_w = (const float*)d_in[9];
  const float* gate_b = (const float*)d_in[10];
  const float* w_gu = (const float*)d_in[11];
  const float* w_dn = (const float*)d_in[12];
  const float* sw_gu = (const float*)d_in[13];
  const float* sw_dn = (const float*)d_in[14];
  float* out = (float*)d_out;

  static bool attr_set = false;
  if (!attr_set) {
    cudaFuncSetAttribute(gemm_tc, cudaFuncAttributeMaxDynamicSharedMemorySize,
                         GEMM_DSMEM);
    cudaFuncSetAttribute(gemm_f16, cudaFuncAttributeMaxDynamicSharedMemorySize,
                         F16_DSMEM);
    attr_set = true;
  }

  float* scr = nullptr;
  cudaGetSymbolAddress((void**)&scr, g_scratch);
  int* topi = nullptr;
  cudaGetSymbolAddress((void**)&topi, g_topi);
  int* slotpos = nullptr;
  cudaGetSymbolAddress((void**)&slotpos, g_slotpos);
  int* cnt = nullptr;
  cudaGetSymbolAddress((void**)&cnt, g_cnt);
  int* tok = nullptr;
  cudaGetSymbolAddress((void**)&tok, g_tok);
  __half* xt16 = nullptr;
  cudaGetSymbolAddress((void**)&xt16, g_xt16);
  __half* bh16 = nullptr;
  cudaGetSymbolAddress((void**)&bh16, g_bh16);
  __half* aout16 = nullptr;
  cudaGetSymbolAddress((void**)&aout16, g_aout16);
  __half* shact16 = nullptr;
  cudaGetSymbolAddress((void**)&shact16, g_shact16);
  __half* act16 = nullptr;
  cudaGetSymbolAddress((void**)&act16, g_act16);
  __half* eo16 = nullptr;
  cudaGetSymbolAddress((void**)&eo16, g_eo16);
  uint32_t* wgu16 = nullptr;
  cudaGetSymbolAddress((void**)&wgu16, g_wgu16);
  uint32_t* wdn16 = nullptr;
  cudaGetSymbolAddress((void**)&wdn16, g_wdn16);
  uint32_t* wqkv16 = nullptr;
  cudaGetSymbolAddress((void**)&wqkv16, g_wqkv16);
  uint32_t* wo16 = nullptr;
  cudaGetSymbolAddress((void**)&wo16, g_wo16);
  uint32_t* sgu16 = nullptr;
  cudaGetSymbolAddress((void**)&sgu16, g_sgu16);
  uint32_t* sdn16 = nullptr;
  cudaGetSymbolAddress((void**)&sdn16, g_sdn16);

  float* bh = scr + OFF_H;
  float* bqkvb = scr + OFF_QKV;
  float* bq = scr + OFF_Q;
  float* bk = scr + OFF_K;
  float* bsc = scr + OFF_SC;
  float* baout = scr + OFF_AOUT;
  float* bh2 = scr + OFF_H2;
  float* bxt = scr + OFF_XT;
  float* blog = scr + OFF_LOG;
  float* bfw = scr + OFF_FW;
  float* bcomb = scr + OFF_COMB;

  // 0. pack weights -> fp16 k-pair layout
  pack_nn<<<dim3((2 * FI) / 256, H / 2, E), 256>>>(w_gu, wgu16, 2 * FI, H);
  pack_nn<<<dim3(H / 256, FI / 2, E), 256>>>(w_dn, wdn16, H, FI);
  pack_nn<<<dim3((2 * FSH) / 256, H / 2, 1), 256>>>(sw_gu, sgu16, 2 * FSH, H);
  pack_nn<<<dim3(H / 256, FSH / 2, 1), 256>>>(sw_dn, sdn16, H, FSH);
  pack_tr<<<dim3(QKVW / 32, H / 64), 256>>>(wqkv, wqkv16, QKVW, H);
  pack_tr<<<dim3(H / 32, (NH * D) / 64), 256>>>(wo, wo16, H, NH * D);

  // 1. rmsnorm1 (fp32 + fp16)
  rmsnorm_kernel<<<T, 256>>>(x, ln1_w, bh, bh16, H);

  // 2. qkv (fp16, packed transposed weights)
  {
    F16P p{};
    p.mode = FM_QKV;
    p.A = bh16; p.Bw = wqkv16; p.Cf = bqkvb; p.bias = bqkv;
    p.lda = H; p.ldbw = QKVW; p.ldc = QKVW; p.K = H; p.M = T;
    gemm_f16<<<dim3(QKVW / 128, T / 128, 1), 256, F16_DSMEM>>>(p);
  }

  // 3. q/k rmsnorm + rope
  qknorm_rope_kernel<<<dim3(T, NH + NKV), 128>>>(bqkvb, positions, qn_w, kn_w,
                                                 bq, bk);

  // 4. scores (tf32)
  {
    GemmP p{};
    p.mode = M_SCORES;
    p.A = bq; p.Bm = bk; p.C = bsc;
    p.M = S; p.N = S; p.K = D;
    p.lda = NH * D; p.ldb = NKV * D; p.ldc = S; p.transB = 1;
    gemm_tc<<<dim3(S / 128, S / 128, B * NH), 256, GEMM_DSMEM>>>(p);
  }

  // 5. softmax
  softmax_kernel<<<B * NH * S, 256>>>(bsc);

  // 6. attn @ v (tf32; dual fp32+fp16 out)
  {
    GemmP p{};
    p.mode = M_AV;
    p.A = bsc; p.Bm = bqkvb; p.C = baout; p.C16 = aout16;
    p.M = S; p.N = D; p.K = S;
    p.lda = S; p.ldb = QKVW; p.ldc = NH * D; p.transB = 0;
    gemm_tc<<<dim3(D / 128, S / 128, B * NH), 256, GEMM_DSMEM>>>(p);
  }

  // 7. h2 = x + aout @ wo^T  (fp16 packed)
  {
    F16P p{};
    p.mode = FM_WO;
    p.A = aout16; p.Bw = wo16; p.Cf = bh2; p.resid = x;
    p.lda = NH * D; p.ldbw = H; p.ldc = H; p.K = NH * D; p.M = T;
    gemm_f16<<<dim3(H / 128, T / 128, 1), 256, F16_DSMEM>>>(p);
  }

  // 8. rmsnorm2 (fp32 + fp16)
  rmsnorm_kernel<<<T, 256>>>(bh2, ln2_w, bxt, xt16, H);

  // 9. gate logits (exact fp32)
  {
    GemmP p{};
    p.mode = M_GATE;
    p.A = bxt; p.Bm = gate_w; p.C = blog;
    p.M = T; p.N = E; p.K = H;
    p.lda = H; p.ldb = H; p.ldc = E; p.transB = 1;
    gemm_kernel<<<dim3(1, T / 64, 1), 256>>>(p);
  }

  // 10. routing
  route_kernel<<<T / 256, 256>>>(blog, gate_b, topi, bfw);
  zero_cnt_kernel<<<1, 64>>>(cnt);
  assign_kernel<<<(T * TK) / 256, 256>>>(topi, cnt, tok, slotpos);

  // 11. shared expert: fused up-gate+SiLU -> shact16, then down -> bcomb
  {
    F16P p{};
    p.mode = FM_GU;
    p.A = xt16; p.Bw = sgu16; p.Ch = shact16;
    p.lda = H; p.ldbw = 2 * FSH; p.ldc = FSH; p.K = H; p.M = T;
    gemm_f16<<<dim3(FSH / 64, T / 128, 1), 256, F16_DSMEM>>>(p);
  }
  {
    F16P p{};
    p.mode = FM_SDN;
    p.A = shact16; p.Bw = sdn16; p.Cf = bcomb;
    p.lda = FSH; p.ldbw = H; p.ldc = H; p.K = FSH; p.M = T;
    gemm_f16<<<dim3(H / 128, T / 128, 1), 256, F16_DSMEM>>>(p);
  }

  // 12. MoE up-gate fused SiLU -> act16
  {
    F16P p{};
    p.mode = FM_GU;
    p.A = xt16; p.Bw = wgu16; p.Ch = act16;
    p.gidx = tok; p.cnt = cnt;
    p.lda = H; p.ldbw = 2 * FI; p.ldc = FI; p.K = H; p.M = CAP;
    p.a_zs = 0; p.b_zs = (long long)(H / 2) * (2 * FI);
    p.c_zs = (long long)CAP * FI;
    gemm_f16<<<dim3(FI / 64, CAP / 128, E), 256, F16_DSMEM>>>(p);
  }

  // 13. MoE down -> eo16 (plain fp16 stores, no atomics)
  {
    F16P p{};
    p.mode = FM_DN;
    p.A = act16; p.Bw = wdn16; p.Ch = eo16;
    p.cnt = cnt;
    p.lda = FI; p.ldbw = H; p.ldc = H; p.K = FI; p.M = CAP;
    p.a_zs = (long long)CAP * FI; p.b_zs = (long long)(FI / 2) * H;
    p.c_zs = (long long)CAP * H;
    gemm_f16<<<dim3(H / 128, CAP / 128, E), 256, F16_DSMEM>>>(p);
  }

  // 14. out = h2 + comb + weighted gather of eo16
  final_kernel<<<T, 256>>>(bh2, bcomb, eo16, topi, slotpos, bfw, out);
}

// round 13
// speedup vs baseline: 1.1295x; 1.1295x over previous
#include <cuda_runtime.h>
#include <cuda_fp16.h>
#include <math.h>
#include <stdint.h>

namespace cfg {
constexpr int B = 2, S = 1024, H = 1024;
constexpr int NH = 8, NKV = 2, D = 128, ROT = 64;
constexpr int E = 64, TK = 8, NG = 8, TG = 4;
constexpr int FI = 512, FSH = 512, CAP = 512;
constexpr int T = B * S;
constexpr int QKVW = (NH + 2 * NKV) * D;  // 1536
constexpr float EPS = 1e-5f;
constexpr float SCALE = 0.08838834764831843f;
constexpr float THETA = 10000.0f;
}  // namespace cfg
using namespace cfg;

// ---------------------------------------------------------------------------
// Static device scratch
// ---------------------------------------------------------------------------
constexpr size_t N_H    = (size_t)T * H;
constexpr size_t N_QKV  = (size_t)T * QKVW;
constexpr size_t N_Q    = (size_t)T * NH * D;
constexpr size_t N_K    = (size_t)T * NKV * D;
constexpr size_t N_SC   = (size_t)B * NH * S * S;
constexpr size_t N_AOUT = (size_t)T * NH * D;
constexpr size_t N_H2   = (size_t)T * H;
constexpr size_t N_XT   = (size_t)T * H;
constexpr size_t N_LOG  = (size_t)T * E;
constexpr size_t N_FW   = (size_t)T * TK;
constexpr size_t N_COMB = (size_t)T * H;

constexpr size_t OFF_H    = 0;
constexpr size_t OFF_QKV  = OFF_H + N_H;
constexpr size_t OFF_Q    = OFF_QKV + N_QKV;
constexpr size_t OFF_K    = OFF_Q + N_Q;
constexpr size_t OFF_SC   = OFF_K + N_K;
constexpr size_t OFF_AOUT = OFF_SC + N_SC;
constexpr size_t OFF_H2   = OFF_AOUT + N_AOUT;
constexpr size_t OFF_XT   = OFF_H2 + N_H2;
constexpr size_t OFF_LOG  = OFF_XT + N_XT;
constexpr size_t OFF_FW   = OFF_LOG + N_LOG;
constexpr size_t OFF_COMB = OFF_FW + N_FW;
constexpr size_t SCRATCH_F = OFF_COMB + N_COMB;

__device__ float g_scratch[SCRATCH_F];
__device__ __half g_xt16[(size_t)T * H];
__device__ __half g_bh16[(size_t)T * H];
__device__ __half g_aout16[(size_t)T * NH * D];
__device__ __half g_shact16[(size_t)T * FSH];
__device__ __half g_act16[(size_t)E * CAP * FI];

// packed fp16 weights: word[kp][n] = (w[2kp][n], w[2kp+1][n])
__device__ uint32_t g_wgu16[(size_t)E * (H / 2) * (2 * FI)];
__device__ uint32_t g_wdn16[(size_t)E * (FI / 2) * H];
__device__ uint32_t g_wqkv16[(size_t)(H / 2) * QKVW];      // transposed
__device__ uint32_t g_wo16[(size_t)(NH * D / 2) * H];      // transposed
__device__ uint32_t g_sgu16[(size_t)(H / 2) * (2 * FSH)];
__device__ uint32_t g_sdn16[(size_t)(FSH / 2) * H];

__device__ int g_topi[T * TK];
__device__ int g_cnt[E];
__device__ int g_tok[E * CAP];
__device__ float g_wslot[E * CAP];

// ---------------------------------------------------------------------------
// helpers
// ---------------------------------------------------------------------------
__device__ __forceinline__ uint32_t h2u(__half2 h) {
  return *reinterpret_cast<uint32_t*>(&h);
}

__device__ __forceinline__ void mma_tf32(float c[4], const uint32_t a[4],
                                         const uint32_t b[2]) {
  asm volatile(
      "mma.sync.aligned.m16n8k8.row.col.f32.tf32.tf32.f32 "
      "{%0,%1,%2,%3}, {%4,%5,%6,%7}, {%8,%9}, {%0,%1,%2,%3};\n"
      : "+f"(c[0]), "+f"(c[1]), "+f"(c[2]), "+f"(c[3])
      : "r"(a[0]), "r"(a[1]), "r"(a[2]), "r"(a[3]), "r"(b[0]), "r"(b[1]));
}

__device__ __forceinline__ void mma_f16(float c[4], const uint32_t a[4],
                                        const uint32_t b[2]) {
  asm volatile(
      "mma.sync.aligned.m16n8k16.row.col.f32.f16.f16.f32 "
      "{%0,%1,%2,%3}, {%4,%5,%6,%7}, {%8,%9}, {%0,%1,%2,%3};\n"
      : "+f"(c[0]), "+f"(c[1]), "+f"(c[2]), "+f"(c[3])
      : "r"(a[0]), "r"(a[1]), "r"(a[2]), "r"(a[3]), "r"(b[0]), "r"(b[1]));
}

__device__ __forceinline__ void ldsm4(uint32_t r[4], uint32_t saddr) {
  asm volatile(
      "ldmatrix.sync.aligned.m8n8.x4.shared.b16 {%0,%1,%2,%3}, [%4];"
      : "=r"(r[0]), "=r"(r[1]), "=r"(r[2]), "=r"(r[3])
      : "r"(saddr));
}

__device__ __forceinline__ void cp_async16(uint32_t dst, const void* src,
                                           bool pred) {
  int sz = pred ? 16 : 0;
  asm volatile("cp.async.cg.shared.global [%0], [%1], 16, %2;\n" ::"r"(dst),
               "l"(src), "r"(sz));
}
__device__ __forceinline__ void cp_commit() {
  asm volatile("cp.async.commit_group;\n");
}
template <int N>
__device__ __forceinline__ void cp_wait() {
  asm volatile("cp.async.wait_group %0;\n" ::"n"(N));
}

// ---------------------------------------------------------------------------
// Weight packing kernels (fp32 -> k-pair packed fp16 words), vectorized.
// pack_nn4: each thread packs 4 consecutive n columns (2x LDG.128 + STG.128).
// ---------------------------------------------------------------------------
__global__ void pack_nn4(const float* __restrict__ in,
                         uint32_t* __restrict__ out, int N, int Ktot) {
  size_t zi = (size_t)blockIdx.z * Ktot * N;
  size_t zo = (size_t)blockIdx.z * (Ktot / 2) * N;
  int n4 = (blockIdx.x * 256 + threadIdx.x) * 4;
  int kp = blockIdx.y;
  float4 a = *(const float4*)&in[zi + (size_t)(2 * kp) * N + n4];
  float4 b = *(const float4*)&in[zi + (size_t)(2 * kp + 1) * N + n4];
  uint4 o;
  o.x = h2u(__floats2half2_rn(a.x, b.x));
  o.y = h2u(__floats2half2_rn(a.y, b.y));
  o.z = h2u(__floats2half2_rn(a.z, b.z));
  o.w = h2u(__floats2half2_rn(a.w, b.w));
  *(uint4*)&out[zo + (size_t)kp * N + n4] = o;
}

// TR: in [N][K] -> out [K/2][N]
__global__ void pack_tr(const float* __restrict__ in, uint32_t* __restrict__ out,
                        int N, int K) {
  __shared__ float s[32][65];
  int n0 = blockIdx.x * 32, k0 = blockIdx.y * 64;
  int tid = threadIdx.x;
#pragma unroll
  for (int l = 0; l < 8; l++) {
    int idx = tid + l * 256;
    int r = idx >> 6, c = idx & 63;
    s[r][c] = in[(size_t)(n0 + r) * K + k0 + c];
  }
  __syncthreads();
#pragma unroll
  for (int l = 0; l < 4; l++) {
    int idx = tid + l * 256;
    int i = idx >> 5, j = idx & 31;
    out[(size_t)(k0 / 2 + i) * N + n0 + j] =
        h2u(__floats2half2_rn(s[j][2 * i], s[j][2 * i + 1]));
  }
}

// ---------------------------------------------------------------------------
// RMSNorm (fp32 out optional, packed fp16 out optional)
// ---------------------------------------------------------------------------
__global__ void rmsnorm_kernel(const float* __restrict__ in,
                               const float* __restrict__ w,
                               float* __restrict__ out,
                               __half* __restrict__ out16, int dim) {
  int t = blockIdx.x;
  const float* r = in + (size_t)t * dim;
  float s = 0.f;
  for (int i = threadIdx.x; i < dim; i += 256) {
    float v = r[i];
    s += v * v;
  }
  for (int o = 16; o; o >>= 1) s += __shfl_xor_sync(~0u, s, o);
  __shared__ float red[8];
  if ((threadIdx.x & 31) == 0) red[threadIdx.x >> 5] = s;
  __syncthreads();
  if (threadIdx.x == 0) {
    float tt = 0.f;
    for (int i = 0; i < 8; i++) tt += red[i];
    red[0] = tt;
  }
  __syncthreads();
  float inv = rsqrtf(red[0] / (float)dim + EPS);
  for (int i = threadIdx.x * 2; i < dim; i += 512) {
    float v0 = r[i] * inv * w[i];
    float v1 = r[i + 1] * inv * w[i + 1];
    if (out) {
      out[(size_t)t * dim + i] = v0;
      out[(size_t)t * dim + i + 1] = v1;
    }
    if (out16) {
      __half2 h = __floats2half2_rn(v0, v1);
      *(__half2*)&out16[(size_t)t * dim + i] = h;
    }
  }
}

// ---------------------------------------------------------------------------
// Per-head Q/K RMSNorm + RoPE
// ---------------------------------------------------------------------------
__global__ void qknorm_rope_kernel(const float* __restrict__ qkv,
                                   const int* __restrict__ positions,
                                   const float* __restrict__ qn,
                                   const float* __restrict__ kn,
                                   float* __restrict__ qout,
                                   float* __restrict__ kout) {
  int t = blockIdx.x, hh = blockIdx.y, d = threadIdx.x;
  const float* src;
  const float* w;
  float* dst;
  if (hh < NH) {
    src = qkv + (size_t)t * QKVW + hh * D;
    w = qn;
    dst = qout + ((size_t)t * NH + hh) * D;
  } else {
    int kv = hh - NH;
    src = qkv + (size_t)t * QKVW + NH * D + kv * D;
    w = kn;
    dst = kout + ((size_t)t * NKV + kv) * D;
  }
  float v = src[d];
  float s = v * v;
  for (int o = 16; o; o >>= 1) s += __shfl_xor_sync(~0u, s, o);
  __shared__ float red[4];
  if ((d & 31) == 0) red[d >> 5] = s;
  __syncthreads();
  float tot = red[0] + red[1] + red[2] + red[3];
  float nv = v * rsqrtf(tot / (float)D + EPS) * w[d];
  __shared__ float sh[128];
  sh[d] = nv;
  __syncthreads();
  int sidx = t & (S - 1);
  float pos = (float)positions[sidx];
  float res;
  if (d < ROT / 2) {
    float ang = pos * powf(THETA, -(float)d / (float)(ROT / 2));
    res = sh[d] * cosf(ang) - sh[d + ROT / 2] * sinf(ang);
  } else if (d < ROT) {
    int i2 = d - ROT / 2;
    float ang = pos * powf(THETA, -(float)i2 / (float)(ROT / 2));
    res = sh[d] * cosf(ang) + sh[d - ROT / 2] * sinf(ang);
  } else {
    res = nv;
  }
  dst[d] = res;
}

// ---------------------------------------------------------------------------
// tf32 GEMM (attention: scores + AV)
// ---------------------------------------------------------------------------
enum GemmMode { M_SCORES = 0, M_AV, M_GATE };

struct GemmP {
  int mode;
  const float* A;
  const float* Bm;
  float* C;
  __half* C16;
  int M, N, K, lda, ldb, ldc;
  int transB;
};

constexpr int APAD = 20;
constexpr int BPAD = 136;
constexpr int STAGES = 4;
constexpr int STW = 128 * APAD;
constexpr int GEMM_DSMEM = STAGES * 2 * STW * 4;

extern __shared__ uint32_t dynsmem[];

__global__ __launch_bounds__(256, 2) void gemm_tc(GemmP p) {
  int z = blockIdx.z;
  const float* Ab = p.A;
  const float* Bb = p.Bm;
  float* Cb = p.C;
  __half* Cb16 = p.C16;
  int Meff = p.M;

  if (p.mode == M_SCORES) {
    int b = z >> 3, h = z & 7;
    Ab = p.A + ((size_t)(b * S) * NH + h) * D;
    Bb = p.Bm + ((size_t)(b * S) * NKV + (h >> 2)) * D;
    Cb = p.C + (size_t)z * S * S;
  } else if (p.mode == M_AV) {
    int b = z >> 3, h = z & 7;
    Ab = p.A + (size_t)z * S * S;
    Bb = p.Bm + (size_t)(b * S) * QKVW + (size_t)(NH + NKV) * D + (h >> 2) * D;
    Cb16 = p.C16 + (size_t)(b * S) * (NH * D) + h * D;
  }

  int m0 = blockIdx.y * 128, n0 = blockIdx.x * 128;
  if (m0 >= Meff) return;
  if (p.mode == M_SCORES && n0 > m0 + 127) return;

  int kend = p.K;
  if (p.mode == M_AV) kend = min(p.K, m0 + 128);
  int nk = kend >> 4;

  uint32_t* Asm = dynsmem;
  uint32_t* Bsm = dynsmem + STAGES * STW;

  int tid = threadIdx.x;
  int lane = tid & 31, wid = tid >> 5;
  int warp_m = wid & 1, warp_n = wid >> 1;
  int gid = lane >> 2, tig = lane & 3;

  uint32_t as_base = (uint32_t)__cvta_generic_to_shared(Asm);
  uint32_t bs_base = (uint32_t)__cvta_generic_to_shared(Bsm);
  int lm_row = (lane & 15);
  int lm_col = (lane >> 4) << 2;

  float acc[4][4][4];
#pragma unroll
  for (int a = 0; a < 4; a++)
#pragma unroll
    for (int b = 0; b < 4; b++)
#pragma unroll
      for (int c = 0; c < 4; c++) acc[a][b][c] = 0.f;

  int a_row0 = tid >> 2, a_kq = (tid & 3) * 4;
  const float* a_src0;
  const float* a_src1;
  {
    int gm0 = m0 + a_row0, gm1 = m0 + a_row0 + 64;
    a_src0 = (gm0 < Meff) ? Ab + (size_t)gm0 * p.lda : Ab;
    a_src1 = (gm1 < Meff) ? Ab + (size_t)gm1 * p.lda : Ab;
  }
  bool a_v0 = (m0 + a_row0) < Meff;
  bool a_v1 = (m0 + a_row0 + 64) < Meff;

  auto issue = [&](int it, int st) {
    if (it < nk) {
      int k0 = it << 4;
      cp_async16(as_base + (uint32_t)(st * STW + a_row0 * APAD + a_kq) * 4u,
                 a_src0 + k0 + a_kq, a_v0);
      cp_async16(
          as_base + (uint32_t)(st * STW + (a_row0 + 64) * APAD + a_kq) * 4u,
          a_src1 + k0 + a_kq, a_v1);
      if (p.transB) {
        int n = tid >> 2, kq = (tid & 3) * 4;
        cp_async16(bs_base + (uint32_t)(st * STW + n * APAD + kq) * 4u,
                   Bb + (size_t)(n0 + n) * p.ldb + k0 + kq, true);
        cp_async16(bs_base + (uint32_t)(st * STW + (n + 64) * APAD + kq) * 4u,
                   Bb + (size_t)(n0 + n + 64) * p.ldb + k0 + kq, true);
      } else {
        int kk = tid >> 5, nq = (tid & 31) * 4;
        cp_async16(bs_base + (uint32_t)(st * STW + kk * BPAD + nq) * 4u,
                   Bb + (size_t)(k0 + kk) * p.ldb + n0 + nq, true);
        cp_async16(bs_base + (uint32_t)(st * STW + (kk + 8) * BPAD + nq) * 4u,
                   Bb + (size_t)(k0 + kk + 8) * p.ldb + n0 + nq, true);
      }
    }
    cp_commit();
  };

  issue(0, 0);
  issue(1, 1);
  issue(2, 2);

  int cur = 0;
  for (int it = 0; it < nk; it++) {
    cp_wait<STAGES - 2>();
    __syncthreads();
    issue(it + 3, (cur + 3) & (STAGES - 1));

    const uint32_t* Bsp = Bsm + cur * STW;
#pragma unroll
    for (int ks = 0; ks < 16; ks += 8) {
      uint32_t afr[4][4];
#pragma unroll
      for (int mt = 0; mt < 4; mt++) {
        int row = warp_m * 64 + mt * 16 + lm_row;
        uint32_t saddr =
            as_base + (uint32_t)(cur * STW + row * APAD + ks + lm_col) * 4u;
        ldsm4(afr[mt], saddr);
      }
      uint32_t bfr[4][2];
      if (p.transB) {
#pragma unroll
        for (int nt = 0; nt < 4; nt++) {
          int ncol = warp_n * 32 + nt * 8 + gid;
          bfr[nt][0] = Bsp[ncol * APAD + ks + tig];
          bfr[nt][1] = Bsp[ncol * APAD + ks + tig + 4];
        }
      } else {
#pragma unroll
        for (int nt = 0; nt < 4; nt++) {
          int ncol = warp_n * 32 + nt * 8 + gid;
          bfr[nt][0] = Bsp[(ks + tig) * BPAD + ncol];
          bfr[nt][1] = Bsp[(ks + tig + 4) * BPAD + ncol];
        }
      }
#pragma unroll
      for (int mt = 0; mt < 4; mt++)
#pragma unroll
        for (int nt = 0; nt < 4; nt++) mma_tf32(acc[mt][nt], afr[mt], bfr[nt]);
    }
    cur = (cur + 1) & (STAGES - 1);
  }

#pragma unroll
  for (int mt = 0; mt < 4; mt++) {
#pragma unroll
    for (int nt = 0; nt < 4; nt++) {
#pragma unroll
      for (int ee = 0; ee < 4; ee++) {
        int gm = m0 + warp_m * 64 + mt * 16 + gid + (ee >= 2 ? 8 : 0);
        int gn = n0 + warp_n * 32 + nt * 8 + tig * 2 + (ee & 1);
        if (gm >= Meff) continue;
        float v = acc[mt][nt][ee];
        if (p.mode == M_SCORES) {
          if (gn > gm) continue;
          Cb[(size_t)gm * p.ldc + gn] = v * SCALE;
        } else if (p.mode == M_AV) {
          Cb16[(size_t)gm * p.ldc + gn] = __float2half(v);
        } else {
          Cb[(size_t)gm * p.ldc + gn] = v;
        }
      }
    }
  }
}

// ---------------------------------------------------------------------------
// Unified fp16 GEMM over PACKED weights, 4-stage cp.async pipeline.
// FM_GU: fused SiLU -> fp16 (interleaved gate/up); FM_DN: scatter-atomic;
// FM_QKV: +bias fp32; FM_WO: +resid fp32; FM_SDN: plain fp32.
// ---------------------------------------------------------------------------
enum F16Mode { FM_GU = 0, FM_DN, FM_QKV, FM_WO, FM_SDN };

struct F16P {
  int mode;
  const __half* A;
  const uint32_t* Bw;
  __half* Ch;
  float* Cf;
  const float* bias;
  const float* resid;
  const int* gidx;
  const int* cnt;
  const float* wslot;
  int lda, ldbw, ldc, K, M;
  long long a_zs, b_zs, c_zs;  // b_zs in words
};

constexpr int HAPAD = 40;
constexpr int F16_ASTW = 128 * HAPAD;
constexpr int F16_BW = 16 * 136;
constexpr int F16_STAGES = 4;
constexpr int F16_DSMEM = F16_STAGES * (F16_ASTW * 2 + F16_BW * 4);

__global__ __launch_bounds__(256, 2) void gemm_f16(F16P p) {
  int z = blockIdx.z;
  int Meff = p.cnt ? min(p.cnt[z], CAP) : p.M;
  int m0 = blockIdx.y * 128;
  if (m0 >= Meff) return;

  const __half* Ab = p.A + (size_t)z * p.a_zs;
  const uint32_t* Bw = p.Bw + (size_t)z * p.b_zs;
  const int* gidx = (p.mode == FM_GU && p.gidx) ? p.gidx + z * CAP : nullptr;
  const int* tokz = (p.mode == FM_DN) ? p.gidx + z * CAP : nullptr;
  const float* wz = (p.mode == FM_DN) ? p.wslot + z * CAP : nullptr;
  int n0 = blockIdx.x * 128;
  int n0g = blockIdx.x * 64;

  uint32_t* BsAll = dynsmem + (F16_STAGES * F16_ASTW / 2);

  int tid = threadIdx.x;
  int lane = tid & 31, wid = tid >> 5;
  int warp_m = wid & 1, warp_n = wid >> 1;
  int gid = lane >> 2, tig = lane & 3;

  uint32_t as_base = (uint32_t)__cvta_generic_to_shared(dynsmem);
  uint32_t bs_base = (uint32_t)__cvta_generic_to_shared(BsAll);

  int nk = p.K >> 5;

  float acc[4][4][4];
#pragma unroll
  for (int a = 0; a < 4; a++)
#pragma unroll
    for (int b = 0; b < 4; b++)
#pragma unroll
      for (int c = 0; c < 4; c++) acc[a][b][c] = 0.f;

  int a_row0 = tid >> 2, a_kq = (tid & 3) * 8;
  const __half* a_src0;
  const __half* a_src1;
  {
    int gm0 = m0 + a_row0, gm1 = m0 + a_row0 + 64;
    a_src0 = (gm0 < Meff)
                 ? (gidx ? Ab + (size_t)gidx[gm0] * p.lda
                         : Ab + (size_t)gm0 * p.lda)
                 : Ab;
    a_src1 = (gm1 < Meff)
                 ? (gidx ? Ab + (size_t)gidx[gm1] * p.lda
                         : Ab + (size_t)gm1 * p.lda)
                 : Ab;
  }
  bool a_v0 = (m0 + a_row0) < Meff;
  bool a_v1 = (m0 + a_row0 + 64) < Meff;

  int b_kp0 = tid >> 5, b_nq0 = (tid & 31) * 4;
  int b_kp1 = (tid + 256) >> 5, b_nq1 = ((tid + 256) & 31) * 4;
  auto bcol = [&](int n) -> int {
    if (p.mode == FM_GU) {
      int grp = n >> 4;
      int isup = (n >> 3) & 1;
      int cc = grp * 8 + (n & 7);
      return (isup ? FI : 0) + n0g + cc;  // FI == FSH
    }
    return n0 + n;
  };
  int b_c0 = bcol(b_nq0);
  int b_c1 = bcol(b_nq1);

  auto issue = [&](int it, int st) {
    if (it < nk) {
      int k0h = it << 5;
      cp_async16(
          as_base + (uint32_t)(st * F16_ASTW + a_row0 * HAPAD + a_kq) * 2u,
          a_src0 + k0h + a_kq, a_v0);
      cp_async16(
          as_base +
              (uint32_t)(st * F16_ASTW + (a_row0 + 64) * HAPAD + a_kq) * 2u,
          a_src1 + k0h + a_kq, a_v1);
      int kp0 = it << 4;
      cp_async16(bs_base + (uint32_t)(st * F16_BW + b_kp0 * 136 + b_nq0) * 4u,
                 Bw + (size_t)(kp0 + b_kp0) * p.ldbw + b_c0, true);
      cp_async16(bs_base + (uint32_t)(st * F16_BW + b_kp1 * 136 + b_nq1) * 4u,
                 Bw + (size_t)(kp0 + b_kp1) * p.ldbw + b_c1, true);
    }
    cp_commit();
  };

  issue(0, 0);
  issue(1, 1);
  issue(2, 2);

  int cur = 0;
  for (int it = 0; it < nk; it++) {
    cp_wait<F16_STAGES - 2>();
    __syncthreads();
    issue(it + 3, (cur + 3) & (F16_STAGES - 1));

    const uint32_t* Bsp = BsAll + cur * F16_BW;
#pragma unroll
    for (int ks = 0; ks < 2; ks++) {
      uint32_t afr[4][4];
#pragma unroll
      for (int mt = 0; mt < 4; mt++) {
        int row = warp_m * 64 + mt * 16 + (lane & 15);
        uint32_t saddr =
            as_base + (uint32_t)(cur * F16_ASTW + row * HAPAD + ks * 16 +
                                 ((lane >> 4) << 3)) *
                          2u;
        ldsm4(afr[mt], saddr);
      }
      uint32_t bfr[4][2];
      int kpb = ks * 8;
#pragma unroll
      for (int nt = 0; nt < 4; nt++) {
        int ncol = warp_n * 32 + nt * 8 + gid;
        bfr[nt][0] = Bsp[(kpb + tig) * 136 + ncol];
        bfr[nt][1] = Bsp[(kpb + 4 + tig) * 136 + ncol];
      }
#pragma unroll
      for (int mt = 0; mt < 4; mt++)
#pragma unroll
        for (int nt = 0; nt < 4; nt++) mma_f16(acc[mt][nt], afr[mt], bfr[nt]);
    }
    cur = (cur + 1) & (F16_STAGES - 1);
  }

  if (p.mode == FM_GU) {
    __half* Chb = p.Ch + (size_t)z * p.c_zs;
#pragma unroll
    for (int mt = 0; mt < 4; mt++) {
#pragma unroll
      for (int q = 0; q < 2; q++) {
#pragma unroll
        for (int half_e = 0; half_e < 2; half_e++) {
          int gm = m0 + warp_m * 64 + mt * 16 + gid + half_e * 8;
          if (gm >= Meff) continue;
          float g0 = acc[mt][2 * q][half_e * 2 + 0];
          float g1 = acc[mt][2 * q][half_e * 2 + 1];
          float u0 = acc[mt][2 * q + 1][half_e * 2 + 0];
          float u1 = acc[mt][2 * q + 1][half_e * 2 + 1];
          float a0 = (g0 / (1.f + expf(-g0))) * u0;
          float a1 = (g1 / (1.f + expf(-g1))) * u1;
          int cc = n0g + (2 * warp_n + q) * 8 + tig * 2;
          __half2 h = __floats2half2_rn(a0, a1);
          *(__half2*)&Chb[(size_t)gm * p.ldc + cc] = h;
        }
      }
    }
  } else if (p.mode == FM_DN) {
#pragma unroll
    for (int mt = 0; mt < 4; mt++) {
#pragma unroll
      for (int nt = 0; nt < 4; nt++) {
#pragma unroll
        for (int ee = 0; ee < 4; ee++) {
          int gm = m0 + warp_m * 64 + mt * 16 + gid + (ee >= 2 ? 8 : 0);
          if (gm >= Meff) continue;
          int gn = n0 + warp_n * 32 + nt * 8 + tig * 2 + (ee & 1);
          int t = tokz[gm];
          float w = wz[gm];
          atomicAdd(&p.Cf[(size_t)t * p.ldc + gn], acc[mt][nt][ee] * w);
        }
      }
    }
  } else {
#pragma unroll
    for (int mt = 0; mt < 4; mt++) {
#pragma unroll
      for (int nt = 0; nt < 4; nt++) {
#pragma unroll
        for (int ee = 0; ee < 4; ee++) {
          int gm = m0 + warp_m * 64 + mt * 16 + gid + (ee >= 2 ? 8 : 0);
          if (gm >= Meff) continue;
          int gn = n0 + warp_n * 32 + nt * 8 + tig * 2 + (ee & 1);
          float v = acc[mt][nt][ee];
          if (p.mode == FM_QKV)
            v += p.bias[gn];
          else if (p.mode == FM_WO)
            v += p.resid[(size_t)gm * p.ldc + gn];
          p.Cf[(size_t)gm * p.ldc + gn] = v;
        }
      }
    }
  }
}

// ---------------------------------------------------------------------------
// fp32 SIMT GEMM (tiny gate GEMM -> exact routing inputs)
// ---------------------------------------------------------------------------
__global__ __launch_bounds__(256) void gemm_kernel(GemmP p) {
  const float* Ab = p.A;
  const float* Bb = p.Bm;
  float* Cb = p.C;
  int Meff = p.M;

  int m0 = blockIdx.y * 64, n0 = blockIdx.x * 64;
  if (m0 >= Meff) return;

  __shared__ float As[16][68];
  __shared__ float Bs[16][68];
  int tid = threadIdx.x, tx = tid & 15, ty = tid >> 4;
  float acc[4][4] = {};

  for (int k0 = 0; k0 < p.K; k0 += 16) {
#pragma unroll
    for (int l = 0; l < 4; l++) {
      int i = tid + l * 256;
      int row = i >> 4, col = i & 15;
      int gm = m0 + row;
      float v = 0.f;
      if (gm < Meff) v = Ab[(size_t)gm * p.lda + k0 + col];
      As[col][row] = v;
    }
#pragma unroll
    for (int l = 0; l < 4; l++) {
      int i = tid + l * 256;
      if (p.transB) {
        int col = i >> 4, kk = i & 15;
        Bs[kk][col] = Bb[(size_t)(n0 + col) * p.ldb + (k0 + kk)];
      } else {
        int kk = i >> 6, col = i & 63;
        Bs[kk][col] = Bb[(size_t)(k0 + kk) * p.ldb + (n0 + col)];
      }
    }
    __syncthreads();
#pragma unroll
    for (int kk = 0; kk < 16; kk++) {
      float4 a4 = *(const float4*)(&As[kk][ty * 4]);
      float4 b4 = *(const float4*)(&Bs[kk][tx * 4]);
      float av[4] = {a4.x, a4.y, a4.z, a4.w};
      float bv[4] = {b4.x, b4.y, b4.z, b4.w};
#pragma unroll
      for (int i = 0; i < 4; i++)
#pragma unroll
        for (int j = 0; j < 4; j++) acc[i][j] += av[i] * bv[j];
    }
    __syncthreads();
  }

#pragma unroll
  for (int i = 0; i < 4; i++) {
    int gm = m0 + ty * 4 + i;
    if (gm >= Meff) continue;
#pragma unroll
    for (int j = 0; j < 4; j++) {
      int gn = n0 + tx * 4 + j;
      Cb[(size_t)gm * p.ldc + gn] = acc[i][j];
    }
  }
}

// ---------------------------------------------------------------------------
// Row softmax, causal-aware.
// ---------------------------------------------------------------------------
__global__ void softmax_kernel(float* __restrict__ sc) {
  size_t row = blockIdx.x;
  int q = (int)(row & (S - 1));
  int len = q + 1;
  int fill_end = ((q >> 7) + 1) << 7;
  float* p = sc + row * (size_t)S;
  __shared__ float red[8];
  float mx = -INFINITY;
  for (int i = threadIdx.x; i < len; i += 256) mx = fmaxf(mx, p[i]);
  for (int o = 16; o; o >>= 1) mx = fmaxf(mx, __shfl_xor_sync(~0u, mx, o));
  if ((threadIdx.x & 31) == 0) red[threadIdx.x >> 5] = mx;
  __syncthreads();
  if (threadIdx.x == 0) {
    float m = red[0];
    for (int i = 1; i < 8; i++) m = fmaxf(m, red[i]);
    red[0] = m;
  }
  __syncthreads();
  mx = red[0];
  __syncthreads();
  float sum = 0.f;
  for (int i = threadIdx.x; i < len; i += 256) {
    float e = expf(p[i] - mx);
    p[i] = e;
    sum += e;
  }
  for (int o = 16; o; o >>= 1) sum += __shfl_xor_sync(~0u, sum, o);
  if ((threadIdx.x & 31) == 0) red[threadIdx.x >> 5] = sum;
  __syncthreads();
  if (threadIdx.x == 0) {
    float t = 0.f;
    for (int i = 0; i < 8; i++) t += red[i];
    red[0] = t;
  }
  __syncthreads();
  float inv = 1.f / red[0];
  for (int i = threadIdx.x; i < len; i += 256) p[i] *= inv;
  for (int i = len + threadIdx.x; i < fill_end; i += 256) p[i] = 0.f;
}

// ---------------------------------------------------------------------------
// Routing
// ---------------------------------------------------------------------------
__global__ void route_kernel(const float* __restrict__ logits,
                             const float* __restrict__ gate_b,
                             int* __restrict__ topi, float* __restrict__ fw) {
  int t = blockIdx.x * blockDim.x + threadIdx.x;
  if (t >= T) return;
  float corr[E];
  const float* lg = logits + (size_t)t * E;
  for (int e = 0; e < E; e++) {
    float s = 1.f / (1.f + expf(-lg[e]));
    corr[e] = s + gate_b[e];
  }
  float grp[NG];
  for (int g = 0; g < NG; g++) {
    float m1 = -INFINITY, m2 = -INFINITY;
    for (int i = 0; i < E / NG; i++) {
      float v = corr[g * (E / NG) + i];
      if (v > m1) {
        m2 = m1;
        m1 = v;
      } else if (v > m2) {
        m2 = v;
      }
    }
    grp[g] = m1 + m2;
  }
  unsigned gsel = 0;
  for (int it = 0; it < TG; it++) {
    float best = -INFINITY;
    int bi = 0;
    for (int g = 0; g < NG; g++)
      if (!((gsel >> g) & 1u) && grp[g] > best) {
        best = grp[g];
        bi = g;
      }
    gsel |= 1u << bi;
  }
  unsigned long long esel = 0ull;
  int sel[TK];
  float ws[TK];
  float wsum = 0.f;
  for (int it = 0; it < TK; it++) {
    float best = -INFINITY;
    int bi = 0;
    for (int e = 0; e < E; e++) {
      if (!((gsel >> (e >> 3)) & 1u)) continue;
      if ((esel >> e) & 1ull) continue;
      if (corr[e] > best) {
        best = corr[e];
        bi = e;
      }
    }
    esel |= 1ull << bi;
    sel[it] = bi;
    float s = corr[bi] - gate_b[bi];
    ws[it] = s;
    wsum += s;
  }
  float inv = 1.f / wsum;
  for (int j = 0; j < TK; j++) {
    topi[t * TK + j] = sel[j];
    fw[t * TK + j] = ws[j] * inv;
  }
}

__global__ void zero_cnt_kernel(int* __restrict__ cnt) {
  if (threadIdx.x < E) cnt[threadIdx.x] = 0;
}

__global__ void assign_kernel(const int* __restrict__ topi,
                              const float* __restrict__ fw,
                              int* __restrict__ cnt, int* __restrict__ tok,
                              float* __restrict__ wslot) {
  int i = blockIdx.x * blockDim.x + threadIdx.x;
  if (i >= T * TK) return;
  int e = topi[i];
  int p = atomicAdd(&cnt[e], 1);
  if (p < CAP) {
    tok[e * CAP + p] = i / TK;
    wslot[e * CAP + p] = fw[i];
  }
}

// ---------------------------------------------------------------------------
// Final: out = h2 + comb
// ---------------------------------------------------------------------------
__global__ void final_kernel(const float* __restrict__ h2,
                             const float* __restrict__ comb,
                             float* __restrict__ out) {
  size_t i = (size_t)blockIdx.x * 256 + threadIdx.x;
  if (i < (size_t)T * H) out[i] = h2[i] + comb[i];
}

// ---------------------------------------------------------------------------
// Host launcher
// ---------------------------------------------------------------------------
extern "C" void kernel_launch(void* const* d_in, const int* in_sizes, int n_in,
                              void* d_out, int out_size) {
  const float* x = (const float*)d_in[0];
  const int* positions = (const int*)d_in[1];
  const float* ln1_w = (const float*)d_in[2];
  const float* ln2_w = (const float*)d_in[3];
  const float* wqkv = (const float*)d_in[4];
  const float* bqkv = (const float*)d_in[5];
  const float* qn_w = (const float*)d_in[6];
  const float* kn_w = (const float*)d_in[7];
  const float* wo = (const float*)d_in[8];
  const float* gate_w = (const float*)d_in[9];
  const float* gate_b = (const float*)d_in[10];
  const float* w_gu = (const float*)d_in[11];
  const float* w_dn = (const float*)d_in[12];
  const float* sw_gu = (const float*)d_in[13];
  const float* sw_dn = (const float*)d_in[14];
  float* out = (float*)d_out;

  static bool attr_set = false;
  if (!attr_set) {
    cudaFuncSetAttribute(gemm_tc, cudaFuncAttributeMaxDynamicSharedMemorySize,
                         GEMM_DSMEM);
    cudaFuncSetAttribute(gemm_f16, cudaFuncAttributeMaxDynamicSharedMemorySize,
                         F16_DSMEM);
    attr_set = true;
  }

  float* scr = nullptr;
  cudaGetSymbolAddress((void**)&scr, g_scratch);
  int* topi = nullptr;
  cudaGetSymbolAddress((void**)&topi, g_topi);
  int* cnt = nullptr;
  cudaGetSymbolAddress((void**)&cnt, g_cnt);
  int* tok = nullptr;
  cudaGetSymbolAddress((void**)&tok, g_tok);
  float* wslot = nullptr;
  cudaGetSymbolAddress((void**)&wslot, g_wslot);
  __half* xt16 = nullptr;
  cudaGetSymbolAddress((void**)&xt16, g_xt16);
  __half* bh16 = nullptr;
  cudaGetSymbolAddress((void**)&bh16, g_bh16);
  __half* aout16 = nullptr;
  cudaGetSymbolAddress((void**)&aout16, g_aout16);
  __half* shact16 = nullptr;
  cudaGetSymbolAddress((void**)&shact16, g_shact16);
  __half* act16 = nullptr;
  cudaGetSymbolAddress((void**)&act16, g_act16);
  uint32_t* wgu16 = nullptr;
  cudaGetSymbolAddress((void**)&wgu16, g_wgu16);
  uint32_t* wdn16 = nullptr;
  cudaGetSymbolAddress((void**)&wdn16, g_wdn16);
  uint32_t* wqkv16 = nullptr;
  cudaGetSymbolAddress((void**)&wqkv16, g_wqkv16);
  uint32_t* wo16 = nullptr;
  cudaGetSymbolAddress((void**)&wo16, g_wo16);
  uint32_t* sgu16 = nullptr;
  cudaGetSymbolAddress((void**)&sgu16, g_sgu16);
  uint32_t* sdn16 = nullptr;
  cudaGetSymbolAddress((void**)&sdn16, g_sdn16);

  float* bqkvb = scr + OFF_QKV;
  float* bq = scr + OFF_Q;
  float* bk = scr + OFF_K;
  float* bsc = scr + OFF_SC;
  float* bh2 = scr + OFF_H2;
  float* bxt = scr + OFF_XT;
  float* blog = scr + OFF_LOG;
  float* bfw = scr + OFF_FW;
  float* bcomb = scr + OFF_COMB;

  // 0. pack weights -> fp16 k-pair layout (vectorized)
  pack_nn4<<<dim3((2 * FI) / 1024, H / 2, E), 256>>>(w_gu, wgu16, 2 * FI, H);
  pack_nn4<<<dim3(H / 1024, FI / 2, E), 256>>>(w_dn, wdn16, H, FI);
  pack_nn4<<<dim3((2 * FSH) / 1024, H / 2, 1), 256>>>(sw_gu, sgu16, 2 * FSH, H);
  pack_nn4<<<dim3(H / 1024, FSH / 2, 1), 256>>>(sw_dn, sdn16, H, FSH);
  pack_tr<<<dim3(QKVW / 32, H / 64), 256>>>(wqkv, wqkv16, QKVW, H);
  pack_tr<<<dim3(H / 32, (NH * D) / 64), 256>>>(wo, wo16, H, NH * D);

  // 1. rmsnorm1 (fp16 only; fp32 copy is dead)
  rmsnorm_kernel<<<T, 256>>>(x, ln1_w, nullptr, bh16, H);

  // 2. qkv (fp16, packed transposed weights)
  {
    F16P p{};
    p.mode = FM_QKV;
    p.A = bh16; p.Bw = wqkv16; p.Cf = bqkvb; p.bias = bqkv;
    p.lda = H; p.ldbw = QKVW; p.ldc = QKVW; p.K = H; p.M = T;
    gemm_f16<<<dim3(QKVW / 128, T / 128, 1), 256, F16_DSMEM>>>(p);
  }

  // 3. q/k rmsnorm + rope
  qknorm_rope_kernel<<<dim3(T, NH + NKV), 128>>>(bqkvb, positions, qn_w, kn_w,
                                                 bq, bk);

  // 4. scores (tf32)
  {
    GemmP p{};
    p.mode = M_SCORES;
    p.A = bq; p.Bm = bk; p.C = bsc;
    p.M = S; p.N = S; p.K = D;
    p.lda = NH * D; p.ldb = NKV * D; p.ldc = S; p.transB = 1;
    gemm_tc<<<dim3(S / 128, S / 128, B * NH), 256, GEMM_DSMEM>>>(p);
  }

  // 5. softmax
  softmax_kernel<<<B * NH * S, 256>>>(bsc);

  // 6. attn @ v (tf32; fp16 out only — fp32 copy is dead)
  {
    GemmP p{};
    p.mode = M_AV;
    p.A = bsc; p.Bm = bqkvb; p.C16 = aout16;
    p.M = S; p.N = D; p.K = S;
    p.lda = S; p.ldb = QKVW; p.ldc = NH * D; p.transB = 0;
    gemm_tc<<<dim3(D / 128, S / 128, B * NH), 256, GEMM_DSMEM>>>(p);
  }

  // 7. h2 = x + aout @ wo^T  (fp16 packed)
  {
    F16P p{};
    p.mode = FM_WO;
    p.A = aout16; p.Bw = wo16; p.Cf = bh2; p.resid = x;
    p.lda = NH * D; p.ldbw = H; p.ldc = H; p.K = NH * D; p.M = T;
    gemm_f16<<<dim3(H / 128, T / 128, 1), 256, F16_DSMEM>>>(p);
  }

  // 8. rmsnorm2 (fp32 + fp16)
  rmsnorm_kernel<<<T, 256>>>(bh2, ln2_w, bxt, xt16, H);

  // 9. gate logits (exact fp32)
  {
    GemmP p{};
    p.mode = M_GATE;
    p.A = bxt; p.Bm = gate_w; p.C = blog;
    p.M = T; p.N = E; p.K = H;
    p.lda = H; p.ldb = H; p.ldc = E; p.transB = 1;
    gemm_kernel<<<dim3(1, T / 64, 1), 256>>>(p);
  }

  // 10. routing
  route_kernel<<<T / 256, 256>>>(blog, gate_b, topi, bfw);
  zero_cnt_kernel<<<1, 64>>>(cnt);
  assign_kernel<<<(T * TK) / 256, 256>>>(topi, bfw, cnt, tok, wslot);

  // 11. shared expert: fused up-gate+SiLU -> shact16, then down -> bcomb
  {
    F16P p{};
    p.mode = FM_GU;
    p.A = xt16; p.Bw = sgu16; p.Ch = shact16;
    p.lda = H; p.ldbw = 2 * FSH; p.ldc = FSH; p.K = H; p.M = T;
    gemm_f16<<<dim3(FSH / 64, T / 128, 1), 256, F16_DSMEM>>>(p);
  }
  {
    F16P p{};
    p.mode = FM_SDN;
    p.A = shact16; p.Bw = sdn16; p.Cf = bcomb;
    p.lda = FSH; p.ldbw = H; p.ldc = H; p.K = FSH; p.M = T;
    gemm_f16<<<dim3(H / 128, T / 128, 1), 256, F16_DSMEM>>>(p);
  }

  // 12. MoE up-gate fused SiLU -> act16
  {
    F16P p{};
    p.mode = FM_GU;
    p.A = xt16; p.Bw = wgu16; p.Ch = act16;
    p.gidx = tok; p.cnt = cnt;
    p.lda = H; p.ldbw = 2 * FI; p.ldc = FI; p.K = H; p.M = CAP;
    p.a_zs = 0; p.b_zs = (long long)(H / 2) * (2 * FI);
    p.c_zs = (long long)CAP * FI;
    gemm_f16<<<dim3(FI / 64, CAP / 128, E), 256, F16_DSMEM>>>(p);
  }

  // 13. MoE down, scatter-accumulate into bcomb
  {
    F16P p{};
    p.mode = FM_DN;
    p.A = act16; p.Bw = wdn16; p.Cf = bcomb;
    p.gidx = tok; p.cnt = cnt; p.wslot = wslot;
    p.lda = FI; p.ldbw = H; p.ldc = H; p.K = FI; p.M = CAP;
    p.a_zs = (long long)CAP * FI; p.b_zs = (long long)(FI / 2) * H; p.c_zs = 0;
    gemm_f16<<<dim3(H / 128, CAP / 128, E), 256, F16_DSMEM>>>(p);
  }

  // 14. out = h2 + comb
  final_kernel<<<(int)(((size_t)T * H + 255) / 256), 256>>>(bh2, bcomb, out);
}

// round 14
// speedup vs baseline: 1.1904x; 1.0540x over previous
#include <cuda_runtime.h>
#include <cuda_fp16.h>
#include <math.h>
#include <stdint.h>

namespace cfg {
constexpr int B = 2, S = 1024, H = 1024;
constexpr int NH = 8, NKV = 2, D = 128, ROT = 64;
constexpr int E = 64, TK = 8, NG = 8, TG = 4;
constexpr int FI = 512, FSH = 512, CAP = 512;
constexpr int T = B * S;
constexpr int QKVW = (NH + 2 * NKV) * D;  // 1536
constexpr float EPS = 1e-5f;
constexpr float SCALE = 0.08838834764831843f;
constexpr float THETA = 10000.0f;
}  // namespace cfg
using namespace cfg;

// ---------------------------------------------------------------------------
// Static device scratch
// ---------------------------------------------------------------------------
constexpr size_t N_QKV  = (size_t)T * QKVW;
constexpr size_t N_SC   = (size_t)B * NH * S * S;
constexpr size_t N_H2   = (size_t)T * H;
constexpr size_t N_XT   = (size_t)T * H;
constexpr size_t N_LOG  = (size_t)T * E;
constexpr size_t N_FW   = (size_t)T * TK;

constexpr size_t OFF_QKV  = 0;
constexpr size_t OFF_SC   = OFF_QKV + N_QKV;
constexpr size_t OFF_H2   = OFF_SC + N_SC;
constexpr size_t OFF_XT   = OFF_H2 + N_H2;
constexpr size_t OFF_LOG  = OFF_XT + N_XT;
constexpr size_t OFF_FW   = OFF_LOG + N_LOG;
constexpr size_t SCRATCH_F = OFF_FW + N_FW;

__device__ float g_scratch[SCRATCH_F];
__device__ __half g_xt16[(size_t)T * H];
__device__ __half g_bh16[(size_t)T * H];
__device__ __half g_q16[(size_t)T * NH * D];
__device__ __half g_aout16[(size_t)T * NH * D];
__device__ __half g_shact16[(size_t)T * FSH];
__device__ __half g_act16[(size_t)E * CAP * FI];
__device__ __half g_sc16[(size_t)B * NH * S * S];
__device__ uint32_t g_k16p[(size_t)B * NKV * (D / 2) * S];
__device__ uint32_t g_v16p[(size_t)B * NKV * (S / 2) * D];

// packed fp16 weights: word[kp][n] = (w[2kp][n], w[2kp+1][n])
__device__ uint32_t g_wgu16[(size_t)E * (H / 2) * (2 * FI)];
__device__ uint32_t g_wdn16[(size_t)E * (FI / 2) * H];
__device__ uint32_t g_wqkv16[(size_t)(H / 2) * QKVW];      // transposed
__device__ uint32_t g_wo16[(size_t)(NH * D / 2) * H];      // transposed
__device__ uint32_t g_sgu16[(size_t)(H / 2) * (2 * FSH)];
__device__ uint32_t g_sdn16[(size_t)(FSH / 2) * H];

__device__ int g_topi[T * TK];
__device__ int g_cnt[E];
__device__ int g_tok[E * CAP];
__device__ float g_wslot[E * CAP];

// ---------------------------------------------------------------------------
// helpers
// ---------------------------------------------------------------------------
__device__ __forceinline__ uint32_t h2u(__half2 h) {
  return *reinterpret_cast<uint32_t*>(&h);
}

__device__ __forceinline__ void mma_f16(float c[4], const uint32_t a[4],
                                        const uint32_t b[2]) {
  asm volatile(
      "mma.sync.aligned.m16n8k16.row.col.f32.f16.f16.f32 "
      "{%0,%1,%2,%3}, {%4,%5,%6,%7}, {%8,%9}, {%0,%1,%2,%3};\n"
      : "+f"(c[0]), "+f"(c[1]), "+f"(c[2]), "+f"(c[3])
      : "r"(a[0]), "r"(a[1]), "r"(a[2]), "r"(a[3]), "r"(b[0]), "r"(b[1]));
}

__device__ __forceinline__ void ldsm4(uint32_t r[4], uint32_t saddr) {
  asm volatile(
      "ldmatrix.sync.aligned.m8n8.x4.shared.b16 {%0,%1,%2,%3}, [%4];"
      : "=r"(r[0]), "=r"(r[1]), "=r"(r[2]), "=r"(r[3])
      : "r"(saddr));
}

__device__ __forceinline__ void cp_async16(uint32_t dst, const void* src,
                                           bool pred) {
  int sz = pred ? 16 : 0;
  asm volatile("cp.async.cg.shared.global [%0], [%1], 16, %2;\n" ::"r"(dst),
               "l"(src), "r"(sz));
}
__device__ __forceinline__ void cp_commit() {
  asm volatile("cp.async.commit_group;\n");
}
template <int N>
__device__ __forceinline__ void cp_wait() {
  asm volatile("cp.async.wait_group %0;\n" ::"n"(N));
}

// ---------------------------------------------------------------------------
// Weight packing kernels
// ---------------------------------------------------------------------------
__global__ void pack_nn4(const float* __restrict__ in,
                         uint32_t* __restrict__ out, int N, int Ktot) {
  size_t zi = (size_t)blockIdx.z * Ktot * N;
  size_t zo = (size_t)blockIdx.z * (Ktot / 2) * N;
  int n4 = (blockIdx.x * 256 + threadIdx.x) * 4;
  int kp = blockIdx.y;
  float4 a = *(const float4*)&in[zi + (size_t)(2 * kp) * N + n4];
  float4 b = *(const float4*)&in[zi + (size_t)(2 * kp + 1) * N + n4];
  uint4 o;
  o.x = h2u(__floats2half2_rn(a.x, b.x));
  o.y = h2u(__floats2half2_rn(a.y, b.y));
  o.z = h2u(__floats2half2_rn(a.z, b.z));
  o.w = h2u(__floats2half2_rn(a.w, b.w));
  *(uint4*)&out[zo + (size_t)kp * N + n4] = o;
}

// TR: in [N][K] -> out [K/2][N]
__global__ void pack_tr(const float* __restrict__ in, uint32_t* __restrict__ out,
                        int N, int K) {
  __shared__ float s[32][65];
  int n0 = blockIdx.x * 32, k0 = blockIdx.y * 64;
  int tid = threadIdx.x;
#pragma unroll
  for (int l = 0; l < 8; l++) {
    int idx = tid + l * 256;
    int r = idx >> 6, c = idx & 63;
    s[r][c] = in[(size_t)(n0 + r) * K + k0 + c];
  }
  __syncthreads();
#pragma unroll
  for (int l = 0; l < 4; l++) {
    int idx = tid + l * 256;
    int i = idx >> 5, j = idx & 31;
    out[(size_t)(k0 / 2 + i) * N + n0 + j] =
        h2u(__floats2half2_rn(s[j][2 * i], s[j][2 * i + 1]));
  }
}

// pack V from qkv: word[zb][tp][d] = (v[2tp][d], v[2tp+1][d])
__global__ void pack_v(const float* __restrict__ qkv,
                       uint32_t* __restrict__ v16p) {
  int d = threadIdx.x;
  int tp = blockIdx.x;
  int zb = blockIdx.y;
  int b = zb >> 1, kv = zb & 1;
  size_t base =
      (size_t)(b * S + 2 * tp) * QKVW + (size_t)(NH + NKV) * D + kv * D + d;
  float v0 = qkv[base];
  float v1 = qkv[base + QKVW];
  v16p[((size_t)zb * (S / 2) + tp) * D + d] = h2u(__floats2half2_rn(v0, v1));
}

// ---------------------------------------------------------------------------
// RMSNorm (fp32 out optional, packed fp16 out optional)
// ---------------------------------------------------------------------------
__global__ void rmsnorm_kernel(const float* __restrict__ in,
                               const float* __restrict__ w,
                               float* __restrict__ out,
                               __half* __restrict__ out16, int dim) {
  int t = blockIdx.x;
  const float* r = in + (size_t)t * dim;
  float s = 0.f;
  for (int i = threadIdx.x; i < dim; i += 256) {
    float v = r[i];
    s += v * v;
  }
  for (int o = 16; o; o >>= 1) s += __shfl_xor_sync(~0u, s, o);
  __shared__ float red[8];
  if ((threadIdx.x & 31) == 0) red[threadIdx.x >> 5] = s;
  __syncthreads();
  if (threadIdx.x == 0) {
    float tt = 0.f;
    for (int i = 0; i < 8; i++) tt += red[i];
    red[0] = tt;
  }
  __syncthreads();
  float inv = rsqrtf(red[0] / (float)dim + EPS);
  for (int i = threadIdx.x * 2; i < dim; i += 512) {
    float v0 = r[i] * inv * w[i];
    float v1 = r[i + 1] * inv * w[i + 1];
    if (out) {
      out[(size_t)t * dim + i] = v0;
      out[(size_t)t * dim + i + 1] = v1;
    }
    if (out16) {
      __half2 h = __floats2half2_rn(v0, v1);
      *(__half2*)&out16[(size_t)t * dim + i] = h;
    }
  }
}

// ---------------------------------------------------------------------------
// Per-head Q/K RMSNorm + RoPE -> q16 (row fp16) and k16p (d-pair packed)
// ---------------------------------------------------------------------------
__global__ void qknorm_rope_kernel(const float* __restrict__ qkv,
                                   const int* __restrict__ positions,
                                   const float* __restrict__ qn,
                                   const float* __restrict__ kn,
                                   __half* __restrict__ q16,
                                   uint32_t* __restrict__ k16p) {
  int t = blockIdx.x, hh = blockIdx.y, d = threadIdx.x;
  const float* src;
  const float* w;
  if (hh < NH) {
    src = qkv + (size_t)t * QKVW + hh * D;
    w = qn;
  } else {
    int kv = hh - NH;
    src = qkv + (size_t)t * QKVW + NH * D + kv * D;
    w = kn;
  }
  float v = src[d];
  float s = v * v;
  for (int o = 16; o; o >>= 1) s += __shfl_xor_sync(~0u, s, o);
  __shared__ float red[4];
  if ((d & 31) == 0) red[d >> 5] = s;
  __syncthreads();
  float tot = red[0] + red[1] + red[2] + red[3];
  float nv = v * rsqrtf(tot / (float)D + EPS) * w[d];
  __shared__ float sh[128];
  __shared__ float sh2[128];
  sh[d] = nv;
  __syncthreads();
  int sidx = t & (S - 1);
  float pos = (float)positions[sidx];
  float res;
  if (d < ROT / 2) {
    float ang = pos * powf(THETA, -(float)d / (float)(ROT / 2));
    res = sh[d] * cosf(ang) - sh[d + ROT / 2] * sinf(ang);
  } else if (d < ROT) {
    int i2 = d - ROT / 2;
    float ang = pos * powf(THETA, -(float)i2 / (float)(ROT / 2));
    res = sh[d] * cosf(ang) + sh[d - ROT / 2] * sinf(ang);
  } else {
    res = nv;
  }
  if (hh < NH) {
    q16[((size_t)t * NH + hh) * D + d] = __float2half(res);
  } else {
    sh2[d] = res;
    __syncthreads();
    if (d < D / 2) {
      int kv = hh - NH;
      int b = t >> 10;  // S = 1024
      k16p[((size_t)(b * NKV + kv) * (D / 2) + d) * S + sidx] =
          h2u(__floats2half2_rn(sh2[2 * d], sh2[2 * d + 1]));
    }
  }
}

// ---------------------------------------------------------------------------
// Unified fp16 GEMM over packed-word B operands, 4-stage cp.async pipeline.
// ---------------------------------------------------------------------------
enum F16Mode { FM_GU = 0, FM_DN, FM_QKV, FM_WO, FM_SC, FM_AV };

struct F16P {
  int mode;
  const __half* A;
  const uint32_t* Bw;
  __half* Ch;
  float* Cf;
  const float* bias;
  const float* resid;
  const int* gidx;
  const int* cnt;
  const float* wslot;
  int lda, ldbw, ldc, K, M;
  long long a_zs, b_zs, c_zs;  // b_zs in words
};

constexpr int HAPAD = 40;
constexpr int F16_ASTW = 128 * HAPAD;
constexpr int F16_BW = 16 * 136;
constexpr int F16_STAGES = 4;
constexpr int F16_DSMEM = F16_STAGES * (F16_ASTW * 2 + F16_BW * 4);

extern __shared__ uint32_t dynsmem[];

__global__ __launch_bounds__(256, 2) void gemm_f16(F16P p) {
  int z = blockIdx.z;
  int Meff = p.cnt ? min(p.cnt[z], CAP) : p.M;
  int m0 = blockIdx.y * 128;
  if (m0 >= Meff) return;
  int n0 = blockIdx.x * 128;
  int n0g = blockIdx.x * 64;
  if (p.mode == FM_SC && n0 > m0 + 127) return;

  const __half* Ab;
  const uint32_t* Bw;
  float* Cf = p.Cf;
  __half* Chb = p.Ch;
  if (p.mode == FM_SC) {
    int b = z >> 3, h = z & 7;
    Ab = p.A + ((size_t)(b * S) * NH + h) * D;
    Bw = p.Bw + (size_t)(b * NKV + (h >> 2)) * (D / 2) * S;
    Cf = p.Cf + (size_t)z * S * S;
  } else if (p.mode == FM_AV) {
    int b = z >> 3, h = z & 7;
    Ab = p.A + (size_t)z * S * S;
    Bw = p.Bw + (size_t)(b * NKV + (h >> 2)) * (S / 2) * D;
    Chb = p.Ch + ((size_t)(b * S) * NH + h) * D;
  } else {
    Ab = p.A + (size_t)z * p.a_zs;
    Bw = p.Bw + (size_t)z * p.b_zs;
    if (p.Ch) Chb = p.Ch + (size_t)z * p.c_zs;
  }
  const int* gidx = (p.mode == FM_GU && p.gidx) ? p.gidx + z * CAP : nullptr;
  const int* tokz = (p.mode == FM_DN) ? p.gidx + z * CAP : nullptr;
  const float* wz = (p.mode == FM_DN) ? p.wslot + z * CAP : nullptr;

  uint32_t* BsAll = dynsmem + (F16_STAGES * F16_ASTW / 2);

  int tid = threadIdx.x;
  int lane = tid & 31, wid = tid >> 5;
  int warp_m = wid & 1, warp_n = wid >> 1;
  int gid = lane >> 2, tig = lane & 3;

  uint32_t as_base = (uint32_t)__cvta_generic_to_shared(dynsmem);
  uint32_t bs_base = (uint32_t)__cvta_generic_to_shared(BsAll);

  int kend = p.K;
  if (p.mode == FM_AV) kend = min(p.K, m0 + 128);
  int nk = kend >> 5;

  float acc[4][4][4];
#pragma unroll
  for (int a = 0; a < 4; a++)
#pragma unroll
    for (int b = 0; b < 4; b++)
#pragma unroll
      for (int c = 0; c < 4; c++) acc[a][b][c] = 0.f;

  int a_row0 = tid >> 2, a_kq = (tid & 3) * 8;
  const __half* a_src0;
  const __half* a_src1;
  {
    int gm0 = m0 + a_row0, gm1 = m0 + a_row0 + 64;
    a_src0 = (gm0 < Meff)
                 ? (gidx ? Ab + (size_t)gidx[gm0] * p.lda
                         : Ab + (size_t)gm0 * p.lda)
                 : Ab;
    a_src1 = (gm1 < Meff)
                 ? (gidx ? Ab + (size_t)gidx[gm1] * p.lda
                         : Ab + (size_t)gm1 * p.lda)
                 : Ab;
  }
  bool a_v0 = (m0 + a_row0) < Meff;
  bool a_v1 = (m0 + a_row0 + 64) < Meff;

  int b_kp0 = tid >> 5, b_nq0 = (tid & 31) * 4;
  int b_kp1 = (tid + 256) >> 5, b_nq1 = ((tid + 256) & 31) * 4;
  auto bcol = [&](int n) -> int {
    if (p.mode == FM_GU) {
      int grp = n >> 4;
      int isup = (n >> 3) & 1;
      int cc = grp * 8 + (n & 7);
      return (isup ? FI : 0) + n0g + cc;  // FI == FSH
    }
    return n0 + n;
  };
  int b_c0 = bcol(b_nq0);
  int b_c1 = bcol(b_nq1);

  auto issue = [&](int it, int st) {
    if (it < nk) {
      int k0h = it << 5;
      cp_async16(
          as_base + (uint32_t)(st * F16_ASTW + a_row0 * HAPAD + a_kq) * 2u,
          a_src0 + k0h + a_kq, a_v0);
      cp_async16(
          as_base +
              (uint32_t)(st * F16_ASTW + (a_row0 + 64) * HAPAD + a_kq) * 2u,
          a_src1 + k0h + a_kq, a_v1);
      int kp0 = it << 4;
      cp_async16(bs_base + (uint32_t)(st * F16_BW + b_kp0 * 136 + b_nq0) * 4u,
                 Bw + (size_t)(kp0 + b_kp0) * p.ldbw + b_c0, true);
      cp_async16(bs_base + (uint32_t)(st * F16_BW + b_kp1 * 136 + b_nq1) * 4u,
                 Bw + (size_t)(kp0 + b_kp1) * p.ldbw + b_c1, true);
    }
    cp_commit();
  };

  issue(0, 0);
  issue(1, 1);
  issue(2, 2);

  int cur = 0;
  for (int it = 0; it < nk; it++) {
    cp_wait<F16_STAGES - 2>();
    __syncthreads();
    issue(it + 3, (cur + 3) & (F16_STAGES - 1));

    const uint32_t* Bsp = BsAll + cur * F16_BW;
#pragma unroll
    for (int ks = 0; ks < 2; ks++) {
      uint32_t afr[4][4];
#pragma unroll
      for (int mt = 0; mt < 4; mt++) {
        int row = warp_m * 64 + mt * 16 + (lane & 15);
        uint32_t saddr =
            as_base + (uint32_t)(cur * F16_ASTW + row * HAPAD + ks * 16 +
                                 ((lane >> 4) << 3)) *
                          2u;
        ldsm4(afr[mt], saddr);
      }
      uint32_t bfr[4][2];
      int kpb = ks * 8;
#pragma unroll
      for (int nt = 0; nt < 4; nt++) {
        int ncol = warp_n * 32 + nt * 8 + gid;
        bfr[nt][0] = Bsp[(kpb + tig) * 136 + ncol];
        bfr[nt][1] = Bsp[(kpb + 4 + tig) * 136 + ncol];
      }
#pragma unroll
      for (int mt = 0; mt < 4; mt++)
#pragma unroll
        for (int nt = 0; nt < 4; nt++) mma_f16(acc[mt][nt], afr[mt], bfr[nt]);
    }
    cur = (cur + 1) & (F16_STAGES - 1);
  }

  if (p.mode == FM_GU) {
#pragma unroll
    for (int mt = 0; mt < 4; mt++) {
#pragma unroll
      for (int q = 0; q < 2; q++) {
#pragma unroll
        for (int half_e = 0; half_e < 2; half_e++) {
          int gm = m0 + warp_m * 64 + mt * 16 + gid + half_e * 8;
          if (gm >= Meff) continue;
          float g0 = acc[mt][2 * q][half_e * 2 + 0];
          float g1 = acc[mt][2 * q][half_e * 2 + 1];
          float u0 = acc[mt][2 * q + 1][half_e * 2 + 0];
          float u1 = acc[mt][2 * q + 1][half_e * 2 + 1];
          float a0 = (g0 / (1.f + expf(-g0))) * u0;
          float a1 = (g1 / (1.f + expf(-g1))) * u1;
          int cc = n0g + (2 * warp_n + q) * 8 + tig * 2;
          __half2 h = __floats2half2_rn(a0, a1);
          *(__half2*)&Chb[(size_t)gm * p.ldc + cc] = h;
        }
      }
    }
  } else if (p.mode == FM_DN) {
#pragma unroll
    for (int mt = 0; mt < 4; mt++) {
#pragma unroll
      for (int nt = 0; nt < 4; nt++) {
#pragma unroll
        for (int ee = 0; ee < 4; ee++) {
          int gm = m0 + warp_m * 64 + mt * 16 + gid + (ee >= 2 ? 8 : 0);
          if (gm >= Meff) continue;
          int gn = n0 + warp_n * 32 + nt * 8 + tig * 2 + (ee & 1);
          int t = tokz[gm];
          float w = wz[gm];
          atomicAdd(&Cf[(size_t)t * p.ldc + gn], acc[mt][nt][ee] * w);
        }
      }
    }
  } else if (p.mode == FM_AV) {
#pragma unroll
    for (int mt = 0; mt < 4; mt++) {
#pragma unroll
      for (int nt = 0; nt < 4; nt++) {
#pragma unroll
        for (int he = 0; he < 2; he++) {
          int gm = m0 + warp_m * 64 + mt * 16 + gid + he * 8;
          if (gm >= Meff) continue;
          int gn = n0 + warp_n * 32 + nt * 8 + tig * 2;
          __half2 h =
              __floats2half2_rn(acc[mt][nt][he * 2], acc[mt][nt][he * 2 + 1]);
          *(__half2*)&Chb[(size_t)gm * p.ldc + gn] = h;
        }
      }
    }
  } else {
#pragma unroll
    for (int mt = 0; mt < 4; mt++) {
#pragma unroll
      for (int nt = 0; nt < 4; nt++) {
#pragma unroll
        for (int ee = 0; ee < 4; ee++) {
          int gm = m0 + warp_m * 64 + mt * 16 + gid + (ee >= 2 ? 8 : 0);
          if (gm >= Meff) continue;
          int gn = n0 + warp_n * 32 + nt * 8 + tig * 2 + (ee & 1);
          float v = acc[mt][nt][ee];
          if (p.mode == FM_QKV)
            v += p.bias[gn];
          else if (p.mode == FM_WO)
            v += p.resid[(size_t)gm * p.ldc + gn];
          else if (p.mode == FM_SC) {
            if (gn > gm) continue;
            v *= SCALE;
          }
          Cf[(size_t)gm * p.ldc + gn] = v;
        }
      }
    }
  }
}

// ---------------------------------------------------------------------------
// fp32 SIMT GEMM (tiny gate GEMM -> exact routing inputs)
// ---------------------------------------------------------------------------
struct GemmP {
  const float* A;
  const float* Bm;
  float* C;
  int M, N, K, lda, ldb, ldc;
};

__global__ __launch_bounds__(256) void gemm_kernel(GemmP p) {
  const float* Ab = p.A;
  const float* Bb = p.Bm;
  float* Cb = p.C;
  int Meff = p.M;

  int m0 = blockIdx.y * 64, n0 = blockIdx.x * 64;
  if (m0 >= Meff) return;

  __shared__ float As[16][68];
  __shared__ float Bs[16][68];
  int tid = threadIdx.x, tx = tid & 15, ty = tid >> 4;
  float acc[4][4] = {};

  for (int k0 = 0; k0 < p.K; k0 += 16) {
#pragma unroll
    for (int l = 0; l < 4; l++) {
      int i = tid + l * 256;
      int row = i >> 4, col = i & 15;
      int gm = m0 + row;
      float v = 0.f;
      if (gm < Meff) v = Ab[(size_t)gm * p.lda + k0 + col];
      As[col][row] = v;
    }
#pragma unroll
    for (int l = 0; l < 4; l++) {
      int i = tid + l * 256;
      int col = i >> 4, kk = i & 15;
      Bs[kk][col] = Bb[(size_t)(n0 + col) * p.ldb + (k0 + kk)];
    }
    __syncthreads();
#pragma unroll
    for (int kk = 0; kk < 16; kk++) {
      float4 a4 = *(const float4*)(&As[kk][ty * 4]);
      float4 b4 = *(const float4*)(&Bs[kk][tx * 4]);
      float av[4] = {a4.x, a4.y, a4.z, a4.w};
      float bv[4] = {b4.x, b4.y, b4.z, b4.w};
#pragma unroll
      for (int i = 0; i < 4; i++)
#pragma unroll
        for (int j = 0; j < 4; j++) acc[i][j] += av[i] * bv[j];
    }
    __syncthreads();
  }

#pragma unroll
  for (int i = 0; i < 4; i++) {
    int gm = m0 + ty * 4 + i;
    if (gm >= Meff) continue;
#pragma unroll
    for (int j = 0; j < 4; j++) {
      int gn = n0 + tx * 4 + j;
      Cb[(size_t)gm * p.ldc + gn] = acc[i][j];
    }
  }
}

// ---------------------------------------------------------------------------
// Row softmax: read fp32 scores, write fp16 probs (causal-aware fill)
// ---------------------------------------------------------------------------
__global__ void softmax_kernel(const float* __restrict__ sc,
                               __half* __restrict__ pr) {
  size_t row = blockIdx.x;
  int q = (int)(row & (S - 1));
  int len = q + 1;
  int fill_end = ((q >> 7) + 1) << 7;
  const float* p = sc + row * (size_t)S;
  __half* po = pr + row * (size_t)S;
  __shared__ float red[8];
  float mx = -INFINITY;
  for (int i = threadIdx.x; i < len; i += 256) mx = fmaxf(mx, p[i]);
  for (int o = 16; o; o >>= 1) mx = fmaxf(mx, __shfl_xor_sync(~0u, mx, o));
  if ((threadIdx.x & 31) == 0) red[threadIdx.x >> 5] = mx;
  __syncthreads();
  if (threadIdx.x == 0) {
    float m = red[0];
    for (int i = 1; i < 8; i++) m = fmaxf(m, red[i]);
    red[0] = m;
  }
  __syncthreads();
  mx = red[0];
  __syncthreads();
  float sum = 0.f;
  for (int i = threadIdx.x; i < len; i += 256) sum += expf(p[i] - mx);
  for (int o = 16; o; o >>= 1) sum += __shfl_xor_sync(~0u, sum, o);
  if ((threadIdx.x & 31) == 0) red[threadIdx.x >> 5] = sum;
  __syncthreads();
  if (threadIdx.x == 0) {
    float t = 0.f;
    for (int i = 0; i < 8; i++) t += red[i];
    red[0] = t;
  }
  __syncthreads();
  float inv = 1.f / red[0];
  for (int i = threadIdx.x; i < len; i += 256)
    po[i] = __float2half(expf(p[i] - mx) * inv);
  for (int i = len + threadIdx.x; i < fill_end; i += 256)
    po[i] = __float2half(0.f);
}

// ---------------------------------------------------------------------------
// Routing
// ---------------------------------------------------------------------------
__global__ void route_kernel(const float* __restrict__ logits,
                             const float* __restrict__ gate_b,
                             int* __restrict__ topi, float* __restrict__ fw) {
  int t = blockIdx.x * blockDim.x + threadIdx.x;
  if (t >= T) return;
  float corr[E];
  const float* lg = logits + (size_t)t * E;
  for (int e = 0; e < E; e++) {
    float s = 1.f / (1.f + expf(-lg[e]));
    corr[e] = s + gate_b[e];
  }
  float grp[NG];
  for (int g = 0; g < NG; g++) {
    float m1 = -INFINITY, m2 = -INFINITY;
    for (int i = 0; i < E / NG; i++) {
      float v = corr[g * (E / NG) + i];
      if (v > m1) {
        m2 = m1;
        m1 = v;
      } else if (v > m2) {
        m2 = v;
      }
    }
    grp[g] = m1 + m2;
  }
  unsigned gsel = 0;
  for (int it = 0; it < TG; it++) {
    float best = -INFINITY;
    int bi = 0;
    for (int g = 0; g < NG; g++)
      if (!((gsel >> g) & 1u) && grp[g] > best) {
        best = grp[g];
        bi = g;
      }
    gsel |= 1u << bi;
  }
  unsigned long long esel = 0ull;
  int sel[TK];
  float ws[TK];
  float wsum = 0.f;
  for (int it = 0; it < TK; it++) {
    float best = -INFINITY;
    int bi = 0;
    for (int e = 0; e < E; e++) {
      if (!((gsel >> (e >> 3)) & 1u)) continue;
      if ((esel >> e) & 1ull) continue;
      if (corr[e] > best) {
        best = corr[e];
        bi = e;
      }
    }
    esel |= 1ull << bi;
    sel[it] = bi;
    float s = corr[bi] - gate_b[bi];
    ws[it] = s;
    wsum += s;
  }
  float inv = 1.f / wsum;
  for (int j = 0; j < TK; j++) {
    topi[t * TK + j] = sel[j];
    fw[t * TK + j] = ws[j] * inv;
  }
}

__global__ void zero_cnt_kernel(int* __restrict__ cnt) {
  if (threadIdx.x < E) cnt[threadIdx.x] = 0;
}

__global__ void assign_kernel(const int* __restrict__ topi,
                              const float* __restrict__ fw,
                              int* __restrict__ cnt, int* __restrict__ tok,
                              float* __restrict__ wslot) {
  int i = blockIdx.x * blockDim.x + threadIdx.x;
  if (i >= T * TK) return;
  int e = topi[i];
  int p = atomicAdd(&cnt[e], 1);
  if (p < CAP) {
    tok[e * CAP + p] = i / TK;
    wslot[e * CAP + p] = fw[i];
  }
}

// ---------------------------------------------------------------------------
// Host launcher
// ---------------------------------------------------------------------------
extern "C" void kernel_launch(void* const* d_in, const int* in_sizes, int n_in,
                              void* d_out, int out_size) {
  const float* x = (const float*)d_in[0];
  const int* positions = (const int*)d_in[1];
  const float* ln1_w = (const float*)d_in[2];
  const float* ln2_w = (const float*)d_in[3];
  const float* wqkv = (const float*)d_in[4];
  const float* bqkv = (const float*)d_in[5];
  const float* qn_w = (const float*)d_in[6];
  const float* kn_w = (const float*)d_in[7];
  const float* wo = (const float*)d_in[8];
  const float* gate_w = (const float*)d_in[9];
  const float* gate_b = (const float*)d_in[10];
  const float* w_gu = (const float*)d_in[11];
  const float* w_dn = (const float*)d_in[12];
  const float* sw_gu = (const float*)d_in[13];
  const float* sw_dn = (const float*)d_in[14];
  float* out = (float*)d_out;

  static bool attr_set = false;
  if (!attr_set) {
    cudaFuncSetAttribute(gemm_f16, cudaFuncAttributeMaxDynamicSharedMemorySize,
                         F16_DSMEM);
    attr_set = true;
  }

  float* scr = nullptr;
  cudaGetSymbolAddress((void**)&scr, g_scratch);
  int* topi = nullptr;
  cudaGetSymbolAddress((void**)&topi, g_topi);
  int* cnt = nullptr;
  cudaGetSymbolAddress((void**)&cnt, g_cnt);
  int* tok = nullptr;
  cudaGetSymbolAddress((void**)&tok, g_tok);
  float* wslot = nullptr;
  cudaGetSymbolAddress((void**)&wslot, g_wslot);
  __half* xt16 = nullptr;
  cudaGetSymbolAddress((void**)&xt16, g_xt16);
  __half* bh16 = nullptr;
  cudaGetSymbolAddress((void**)&bh16, g_bh16);
  __half* q16 = nullptr;
  cudaGetSymbolAddress((void**)&q16, g_q16);
  __half* aout16 = nullptr;
  cudaGetSymbolAddress((void**)&aout16, g_aout16);
  __half* shact16 = nullptr;
  cudaGetSymbolAddress((void**)&shact16, g_shact16);
  __half* act16 = nullptr;
  cudaGetSymbolAddress((void**)&act16, g_act16);
  __half* sc16 = nullptr;
  cudaGetSymbolAddress((void**)&sc16, g_sc16);
  uint32_t* k16p = nullptr;
  cudaGetSymbolAddress((void**)&k16p, g_k16p);
  uint32_t* v16p = nullptr;
  cudaGetSymbolAddress((void**)&v16p, g_v16p);
  uint32_t* wgu16 = nullptr;
  cudaGetSymbolAddress((void**)&wgu16, g_wgu16);
  uint32_t* wdn16 = nullptr;
  cudaGetSymbolAddress((void**)&wdn16, g_wdn16);
  uint32_t* wqkv16 = nullptr;
  cudaGetSymbolAddress((void**)&wqkv16, g_wqkv16);
  uint32_t* wo16 = nullptr;
  cudaGetSymbolAddress((void**)&wo16, g_wo16);
  uint32_t* sgu16 = nullptr;
  cudaGetSymbolAddress((void**)&sgu16, g_sgu16);
  uint32_t* sdn16 = nullptr;
  cudaGetSymbolAddress((void**)&sdn16, g_sdn16);

  float* bqkvb = scr + OFF_QKV;
  float* bsc = scr + OFF_SC;
  float* bh2 = scr + OFF_H2;
  float* bxt = scr + OFF_XT;
  float* blog = scr + OFF_LOG;
  float* bfw = scr + OFF_FW;

  // 0. pack weights
  pack_nn4<<<dim3((2 * FI) / 1024, H / 2, E), 256>>>(w_gu, wgu16, 2 * FI, H);
  pack_nn4<<<dim3(H / 1024, FI / 2, E), 256>>>(w_dn, wdn16, H, FI);
  pack_nn4<<<dim3((2 * FSH) / 1024, H / 2, 1), 256>>>(sw_gu, sgu16, 2 * FSH, H);
  pack_nn4<<<dim3(H / 1024, FSH / 2, 1), 256>>>(sw_dn, sdn16, H, FSH);
  pack_tr<<<dim3(QKVW / 32, H / 64), 256>>>(wqkv, wqkv16, QKVW, H);
  pack_tr<<<dim3(H / 32, (NH * D) / 64), 256>>>(wo, wo16, H, NH * D);

  // 1. rmsnorm1 (fp16 only)
  rmsnorm_kernel<<<T, 256>>>(x, ln1_w, nullptr, bh16, H);

  // 2. qkv (fp16)
  {
    F16P p{};
    p.mode = FM_QKV;
    p.A = bh16; p.Bw = wqkv16; p.Cf = bqkvb; p.bias = bqkv;
    p.lda = H; p.ldbw = QKVW; p.ldc = QKVW; p.K = H; p.M = T;
    gemm_f16<<<dim3(QKVW / 128, T / 128, 1), 256, F16_DSMEM>>>(p);
  }

  // 3. q/k rmsnorm + rope -> q16, k16p ; pack v
  qknorm_rope_kernel<<<dim3(T, NH + NKV), 128>>>(bqkvb, positions, qn_w, kn_w,
                                                 q16, k16p);
  pack_v<<<dim3(S / 2, B * NKV), 128>>>(bqkvb, v16p);

  // 4. scores (fp16) -> fp32 bsc
  {
    F16P p{};
    p.mode = FM_SC;
    p.A = q16; p.Bw = k16p; p.Cf = bsc;
    p.lda = NH * D; p.ldbw = S; p.ldc = S; p.K = D; p.M = S;
    gemm_f16<<<dim3(S / 128, S / 128, B * NH), 256, F16_DSMEM>>>(p);
  }

  // 5. softmax -> fp16 probs
  softmax_kernel<<<B * NH * S, 256>>>(bsc, sc16);

  // 6. attn @ v (fp16) -> aout16
  {
    F16P p{};
    p.mode = FM_AV;
    p.A = sc16; p.Bw = v16p; p.Ch = aout16;
    p.lda = S; p.ldbw = D; p.ldc = NH * D; p.K = S; p.M = S;
    gemm_f16<<<dim3(1, S / 128, B * NH), 256, F16_DSMEM>>>(p);
  }

  // 7. h2 = x + aout @ wo^T
  {
    F16P p{};
    p.mode = FM_WO;
    p.A = aout16; p.Bw = wo16; p.Cf = bh2; p.resid = x;
    p.lda = NH * D; p.ldbw = H; p.ldc = H; p.K = NH * D; p.M = T;
    gemm_f16<<<dim3(H / 128, T / 128, 1), 256, F16_DSMEM>>>(p);
  }

  // 8. rmsnorm2 (fp32 + fp16)
  rmsnorm_kernel<<<T, 256>>>(bh2, ln2_w, bxt, xt16, H);

  // 9. gate logits (exact fp32)
  {
    GemmP p{};
    p.A = bxt; p.Bm = gate_w; p.C = blog;
    p.M = T; p.N = E; p.K = H;
    p.lda = H; p.ldb = H; p.ldc = E;
    gemm_kernel<<<dim3(1, T / 64, 1), 256>>>(p);
  }

  // 10. routing
  route_kernel<<<T / 256, 256>>>(blog, gate_b, topi, bfw);
  zero_cnt_kernel<<<1, 64>>>(cnt);
  assign_kernel<<<(T * TK) / 256, 256>>>(topi, bfw, cnt, tok, wslot);

  // 11. shared expert: GU+SiLU -> shact16; down (+h2 resid) -> out
  {
    F16P p{};
    p.mode = FM_GU;
    p.A = xt16; p.Bw = sgu16; p.Ch = shact16;
    p.lda = H; p.ldbw = 2 * FSH; p.ldc = FSH; p.K = H; p.M = T;
    gemm_f16<<<dim3(FSH / 64, T / 128, 1), 256, F16_DSMEM>>>(p);
  }
  {
    F16P p{};
    p.mode = FM_WO;
    p.A = shact16; p.Bw = sdn16; p.Cf = out; p.resid = bh2;
    p.lda = FSH; p.ldbw = H; p.ldc = H; p.K = FSH; p.M = T;
    gemm_f16<<<dim3(H / 128, T / 128, 1), 256, F16_DSMEM>>>(p);
  }

  // 12. MoE up-gate fused SiLU -> act16
  {
    F16P p{};
    p.mode = FM_GU;
    p.A = xt16; p.Bw = wgu16; p.Ch = act16;
    p.gidx = tok; p.cnt = cnt;
    p.lda = H; p.ldbw = 2 * FI; p.ldc = FI; p.K = H; p.M = CAP;
    p.a_zs = 0; p.b_zs = (long long)(H / 2) * (2 * FI);
    p.c_zs = (long long)CAP * FI;
    gemm_f16<<<dim3(FI / 64, CAP / 128, E), 256, F16_DSMEM>>>(p);
  }

  // 13. MoE down, scatter-accumulate directly into out
  {
    F16P p{};
    p.mode = FM_DN;
    p.A = act16; p.Bw = wdn16; p.Cf = out;
    p.gidx = tok; p.cnt = cnt; p.wslot = wslot;
    p.lda = FI; p.ldbw = H; p.ldc = H; p.K = FI; p.M = CAP;
    p.a_zs = (long long)CAP * FI; p.b_zs = (long long)(FI / 2) * H; p.c_zs = 0;
    gemm_f16<<<dim3(H / 128, CAP / 128, E), 256, F16_DSMEM>>>(p);
  }
}

// round 15
// speedup vs baseline: 1.2495x; 1.0496x over previous
#include <cuda_runtime.h>
#include <cuda_fp16.h>
#include <math.h>
#include <stdint.h>

namespace cfg {
constexpr int B = 2, S = 1024, H = 1024;
constexpr int NH = 8, NKV = 2, D = 128, ROT = 64;
constexpr int E = 64, TK = 8, NG = 8, TG = 4;
constexpr int FI = 512, FSH = 512, CAP = 512;
constexpr int T = B * S;
constexpr int QKVW = (NH + 2 * NKV) * D;  // 1536
constexpr float EPS = 1e-5f;
constexpr float SCALE = 0.08838834764831843f;
constexpr float THETA = 10000.0f;
}  // namespace cfg
using namespace cfg;

// ---------------------------------------------------------------------------
// Static device scratch
// ---------------------------------------------------------------------------
constexpr size_t N_QKV  = (size_t)T * QKVW;
constexpr size_t N_SC   = (size_t)B * NH * S * S;
constexpr size_t N_H2   = (size_t)T * H;
constexpr size_t N_XT   = (size_t)T * H;
constexpr size_t N_LOG  = (size_t)T * E;
constexpr size_t N_FW   = (size_t)T * TK;

constexpr size_t OFF_QKV  = 0;
constexpr size_t OFF_SC   = OFF_QKV + N_QKV;
constexpr size_t OFF_H2   = OFF_SC + N_SC;
constexpr size_t OFF_XT   = OFF_H2 + N_H2;
constexpr size_t OFF_LOG  = OFF_XT + N_XT;
constexpr size_t OFF_FW   = OFF_LOG + N_LOG;
constexpr size_t SCRATCH_F = OFF_FW + N_FW;

__device__ float g_scratch[SCRATCH_F];
__device__ __half g_xt16[(size_t)T * H];
__device__ __half g_bh16[(size_t)T * H];
__device__ __half g_q16[(size_t)T * NH * D];
__device__ __half g_aout16[(size_t)T * NH * D];
__device__ __half g_shact16[(size_t)T * FSH];
__device__ __half g_act16[(size_t)E * CAP * FI];
__device__ __half g_sc16[(size_t)B * NH * S * S];
__device__ uint32_t g_k16p[(size_t)B * NKV * (D / 2) * S];
__device__ uint32_t g_v16p[(size_t)B * NKV * (S / 2) * D];

// packed fp16 weights: word[kp][n] = (w[2kp][n], w[2kp+1][n])
__device__ uint32_t g_wgu16[(size_t)E * (H / 2) * (2 * FI)];
__device__ uint32_t g_wdn16[(size_t)E * (FI / 2) * H];
__device__ uint32_t g_wqkv16[(size_t)(H / 2) * QKVW];      // transposed
__device__ uint32_t g_wo16[(size_t)(NH * D / 2) * H];      // transposed
__device__ uint32_t g_sgu16[(size_t)(H / 2) * (2 * FSH)];
__device__ uint32_t g_sdn16[(size_t)(FSH / 2) * H];

__device__ int g_topi[T * TK];
__device__ int g_cnt[E];
__device__ int g_tok[E * CAP];
__device__ float g_wslot[E * CAP];

// ---------------------------------------------------------------------------
// helpers
// ---------------------------------------------------------------------------
__device__ __forceinline__ uint32_t h2u(__half2 h) {
  return *reinterpret_cast<uint32_t*>(&h);
}

__device__ __forceinline__ void mma_f16(float c[4], const uint32_t a[4],
                                        const uint32_t b[2]) {
  asm volatile(
      "mma.sync.aligned.m16n8k16.row.col.f32.f16.f16.f32 "
      "{%0,%1,%2,%3}, {%4,%5,%6,%7}, {%8,%9}, {%0,%1,%2,%3};\n"
      : "+f"(c[0]), "+f"(c[1]), "+f"(c[2]), "+f"(c[3])
      : "r"(a[0]), "r"(a[1]), "r"(a[2]), "r"(a[3]), "r"(b[0]), "r"(b[1]));
}

__device__ __forceinline__ void ldsm4(uint32_t r[4], uint32_t saddr) {
  asm volatile(
      "ldmatrix.sync.aligned.m8n8.x4.shared.b16 {%0,%1,%2,%3}, [%4];"
      : "=r"(r[0]), "=r"(r[1]), "=r"(r[2]), "=r"(r[3])
      : "r"(saddr));
}

__device__ __forceinline__ void cp_async16(uint32_t dst, const void* src,
                                           bool pred) {
  int sz = pred ? 16 : 0;
  asm volatile("cp.async.cg.shared.global [%0], [%1], 16, %2;\n" ::"r"(dst),
               "l"(src), "r"(sz));
}
__device__ __forceinline__ void cp_commit() {
  asm volatile("cp.async.commit_group;\n");
}
template <int N>
__device__ __forceinline__ void cp_wait() {
  asm volatile("cp.async.wait_group %0;\n" ::"n"(N));
}

// ---------------------------------------------------------------------------
// Weight packing kernels
// ---------------------------------------------------------------------------
__global__ void pack_nn4(const float* __restrict__ in,
                         uint32_t* __restrict__ out, int N, int Ktot) {
  size_t zi = (size_t)blockIdx.z * Ktot * N;
  size_t zo = (size_t)blockIdx.z * (Ktot / 2) * N;
  int n4 = (blockIdx.x * 256 + threadIdx.x) * 4;
  int kp = blockIdx.y;
  float4 a = *(const float4*)&in[zi + (size_t)(2 * kp) * N + n4];
  float4 b = *(const float4*)&in[zi + (size_t)(2 * kp + 1) * N + n4];
  uint4 o;
  o.x = h2u(__floats2half2_rn(a.x, b.x));
  o.y = h2u(__floats2half2_rn(a.y, b.y));
  o.z = h2u(__floats2half2_rn(a.z, b.z));
  o.w = h2u(__floats2half2_rn(a.w, b.w));
  *(uint4*)&out[zo + (size_t)kp * N + n4] = o;
}

// TR: in [N][K] -> out [K/2][N]
__global__ void pack_tr(const float* __restrict__ in, uint32_t* __restrict__ out,
                        int N, int K) {
  __shared__ float s[32][65];
  int n0 = blockIdx.x * 32, k0 = blockIdx.y * 64;
  int tid = threadIdx.x;
#pragma unroll
  for (int l = 0; l < 8; l++) {
    int idx = tid + l * 256;
    int r = idx >> 6, c = idx & 63;
    s[r][c] = in[(size_t)(n0 + r) * K + k0 + c];
  }
  __syncthreads();
#pragma unroll
  for (int l = 0; l < 4; l++) {
    int idx = tid + l * 256;
    int i = idx >> 5, j = idx & 31;
    out[(size_t)(k0 / 2 + i) * N + n0 + j] =
        h2u(__floats2half2_rn(s[j][2 * i], s[j][2 * i + 1]));
  }
}

// pack V from qkv: word[zb][tp][d] = (v[2tp][d], v[2tp+1][d])
__global__ void pack_v(const float* __restrict__ qkv,
                       uint32_t* __restrict__ v16p) {
  int d = threadIdx.x;
  int tp = blockIdx.x;
  int zb = blockIdx.y;
  int b = zb >> 1, kv = zb & 1;
  size_t base =
      (size_t)(b * S + 2 * tp) * QKVW + (size_t)(NH + NKV) * D + kv * D + d;
  float v0 = qkv[base];
  float v1 = qkv[base + QKVW];
  v16p[((size_t)zb * (S / 2) + tp) * D + d] = h2u(__floats2half2_rn(v0, v1));
}

// ---------------------------------------------------------------------------
// RMSNorm (fp32 out optional, packed fp16 out optional)
// ---------------------------------------------------------------------------
__global__ void rmsnorm_kernel(const float* __restrict__ in,
                               const float* __restrict__ w,
                               float* __restrict__ out,
                               __half* __restrict__ out16, int dim) {
  int t = blockIdx.x;
  const float* r = in + (size_t)t * dim;
  float s = 0.f;
  for (int i = threadIdx.x; i < dim; i += 256) {
    float v = r[i];
    s += v * v;
  }
  for (int o = 16; o; o >>= 1) s += __shfl_xor_sync(~0u, s, o);
  __shared__ float red[8];
  if ((threadIdx.x & 31) == 0) red[threadIdx.x >> 5] = s;
  __syncthreads();
  if (threadIdx.x == 0) {
    float tt = 0.f;
    for (int i = 0; i < 8; i++) tt += red[i];
    red[0] = tt;
  }
  __syncthreads();
  float inv = rsqrtf(red[0] / (float)dim + EPS);
  for (int i = threadIdx.x * 2; i < dim; i += 512) {
    float v0 = r[i] * inv * w[i];
    float v1 = r[i + 1] * inv * w[i + 1];
    if (out) {
      out[(size_t)t * dim + i] = v0;
      out[(size_t)t * dim + i + 1] = v1;
    }
    if (out16) {
      __half2 h = __floats2half2_rn(v0, v1);
      *(__half2*)&out16[(size_t)t * dim + i] = h;
    }
  }
}

// ---------------------------------------------------------------------------
// Per-head Q/K RMSNorm + RoPE -> q16 (row fp16) and k16p (d-pair packed)
// ---------------------------------------------------------------------------
__global__ void qknorm_rope_kernel(const float* __restrict__ qkv,
                                   const int* __restrict__ positions,
                                   const float* __restrict__ qn,
                                   const float* __restrict__ kn,
                                   __half* __restrict__ q16,
                                   uint32_t* __restrict__ k16p) {
  int t = blockIdx.x, hh = blockIdx.y, d = threadIdx.x;
  const float* src;
  const float* w;
  if (hh < NH) {
    src = qkv + (size_t)t * QKVW + hh * D;
    w = qn;
  } else {
    int kv = hh - NH;
    src = qkv + (size_t)t * QKVW + NH * D + kv * D;
    w = kn;
  }
  float v = src[d];
  float s = v * v;
  for (int o = 16; o; o >>= 1) s += __shfl_xor_sync(~0u, s, o);
  __shared__ float red[4];
  if ((d & 31) == 0) red[d >> 5] = s;
  __syncthreads();
  float tot = red[0] + red[1] + red[2] + red[3];
  float nv = v * rsqrtf(tot / (float)D + EPS) * w[d];
  __shared__ float sh[128];
  __shared__ float sh2[128];
  sh[d] = nv;
  __syncthreads();
  int sidx = t & (S - 1);
  float pos = (float)positions[sidx];
  float res;
  if (d < ROT / 2) {
    float ang = pos * powf(THETA, -(float)d / (float)(ROT / 2));
    res = sh[d] * cosf(ang) - sh[d + ROT / 2] * sinf(ang);
  } else if (d < ROT) {
    int i2 = d - ROT / 2;
    float ang = pos * powf(THETA, -(float)i2 / (float)(ROT / 2));
    res = sh[d] * cosf(ang) + sh[d - ROT / 2] * sinf(ang);
  } else {
    res = nv;
  }
  if (hh < NH) {
    q16[((size_t)t * NH + hh) * D + d] = __float2half(res);
  } else {
    sh2[d] = res;
    __syncthreads();
    if (d < D / 2) {
      int kv = hh - NH;
      int b = t >> 10;  // S = 1024
      k16p[((size_t)(b * NKV + kv) * (D / 2) + d) * S + sidx] =
          h2u(__floats2half2_rn(sh2[2 * d], sh2[2 * d + 1]));
    }
  }
}

// ---------------------------------------------------------------------------
// Unified fp16 GEMM over packed-word B operands, 4-stage cp.async pipeline.
// ---------------------------------------------------------------------------
enum F16Mode { FM_GU = 0, FM_DN, FM_QKV, FM_WO, FM_SC, FM_AV };

struct F16P {
  int mode;
  const __half* A;
  const uint32_t* Bw;
  __half* Ch;
  float* Cf;
  const float* bias;
  const float* resid;
  const int* gidx;
  const int* cnt;
  const float* wslot;
  int lda, ldbw, ldc, K, M;
  long long a_zs, b_zs, c_zs;  // b_zs in words
};

constexpr int HAPAD = 40;
constexpr int F16_ASTW = 128 * HAPAD;
constexpr int F16_BW = 16 * 136;
constexpr int F16_STAGES = 4;
constexpr int F16_DSMEM = F16_STAGES * (F16_ASTW * 2 + F16_BW * 4);

extern __shared__ uint32_t dynsmem[];

__global__ __launch_bounds__(256, 2) void gemm_f16(F16P p) {
  int z = blockIdx.z;
  int Meff = p.cnt ? min(p.cnt[z], CAP) : p.M;
  int m0 = blockIdx.y * 128;
  if (m0 >= Meff) return;
  int n0 = blockIdx.x * 128;
  int n0g = blockIdx.x * 64;
  if (p.mode == FM_SC && n0 > m0 + 127) return;

  const __half* Ab;
  const uint32_t* Bw;
  float* Cf = p.Cf;
  __half* Chb = p.Ch;
  if (p.mode == FM_SC) {
    int b = z >> 3, h = z & 7;
    Ab = p.A + ((size_t)(b * S) * NH + h) * D;
    Bw = p.Bw + (size_t)(b * NKV + (h >> 2)) * (D / 2) * S;
    Cf = p.Cf + (size_t)z * S * S;
  } else if (p.mode == FM_AV) {
    int b = z >> 3, h = z & 7;
    Ab = p.A + (size_t)z * S * S;
    Bw = p.Bw + (size_t)(b * NKV + (h >> 2)) * (S / 2) * D;
    Chb = p.Ch + ((size_t)(b * S) * NH + h) * D;
  } else {
    Ab = p.A + (size_t)z * p.a_zs;
    Bw = p.Bw + (size_t)z * p.b_zs;
    if (p.Ch) Chb = p.Ch + (size_t)z * p.c_zs;
  }
  const int* gidx = (p.mode == FM_GU && p.gidx) ? p.gidx + z * CAP : nullptr;
  const int* tokz = (p.mode == FM_DN) ? p.gidx + z * CAP : nullptr;
  const float* wz = (p.mode == FM_DN) ? p.wslot + z * CAP : nullptr;

  uint32_t* BsAll = dynsmem + (F16_STAGES * F16_ASTW / 2);

  int tid = threadIdx.x;
  int lane = tid & 31, wid = tid >> 5;
  int warp_m = wid & 1, warp_n = wid >> 1;
  int gid = lane >> 2, tig = lane & 3;

  uint32_t as_base = (uint32_t)__cvta_generic_to_shared(dynsmem);
  uint32_t bs_base = (uint32_t)__cvta_generic_to_shared(BsAll);

  int kend = p.K;
  if (p.mode == FM_AV) kend = min(p.K, m0 + 128);
  int nk = kend >> 5;

  float acc[4][4][4];
#pragma unroll
  for (int a = 0; a < 4; a++)
#pragma unroll
    for (int b = 0; b < 4; b++)
#pragma unroll
      for (int c = 0; c < 4; c++) acc[a][b][c] = 0.f;

  int a_row0 = tid >> 2, a_kq = (tid & 3) * 8;
  const __half* a_src0;
  const __half* a_src1;
  {
    int gm0 = m0 + a_row0, gm1 = m0 + a_row0 + 64;
    a_src0 = (gm0 < Meff)
                 ? (gidx ? Ab + (size_t)gidx[gm0] * p.lda
                         : Ab + (size_t)gm0 * p.lda)
                 : Ab;
    a_src1 = (gm1 < Meff)
                 ? (gidx ? Ab + (size_t)gidx[gm1] * p.lda
                         : Ab + (size_t)gm1 * p.lda)
                 : Ab;
  }
  bool a_v0 = (m0 + a_row0) < Meff;
  bool a_v1 = (m0 + a_row0 + 64) < Meff;

  int b_kp0 = tid >> 5, b_nq0 = (tid & 31) * 4;
  int b_kp1 = (tid + 256) >> 5, b_nq1 = ((tid + 256) & 31) * 4;
  auto bcol = [&](int n) -> int {
    if (p.mode == FM_GU) {
      int grp = n >> 4;
      int isup = (n >> 3) & 1;
      int cc = grp * 8 + (n & 7);
      return (isup ? FI : 0) + n0g + cc;  // FI == FSH
    }
    return n0 + n;
  };
  int b_c0 = bcol(b_nq0);
  int b_c1 = bcol(b_nq1);

  auto issue = [&](int it, int st) {
    if (it < nk) {
      int k0h = it << 5;
      cp_async16(
          as_base + (uint32_t)(st * F16_ASTW + a_row0 * HAPAD + a_kq) * 2u,
          a_src0 + k0h + a_kq, a_v0);
      cp_async16(
          as_base +
              (uint32_t)(st * F16_ASTW + (a_row0 + 64) * HAPAD + a_kq) * 2u,
          a_src1 + k0h + a_kq, a_v1);
      int kp0 = it << 4;
      cp_async16(bs_base + (uint32_t)(st * F16_BW + b_kp0 * 136 + b_nq0) * 4u,
                 Bw + (size_t)(kp0 + b_kp0) * p.ldbw + b_c0, true);
      cp_async16(bs_base + (uint32_t)(st * F16_BW + b_kp1 * 136 + b_nq1) * 4u,
                 Bw + (size_t)(kp0 + b_kp1) * p.ldbw + b_c1, true);
    }
    cp_commit();
  };

  issue(0, 0);
  issue(1, 1);
  issue(2, 2);

  int cur = 0;
  for (int it = 0; it < nk; it++) {
    cp_wait<F16_STAGES - 2>();
    __syncthreads();
    issue(it + 3, (cur + 3) & (F16_STAGES - 1));

    const uint32_t* Bsp = BsAll + cur * F16_BW;
#pragma unroll
    for (int ks = 0; ks < 2; ks++) {
      uint32_t afr[4][4];
#pragma unroll
      for (int mt = 0; mt < 4; mt++) {
        int row = warp_m * 64 + mt * 16 + (lane & 15);
        uint32_t saddr =
            as_base + (uint32_t)(cur * F16_ASTW + row * HAPAD + ks * 16 +
                                 ((lane >> 4) << 3)) *
                          2u;
        ldsm4(afr[mt], saddr);
      }
      uint32_t bfr[4][2];
      int kpb = ks * 8;
#pragma unroll
      for (int nt = 0; nt < 4; nt++) {
        int ncol = warp_n * 32 + nt * 8 + gid;
        bfr[nt][0] = Bsp[(kpb + tig) * 136 + ncol];
        bfr[nt][1] = Bsp[(kpb + 4 + tig) * 136 + ncol];
      }
#pragma unroll
      for (int mt = 0; mt < 4; mt++)
#pragma unroll
        for (int nt = 0; nt < 4; nt++) mma_f16(acc[mt][nt], afr[mt], bfr[nt]);
    }
    cur = (cur + 1) & (F16_STAGES - 1);
  }

  if (p.mode == FM_GU) {
#pragma unroll
    for (int mt = 0; mt < 4; mt++) {
#pragma unroll
      for (int q = 0; q < 2; q++) {
#pragma unroll
        for (int half_e = 0; half_e < 2; half_e++) {
          int gm = m0 + warp_m * 64 + mt * 16 + gid + half_e * 8;
          if (gm >= Meff) continue;
          float g0 = acc[mt][2 * q][half_e * 2 + 0];
          float g1 = acc[mt][2 * q][half_e * 2 + 1];
          float u0 = acc[mt][2 * q + 1][half_e * 2 + 0];
          float u1 = acc[mt][2 * q + 1][half_e * 2 + 1];
          float a0 = (g0 / (1.f + expf(-g0))) * u0;
          float a1 = (g1 / (1.f + expf(-g1))) * u1;
          int cc = n0g + (2 * warp_n + q) * 8 + tig * 2;
          __half2 h = __floats2half2_rn(a0, a1);
          *(__half2*)&Chb[(size_t)gm * p.ldc + cc] = h;
        }
      }
    }
  } else if (p.mode == FM_DN) {
#pragma unroll
    for (int mt = 0; mt < 4; mt++) {
#pragma unroll
      for (int nt = 0; nt < 4; nt++) {
#pragma unroll
        for (int ee = 0; ee < 4; ee++) {
          int gm = m0 + warp_m * 64 + mt * 16 + gid + (ee >= 2 ? 8 : 0);
          if (gm >= Meff) continue;
          int gn = n0 + warp_n * 32 + nt * 8 + tig * 2 + (ee & 1);
          int t = tokz[gm];
          float w = wz[gm];
          atomicAdd(&Cf[(size_t)t * p.ldc + gn], acc[mt][nt][ee] * w);
        }
      }
    }
  } else if (p.mode == FM_AV) {
#pragma unroll
    for (int mt = 0; mt < 4; mt++) {
#pragma unroll
      for (int nt = 0; nt < 4; nt++) {
#pragma unroll
        for (int he = 0; he < 2; he++) {
          int gm = m0 + warp_m * 64 + mt * 16 + gid + he * 8;
          if (gm >= Meff) continue;
          int gn = n0 + warp_n * 32 + nt * 8 + tig * 2;
          __half2 h =
              __floats2half2_rn(acc[mt][nt][he * 2], acc[mt][nt][he * 2 + 1]);
          *(__half2*)&Chb[(size_t)gm * p.ldc + gn] = h;
        }
      }
    }
  } else {
#pragma unroll
    for (int mt = 0; mt < 4; mt++) {
#pragma unroll
      for (int nt = 0; nt < 4; nt++) {
#pragma unroll
        for (int ee = 0; ee < 4; ee++) {
          int gm = m0 + warp_m * 64 + mt * 16 + gid + (ee >= 2 ? 8 : 0);
          if (gm >= Meff) continue;
          int gn = n0 + warp_n * 32 + nt * 8 + tig * 2 + (ee & 1);
          float v = acc[mt][nt][ee];
          if (p.mode == FM_QKV)
            v += p.bias[gn];
          else if (p.mode == FM_WO)
            v += p.resid[(size_t)gm * p.ldc + gn];
          else if (p.mode == FM_SC) {
            if (gn > gm) continue;
            v *= SCALE;
          }
          Cf[(size_t)gm * p.ldc + gn] = v;
        }
      }
    }
  }
}

// ---------------------------------------------------------------------------
// fp32 SIMT GEMM (tiny gate GEMM -> exact routing inputs)
// ---------------------------------------------------------------------------
struct GemmP {
  const float* A;
  const float* Bm;
  float* C;
  int M, N, K, lda, ldb, ldc;
};

__global__ __launch_bounds__(256) void gemm_kernel(GemmP p) {
  const float* Ab = p.A;
  const float* Bb = p.Bm;
  float* Cb = p.C;
  int Meff = p.M;

  int m0 = blockIdx.y * 64, n0 = blockIdx.x * 64;
  if (m0 >= Meff) return;

  __shared__ float As[16][68];
  __shared__ float Bs[16][68];
  int tid = threadIdx.x, tx = tid & 15, ty = tid >> 4;
  float acc[4][4] = {};

  for (int k0 = 0; k0 < p.K; k0 += 16) {
#pragma unroll
    for (int l = 0; l < 4; l++) {
      int i = tid + l * 256;
      int row = i >> 4, col = i & 15;
      int gm = m0 + row;
      float v = 0.f;
      if (gm < Meff) v = Ab[(size_t)gm * p.lda + k0 + col];
      As[col][row] = v;
    }
#pragma unroll
    for (int l = 0; l < 4; l++) {
      int i = tid + l * 256;
      int col = i >> 4, kk = i & 15;
      Bs[kk][col] = Bb[(size_t)(n0 + col) * p.ldb + (k0 + kk)];
    }
    __syncthreads();
#pragma unroll
    for (int kk = 0; kk < 16; kk++) {
      float4 a4 = *(const float4*)(&As[kk][ty * 4]);
      float4 b4 = *(const float4*)(&Bs[kk][tx * 4]);
      float av[4] = {a4.x, a4.y, a4.z, a4.w};
      float bv[4] = {b4.x, b4.y, b4.z, b4.w};
#pragma unroll
      for (int i = 0; i < 4; i++)
#pragma unroll
        for (int j = 0; j < 4; j++) acc[i][j] += av[i] * bv[j];
    }
    __syncthreads();
  }

#pragma unroll
  for (int i = 0; i < 4; i++) {
    int gm = m0 + ty * 4 + i;
    if (gm >= Meff) continue;
#pragma unroll
    for (int j = 0; j < 4; j++) {
      int gn = n0 + tx * 4 + j;
      Cb[(size_t)gm * p.ldc + gn] = acc[i][j];
    }
  }
}

// ---------------------------------------------------------------------------
// Row softmax: read fp32 scores, write fp16 probs (causal-aware fill)
// ---------------------------------------------------------------------------
__global__ void softmax_kernel(const float* __restrict__ sc,
                               __half* __restrict__ pr) {
  size_t row = blockIdx.x;
  int q = (int)(row & (S - 1));
  int len = q + 1;
  int fill_end = ((q >> 7) + 1) << 7;
  const float* p = sc + row * (size_t)S;
  __half* po = pr + row * (size_t)S;
  __shared__ float red[8];
  float mx = -INFINITY;
  for (int i = threadIdx.x; i < len; i += 256) mx = fmaxf(mx, p[i]);
  for (int o = 16; o; o >>= 1) mx = fmaxf(mx, __shfl_xor_sync(~0u, mx, o));
  if ((threadIdx.x & 31) == 0) red[threadIdx.x >> 5] = mx;
  __syncthreads();
  if (threadIdx.x == 0) {
    float m = red[0];
    for (int i = 1; i < 8; i++) m = fmaxf(m, red[i]);
    red[0] = m;
  }
  __syncthreads();
  mx = red[0];
  __syncthreads();
  float sum = 0.f;
  for (int i = threadIdx.x; i < len; i += 256) sum += expf(p[i] - mx);
  for (int o = 16; o; o >>= 1) sum += __shfl_xor_sync(~0u, sum, o);
  if ((threadIdx.x & 31) == 0) red[threadIdx.x >> 5] = sum;
  __syncthreads();
  if (threadIdx.x == 0) {
    float t = 0.f;
    for (int i = 0; i < 8; i++) t += red[i];
    red[0] = t;
  }
  __syncthreads();
  float inv = 1.f / red[0];
  for (int i = threadIdx.x; i < len; i += 256)
    po[i] = __float2half(expf(p[i] - mx) * inv);
  for (int i = len + threadIdx.x; i < fill_end; i += 256)
    po[i] = __float2half(0.f);
}

// ---------------------------------------------------------------------------
// Routing
// ---------------------------------------------------------------------------
__global__ void route_kernel(const float* __restrict__ logits,
                             const float* __restrict__ gate_b,
                             int* __restrict__ topi, float* __restrict__ fw) {
  int t = blockIdx.x * blockDim.x + threadIdx.x;
  if (t >= T) return;
  float corr[E];
  const float* lg = logits + (size_t)t * E;
  for (int e = 0; e < E; e++) {
    float s = 1.f / (1.f + expf(-lg[e]));
    corr[e] = s + gate_b[e];
  }
  float grp[NG];
  for (int g = 0; g < NG; g++) {
    float m1 = -INFINITY, m2 = -INFINITY;
    for (int i = 0; i < E / NG; i++) {
      float v = corr[g * (E / NG) + i];
      if (v > m1) {
        m2 = m1;
        m1 = v;
      } else if (v > m2) {
        m2 = v;
      }
    }
    grp[g] = m1 + m2;
  }
  unsigned gsel = 0;
  for (int it = 0; it < TG; it++) {
    float best = -INFINITY;
    int bi = 0;
    for (int g = 0; g < NG; g++)
      if (!((gsel >> g) & 1u) && grp[g] > best) {
        best = grp[g];
        bi = g;
      }
    gsel |= 1u << bi;
  }
  unsigned long long esel = 0ull;
  int sel[TK];
  float ws[TK];
  float wsum = 0.f;
  for (int it = 0; it < TK; it++) {
    float best = -INFINITY;
    int bi = 0;
    for (int e = 0; e < E; e++) {
      if (!((gsel >> (e >> 3)) & 1u)) continue;
      if ((esel >> e) & 1ull) continue;
      if (corr[e] > best) {
        best = corr[e];
        bi = e;
      }
    }
    esel |= 1ull << bi;
    sel[it] = bi;
    float s = corr[bi] - gate_b[bi];
    ws[it] = s;
    wsum += s;
  }
  float inv = 1.f / wsum;
  for (int j = 0; j < TK; j++) {
    topi[t * TK + j] = sel[j];
    fw[t * TK + j] = ws[j] * inv;
  }
}

__global__ void zero_cnt_kernel(int* __restrict__ cnt) {
  if (threadIdx.x < E) cnt[threadIdx.x] = 0;
}

__global__ void assign_kernel(const int* __restrict__ topi,
                              const float* __restrict__ fw,
                              int* __restrict__ cnt, int* __restrict__ tok,
                              float* __restrict__ wslot) {
  int i = blockIdx.x * blockDim.x + threadIdx.x;
  if (i >= T * TK) return;
  int e = topi[i];
  int p = atomicAdd(&cnt[e], 1);
  if (p < CAP) {
    tok[e * CAP + p] = i / TK;
    wslot[e * CAP + p] = fw[i];
  }
}

// ---------------------------------------------------------------------------
// Host launcher (multi-stream: big weight packs overlap the forward pass)
// ---------------------------------------------------------------------------
extern "C" void kernel_launch(void* const* d_in, const int* in_sizes, int n_in,
                              void* d_out, int out_size) {
  const float* x = (const float*)d_in[0];
  const int* positions = (const int*)d_in[1];
  const float* ln1_w = (const float*)d_in[2];
  const float* ln2_w = (const float*)d_in[3];
  const float* wqkv = (const float*)d_in[4];
  const float* bqkv = (const float*)d_in[5];
  const float* qn_w = (const float*)d_in[6];
  const float* kn_w = (const float*)d_in[7];
  const float* wo = (const float*)d_in[8];
  const float* gate_w = (const float*)d_in[9];
  const float* gate_b = (const float*)d_in[10];
  const float* w_gu = (const float*)d_in[11];
  const float* w_dn = (const float*)d_in[12];
  const float* sw_gu = (const float*)d_in[13];
  const float* sw_dn = (const float*)d_in[14];
  float* out = (float*)d_out;

  static bool init_done = false;
  static cudaStream_t s_side = nullptr;
  static cudaEvent_t ev_fork, ev_wo, ev_sh, ev_moe;
  if (!init_done) {
    cudaFuncSetAttribute(gemm_f16, cudaFuncAttributeMaxDynamicSharedMemorySize,
                         F16_DSMEM);
    cudaStreamCreateWithFlags(&s_side, cudaStreamNonBlocking);
    cudaEventCreateWithFlags(&ev_fork, cudaEventDisableTiming);
    cudaEventCreateWithFlags(&ev_wo, cudaEventDisableTiming);
    cudaEventCreateWithFlags(&ev_sh, cudaEventDisableTiming);
    cudaEventCreateWithFlags(&ev_moe, cudaEventDisableTiming);
    init_done = true;
  }

  float* scr = nullptr;
  cudaGetSymbolAddress((void**)&scr, g_scratch);
  int* topi = nullptr;
  cudaGetSymbolAddress((void**)&topi, g_topi);
  int* cnt = nullptr;
  cudaGetSymbolAddress((void**)&cnt, g_cnt);
  int* tok = nullptr;
  cudaGetSymbolAddress((void**)&tok, g_tok);
  float* wslot = nullptr;
  cudaGetSymbolAddress((void**)&wslot, g_wslot);
  __half* xt16 = nullptr;
  cudaGetSymbolAddress((void**)&xt16, g_xt16);
  __half* bh16 = nullptr;
  cudaGetSymbolAddress((void**)&bh16, g_bh16);
  __half* q16 = nullptr;
  cudaGetSymbolAddress((void**)&q16, g_q16);
  __half* aout16 = nullptr;
  cudaGetSymbolAddress((void**)&aout16, g_aout16);
  __half* shact16 = nullptr;
  cudaGetSymbolAddress((void**)&shact16, g_shact16);
  __half* act16 = nullptr;
  cudaGetSymbolAddress((void**)&act16, g_act16);
  __half* sc16 = nullptr;
  cudaGetSymbolAddress((void**)&sc16, g_sc16);
  uint32_t* k16p = nullptr;
  cudaGetSymbolAddress((void**)&k16p, g_k16p);
  uint32_t* v16p = nullptr;
  cudaGetSymbolAddress((void**)&v16p, g_v16p);
  uint32_t* wgu16 = nullptr;
  cudaGetSymbolAddress((void**)&wgu16, g_wgu16);
  uint32_t* wdn16 = nullptr;
  cudaGetSymbolAddress((void**)&wdn16, g_wdn16);
  uint32_t* wqkv16 = nullptr;
  cudaGetSymbolAddress((void**)&wqkv16, g_wqkv16);
  uint32_t* wo16 = nullptr;
  cudaGetSymbolAddress((void**)&wo16, g_wo16);
  uint32_t* sgu16 = nullptr;
  cudaGetSymbolAddress((void**)&sgu16, g_sgu16);
  uint32_t* sdn16 = nullptr;
  cudaGetSymbolAddress((void**)&sdn16, g_sdn16);

  float* bqkvb = scr + OFF_QKV;
  float* bsc = scr + OFF_SC;
  float* bh2 = scr + OFF_H2;
  float* bxt = scr + OFF_XT;
  float* blog = scr + OFF_LOG;
  float* bfw = scr + OFF_FW;

  // ---- fork: side stream packs the non-immediate weights ----
  cudaEventRecord(ev_fork, 0);
  cudaStreamWaitEvent(s_side, ev_fork, 0);
  pack_tr<<<dim3(H / 32, (NH * D) / 64), 256, 0, s_side>>>(wo, wo16, H,
                                                           NH * D);
  cudaEventRecord(ev_wo, s_side);
  pack_nn4<<<dim3((2 * FSH) / 1024, H / 2, 1), 256, 0, s_side>>>(
      sw_gu, sgu16, 2 * FSH, H);
  pack_nn4<<<dim3(H / 1024, FSH / 2, 1), 256, 0, s_side>>>(sw_dn, sdn16, H,
                                                           FSH);
  cudaEventRecord(ev_sh, s_side);
  pack_nn4<<<dim3((2 * FI) / 1024, H / 2, E), 256, 0, s_side>>>(w_gu, wgu16,
                                                                2 * FI, H);
  pack_nn4<<<dim3(H / 1024, FI / 2, E), 256, 0, s_side>>>(w_dn, wdn16, H, FI);
  cudaEventRecord(ev_moe, s_side);

  // ---- main stream ----
  pack_tr<<<dim3(QKVW / 32, H / 64), 256>>>(wqkv, wqkv16, QKVW, H);

  // 1. rmsnorm1 (fp16 only)
  rmsnorm_kernel<<<T, 256>>>(x, ln1_w, nullptr, bh16, H);

  // 2. qkv (fp16)
  {
    F16P p{};
    p.mode = FM_QKV;
    p.A = bh16; p.Bw = wqkv16; p.Cf = bqkvb; p.bias = bqkv;
    p.lda = H; p.ldbw = QKVW; p.ldc = QKVW; p.K = H; p.M = T;
    gemm_f16<<<dim3(QKVW / 128, T / 128, 1), 256, F16_DSMEM>>>(p);
  }

  // 3. q/k rmsnorm + rope -> q16, k16p ; pack v
  qknorm_rope_kernel<<<dim3(T, NH + NKV), 128>>>(bqkvb, positions, qn_w, kn_w,
                                                 q16, k16p);
  pack_v<<<dim3(S / 2, B * NKV), 128>>>(bqkvb, v16p);

  // 4. scores (fp16) -> fp32 bsc
  {
    F16P p{};
    p.mode = FM_SC;
    p.A = q16; p.Bw = k16p; p.Cf = bsc;
    p.lda = NH * D; p.ldbw = S; p.ldc = S; p.K = D; p.M = S;
    gemm_f16<<<dim3(S / 128, S / 128, B * NH), 256, F16_DSMEM>>>(p);
  }

  // 5. softmax -> fp16 probs
  softmax_kernel<<<B * NH * S, 256>>>(bsc, sc16);

  // 6. attn @ v (fp16) -> aout16
  {
    F16P p{};
    p.mode = FM_AV;
    p.A = sc16; p.Bw = v16p; p.Ch = aout16;
    p.lda = S; p.ldbw = D; p.ldc = NH * D; p.K = S; p.M = S;
    gemm_f16<<<dim3(1, S / 128, B * NH), 256, F16_DSMEM>>>(p);
  }

  // 7. h2 = x + aout @ wo^T  (needs wo16)
  cudaStreamWaitEvent(0, ev_wo, 0);
  {
    F16P p{};
    p.mode = FM_WO;
    p.A = aout16; p.Bw = wo16; p.Cf = bh2; p.resid = x;
    p.lda = NH * D; p.ldbw = H; p.ldc = H; p.K = NH * D; p.M = T;
    gemm_f16<<<dim3(H / 128, T / 128, 1), 256, F16_DSMEM>>>(p);
  }

  // 8. rmsnorm2 (fp32 + fp16)
  rmsnorm_kernel<<<T, 256>>>(bh2, ln2_w, bxt, xt16, H);

  // 9. gate logits (exact fp32)
  {
    GemmP p{};
    p.A = bxt; p.Bm = gate_w; p.C = blog;
    p.M = T; p.N = E; p.K = H;
    p.lda = H; p.ldb = H; p.ldc = E;
    gemm_kernel<<<dim3(1, T / 64, 1), 256>>>(p);
  }

  // 10. routing
  route_kernel<<<T / 256, 256>>>(blog, gate_b, topi, bfw);
  zero_cnt_kernel<<<1, 64>>>(cnt);
  assign_kernel<<<(T * TK) / 256, 256>>>(topi, bfw, cnt, tok, wslot);

  // 11. shared expert (needs sgu16/sdn16): GU+SiLU -> shact16; down -> out
  cudaStreamWaitEvent(0, ev_sh, 0);
  {
    F16P p{};
    p.mode = FM_GU;
    p.A = xt16; p.Bw = sgu16; p.Ch = shact16;
    p.lda = H; p.ldbw = 2 * FSH; p.ldc = FSH; p.K = H; p.M = T;
    gemm_f16<<<dim3(FSH / 64, T / 128, 1), 256, F16_DSMEM>>>(p);
  }
  {
    F16P p{};
    p.mode = FM_WO;
    p.A = shact16; p.Bw = sdn16; p.Cf = out; p.resid = bh2;
    p.lda = FSH; p.ldbw = H; p.ldc = H; p.K = FSH; p.M = T;
    gemm_f16<<<dim3(H / 128, T / 128, 1), 256, F16_DSMEM>>>(p);
  }

  // 12. MoE up-gate (needs wgu16) fused SiLU -> act16
  cudaStreamWaitEvent(0, ev_moe, 0);
  {
    F16P p{};
    p.mode = FM_GU;
    p.A = xt16; p.Bw = wgu16; p.Ch = act16;
    p.gidx = tok; p.cnt = cnt;
    p.lda = H; p.ldbw = 2 * FI; p.ldc = FI; p.K = H; p.M = CAP;
    p.a_zs = 0; p.b_zs = (long long)(H / 2) * (2 * FI);
    p.c_zs = (long long)CAP * FI;
    gemm_f16<<<dim3(FI / 64, CAP / 128, E), 256, F16_DSMEM>>>(p);
  }

  // 13. MoE down, scatter-accumulate directly into out
  {
    F16P p{};
    p.mode = FM_DN;
    p.A = act16; p.Bw = wdn16; p.Cf = out;
    p.gidx = tok; p.cnt = cnt; p.wslot = wslot;
    p.lda = FI; p.ldbw = H; p.ldc = H; p.K = FI; p.M = CAP;
    p.a_zs = (long long)CAP * FI; p.b_zs = (long long)(FI / 2) * H; p.c_zs = 0;
    gemm_f16<<<dim3(H / 128, CAP / 128, E), 256, F16_DSMEM>>>(p);
  }
}

// round 16
// speedup vs baseline: 1.3469x; 1.0780x over previous
#include <cuda_runtime.h>
#include <cuda_fp16.h>
#include <math.h>
#include <stdint.h>

namespace cfg {
constexpr int B = 2, S = 1024, H = 1024;
constexpr int NH = 8, NKV = 2, D = 128, ROT = 64;
constexpr int E = 64, TK = 8, NG = 8, TG = 4;
constexpr int FI = 512, FSH = 512, CAP = 512;
constexpr int T = B * S;
constexpr int QKVW = (NH + 2 * NKV) * D;  // 1536
constexpr float EPS = 1e-5f;
constexpr float SCALE = 0.08838834764831843f;
constexpr float THETA = 10000.0f;
}  // namespace cfg
using namespace cfg;

// ---------------------------------------------------------------------------
// Static device scratch
// ---------------------------------------------------------------------------
constexpr size_t N_QKV  = (size_t)T * QKVW;
constexpr size_t N_SC   = (size_t)B * NH * S * S;
constexpr size_t N_H2   = (size_t)T * H;
constexpr size_t N_XT   = (size_t)T * H;
constexpr size_t N_LOG  = (size_t)T * E;
constexpr size_t N_FW   = (size_t)T * TK;

constexpr size_t OFF_QKV  = 0;
constexpr size_t OFF_SC   = OFF_QKV + N_QKV;
constexpr size_t OFF_H2   = OFF_SC + N_SC;
constexpr size_t OFF_XT   = OFF_H2 + N_H2;
constexpr size_t OFF_LOG  = OFF_XT + N_XT;
constexpr size_t OFF_FW   = OFF_LOG + N_LOG;
constexpr size_t SCRATCH_F = OFF_FW + N_FW;

__device__ float g_scratch[SCRATCH_F];
__device__ __half g_xt16[(size_t)T * H];
__device__ __half g_bh16[(size_t)T * H];
__device__ __half g_q16[(size_t)T * NH * D];
__device__ __half g_aout16[(size_t)T * NH * D];
__device__ __half g_shact16[(size_t)T * FSH];
__device__ __half g_act16[(size_t)E * CAP * FI];
__device__ __half g_sc16[(size_t)B * NH * S * S];
__device__ uint32_t g_k16p[(size_t)B * NKV * (D / 2) * S];
__device__ uint32_t g_v16p[(size_t)B * NKV * (S / 2) * D];

// packed fp16 weights: word[kp][n] = (w[2kp][n], w[2kp+1][n])
__device__ uint32_t g_wgu16[(size_t)E * (H / 2) * (2 * FI)];
__device__ uint32_t g_wdn16[(size_t)E * (FI / 2) * H];
__device__ uint32_t g_wqkv16[(size_t)(H / 2) * QKVW];      // transposed
__device__ uint32_t g_wo16[(size_t)(NH * D / 2) * H];      // transposed
__device__ uint32_t g_sgu16[(size_t)(H / 2) * (2 * FSH)];
__device__ uint32_t g_sdn16[(size_t)(FSH / 2) * H];

__device__ int g_topi[T * TK];
__device__ int g_cnt[E];
__device__ int g_tok[E * CAP];
__device__ float g_wslot[E * CAP];

// ---------------------------------------------------------------------------
// helpers
// ---------------------------------------------------------------------------
__device__ __forceinline__ uint32_t h2u(__half2 h) {
  return *reinterpret_cast<uint32_t*>(&h);
}

__device__ __forceinline__ void mma_f16(float c[4], const uint32_t a[4],
                                        const uint32_t b[2]) {
  asm volatile(
      "mma.sync.aligned.m16n8k16.row.col.f32.f16.f16.f32 "
      "{%0,%1,%2,%3}, {%4,%5,%6,%7}, {%8,%9}, {%0,%1,%2,%3};\n"
      : "+f"(c[0]), "+f"(c[1]), "+f"(c[2]), "+f"(c[3])
      : "r"(a[0]), "r"(a[1]), "r"(a[2]), "r"(a[3]), "r"(b[0]), "r"(b[1]));
}

__device__ __forceinline__ void ldsm4(uint32_t r[4], uint32_t saddr) {
  asm volatile(
      "ldmatrix.sync.aligned.m8n8.x4.shared.b16 {%0,%1,%2,%3}, [%4];"
      : "=r"(r[0]), "=r"(r[1]), "=r"(r[2]), "=r"(r[3])
      : "r"(saddr));
}

__device__ __forceinline__ void cp_async16(uint32_t dst, const void* src,
                                           bool pred) {
  int sz = pred ? 16 : 0;
  asm volatile("cp.async.cg.shared.global [%0], [%1], 16, %2;\n" ::"r"(dst),
               "l"(src), "r"(sz));
}
__device__ __forceinline__ void cp_commit() {
  asm volatile("cp.async.commit_group;\n");
}
template <int N>
__device__ __forceinline__ void cp_wait() {
  asm volatile("cp.async.wait_group %0;\n" ::"n"(N));
}

// ---------------------------------------------------------------------------
// Weight packing kernels
// ---------------------------------------------------------------------------
__global__ void pack_nn4(const float* __restrict__ in,
                         uint32_t* __restrict__ out, int N, int Ktot) {
  size_t zi = (size_t)blockIdx.z * Ktot * N;
  size_t zo = (size_t)blockIdx.z * (Ktot / 2) * N;
  int n4 = (blockIdx.x * 256 + threadIdx.x) * 4;
  int kp = blockIdx.y;
  float4 a = *(const float4*)&in[zi + (size_t)(2 * kp) * N + n4];
  float4 b = *(const float4*)&in[zi + (size_t)(2 * kp + 1) * N + n4];
  uint4 o;
  o.x = h2u(__floats2half2_rn(a.x, b.x));
  o.y = h2u(__floats2half2_rn(a.y, b.y));
  o.z = h2u(__floats2half2_rn(a.z, b.z));
  o.w = h2u(__floats2half2_rn(a.w, b.w));
  *(uint4*)&out[zo + (size_t)kp * N + n4] = o;
}

// TR: in [N][K] -> out [K/2][N]
__global__ void pack_tr(const float* __restrict__ in, uint32_t* __restrict__ out,
                        int N, int K) {
  __shared__ float s[32][65];
  int n0 = blockIdx.x * 32, k0 = blockIdx.y * 64;
  int tid = threadIdx.x;
#pragma unroll
  for (int l = 0; l < 8; l++) {
    int idx = tid + l * 256;
    int r = idx >> 6, c = idx & 63;
    s[r][c] = in[(size_t)(n0 + r) * K + k0 + c];
  }
  __syncthreads();
#pragma unroll
  for (int l = 0; l < 4; l++) {
    int idx = tid + l * 256;
    int i = idx >> 5, j = idx & 31;
    out[(size_t)(k0 / 2 + i) * N + n0 + j] =
        h2u(__floats2half2_rn(s[j][2 * i], s[j][2 * i + 1]));
  }
}

// pack V from qkv: word[zb][tp][d] = (v[2tp][d], v[2tp+1][d])
__global__ void pack_v(const float* __restrict__ qkv,
                       uint32_t* __restrict__ v16p) {
  int d = threadIdx.x;
  int tp = blockIdx.x;
  int zb = blockIdx.y;
  int b = zb >> 1, kv = zb & 1;
  size_t base =
      (size_t)(b * S + 2 * tp) * QKVW + (size_t)(NH + NKV) * D + kv * D + d;
  float v0 = qkv[base];
  float v1 = qkv[base + QKVW];
  v16p[((size_t)zb * (S / 2) + tp) * D + d] = h2u(__floats2half2_rn(v0, v1));
}

// ---------------------------------------------------------------------------
// RMSNorm (fp32 out optional, packed fp16 out optional)
// ---------------------------------------------------------------------------
__global__ void rmsnorm_kernel(const float* __restrict__ in,
                               const float* __restrict__ w,
                               float* __restrict__ out,
                               __half* __restrict__ out16, int dim) {
  int t = blockIdx.x;
  const float* r = in + (size_t)t * dim;
  float s = 0.f;
  for (int i = threadIdx.x; i < dim; i += 256) {
    float v = r[i];
    s += v * v;
  }
  for (int o = 16; o; o >>= 1) s += __shfl_xor_sync(~0u, s, o);
  __shared__ float red[8];
  if ((threadIdx.x & 31) == 0) red[threadIdx.x >> 5] = s;
  __syncthreads();
  if (threadIdx.x == 0) {
    float tt = 0.f;
    for (int i = 0; i < 8; i++) tt += red[i];
    red[0] = tt;
  }
  __syncthreads();
  float inv = rsqrtf(red[0] / (float)dim + EPS);
  for (int i = threadIdx.x * 2; i < dim; i += 512) {
    float v0 = r[i] * inv * w[i];
    float v1 = r[i + 1] * inv * w[i + 1];
    if (out) {
      out[(size_t)t * dim + i] = v0;
      out[(size_t)t * dim + i + 1] = v1;
    }
    if (out16) {
      __half2 h = __floats2half2_rn(v0, v1);
      *(__half2*)&out16[(size_t)t * dim + i] = h;
    }
  }
}

// ---------------------------------------------------------------------------
// Per-head Q/K RMSNorm + RoPE -> q16 (row fp16) and k16p (d-pair packed)
// ---------------------------------------------------------------------------
__global__ void qknorm_rope_kernel(const float* __restrict__ qkv,
                                   const int* __restrict__ positions,
                                   const float* __restrict__ qn,
                                   const float* __restrict__ kn,
                                   __half* __restrict__ q16,
                                   uint32_t* __restrict__ k16p) {
  int t = blockIdx.x, hh = blockIdx.y, d = threadIdx.x;
  const float* src;
  const float* w;
  if (hh < NH) {
    src = qkv + (size_t)t * QKVW + hh * D;
    w = qn;
  } else {
    int kv = hh - NH;
    src = qkv + (size_t)t * QKVW + NH * D + kv * D;
    w = kn;
  }
  float v = src[d];
  float s = v * v;
  for (int o = 16; o; o >>= 1) s += __shfl_xor_sync(~0u, s, o);
  __shared__ float red[4];
  if ((d & 31) == 0) red[d >> 5] = s;
  __syncthreads();
  float tot = red[0] + red[1] + red[2] + red[3];
  float nv = v * rsqrtf(tot / (float)D + EPS) * w[d];
  __shared__ float sh[128];
  __shared__ float sh2[128];
  sh[d] = nv;
  __syncthreads();
  int sidx = t & (S - 1);
  float pos = (float)positions[sidx];
  float res;
  if (d < ROT / 2) {
    float ang = pos * powf(THETA, -(float)d / (float)(ROT / 2));
    res = sh[d] * cosf(ang) - sh[d + ROT / 2] * sinf(ang);
  } else if (d < ROT) {
    int i2 = d - ROT / 2;
    float ang = pos * powf(THETA, -(float)i2 / (float)(ROT / 2));
    res = sh[d] * cosf(ang) + sh[d - ROT / 2] * sinf(ang);
  } else {
    res = nv;
  }
  if (hh < NH) {
    q16[((size_t)t * NH + hh) * D + d] = __float2half(res);
  } else {
    sh2[d] = res;
    __syncthreads();
    if (d < D / 2) {
      int kv = hh - NH;
      int b = t >> 10;  // S = 1024
      k16p[((size_t)(b * NKV + kv) * (D / 2) + d) * S + sidx] =
          h2u(__floats2half2_rn(sh2[2 * d], sh2[2 * d + 1]));
    }
  }
}

// ---------------------------------------------------------------------------
// Unified fp16 GEMM over packed-word B operands, 4-stage cp.async pipeline.
// ---------------------------------------------------------------------------
enum F16Mode { FM_GU = 0, FM_DN, FM_QKV, FM_WO, FM_SC, FM_AV };

struct F16P {
  int mode;
  const __half* A;
  const uint32_t* Bw;
  __half* Ch;
  float* Cf;
  const float* bias;
  const float* resid;
  const int* gidx;
  const int* cnt;
  const float* wslot;
  int lda, ldbw, ldc, K, M;
  long long a_zs, b_zs, c_zs;  // b_zs in words
};

constexpr int HAPAD = 40;
constexpr int F16_ASTW = 128 * HAPAD;
constexpr int F16_BW = 16 * 136;
constexpr int F16_STAGES = 4;
constexpr int F16_DSMEM = F16_STAGES * (F16_ASTW * 2 + F16_BW * 4);

extern __shared__ uint32_t dynsmem[];

__global__ __launch_bounds__(256, 2) void gemm_f16(F16P p) {
  int z = blockIdx.z;
  int Meff = p.cnt ? min(p.cnt[z], CAP) : p.M;
  int m0 = blockIdx.y * 128;
  if (m0 >= Meff) return;
  int n0 = blockIdx.x * 128;
  int n0g = blockIdx.x * 64;
  if (p.mode == FM_SC && n0 > m0 + 127) return;

  const __half* Ab;
  const uint32_t* Bw;
  float* Cf = p.Cf;
  __half* Chb = p.Ch;
  if (p.mode == FM_SC) {
    int b = z >> 3, h = z & 7;
    Ab = p.A + ((size_t)(b * S) * NH + h) * D;
    Bw = p.Bw + (size_t)(b * NKV + (h >> 2)) * (D / 2) * S;
    Cf = p.Cf + (size_t)z * S * S;
  } else if (p.mode == FM_AV) {
    int b = z >> 3, h = z & 7;
    Ab = p.A + (size_t)z * S * S;
    Bw = p.Bw + (size_t)(b * NKV + (h >> 2)) * (S / 2) * D;
    Chb = p.Ch + ((size_t)(b * S) * NH + h) * D;
  } else {
    Ab = p.A + (size_t)z * p.a_zs;
    Bw = p.Bw + (size_t)z * p.b_zs;
    if (p.Ch) Chb = p.Ch + (size_t)z * p.c_zs;
  }
  const int* gidx = (p.mode == FM_GU && p.gidx) ? p.gidx + z * CAP : nullptr;
  const int* tokz = (p.mode == FM_DN) ? p.gidx + z * CAP : nullptr;
  const float* wz = (p.mode == FM_DN) ? p.wslot + z * CAP : nullptr;

  uint32_t* BsAll = dynsmem + (F16_STAGES * F16_ASTW / 2);

  int tid = threadIdx.x;
  int lane = tid & 31, wid = tid >> 5;
  int warp_m = wid & 1, warp_n = wid >> 1;
  int gid = lane >> 2, tig = lane & 3;

  uint32_t as_base = (uint32_t)__cvta_generic_to_shared(dynsmem);
  uint32_t bs_base = (uint32_t)__cvta_generic_to_shared(BsAll);

  int kend = p.K;
  if (p.mode == FM_AV) kend = min(p.K, m0 + 128);
  int nk = kend >> 5;

  float acc[4][4][4];
#pragma unroll
  for (int a = 0; a < 4; a++)
#pragma unroll
    for (int b = 0; b < 4; b++)
#pragma unroll
      for (int c = 0; c < 4; c++) acc[a][b][c] = 0.f;

  int a_row0 = tid >> 2, a_kq = (tid & 3) * 8;
  const __half* a_src0;
  const __half* a_src1;
  {
    int gm0 = m0 + a_row0, gm1 = m0 + a_row0 + 64;
    a_src0 = (gm0 < Meff)
                 ? (gidx ? Ab + (size_t)gidx[gm0] * p.lda
                         : Ab + (size_t)gm0 * p.lda)
                 : Ab;
    a_src1 = (gm1 < Meff)
                 ? (gidx ? Ab + (size_t)gidx[gm1] * p.lda
                         : Ab + (size_t)gm1 * p.lda)
                 : Ab;
  }
  bool a_v0 = (m0 + a_row0) < Meff;
  bool a_v1 = (m0 + a_row0 + 64) < Meff;

  int b_kp0 = tid >> 5, b_nq0 = (tid & 31) * 4;
  int b_kp1 = (tid + 256) >> 5, b_nq1 = ((tid + 256) & 31) * 4;
  auto bcol = [&](int n) -> int {
    if (p.mode == FM_GU) {
      int grp = n >> 4;
      int isup = (n >> 3) & 1;
      int cc = grp * 8 + (n & 7);
      return (isup ? FI : 0) + n0g + cc;  // FI == FSH
    }
    return n0 + n;
  };
  int b_c0 = bcol(b_nq0);
  int b_c1 = bcol(b_nq1);

  auto issue = [&](int it, int st) {
    if (it < nk) {
      int k0h = it << 5;
      cp_async16(
          as_base + (uint32_t)(st * F16_ASTW + a_row0 * HAPAD + a_kq) * 2u,
          a_src0 + k0h + a_kq, a_v0);
      cp_async16(
          as_base +
              (uint32_t)(st * F16_ASTW + (a_row0 + 64) * HAPAD + a_kq) * 2u,
          a_src1 + k0h + a_kq, a_v1);
      int kp0 = it << 4;
      cp_async16(bs_base + (uint32_t)(st * F16_BW + b_kp0 * 136 + b_nq0) * 4u,
                 Bw + (size_t)(kp0 + b_kp0) * p.ldbw + b_c0, true);
      cp_async16(bs_base + (uint32_t)(st * F16_BW + b_kp1 * 136 + b_nq1) * 4u,
                 Bw + (size_t)(kp0 + b_kp1) * p.ldbw + b_c1, true);
    }
    cp_commit();
  };

  issue(0, 0);
  issue(1, 1);
  issue(2, 2);

  int cur = 0;
  for (int it = 0; it < nk; it++) {
    cp_wait<F16_STAGES - 2>();
    __syncthreads();
    issue(it + 3, (cur + 3) & (F16_STAGES - 1));

    const uint32_t* Bsp = BsAll + cur * F16_BW;
#pragma unroll
    for (int ks = 0; ks < 2; ks++) {
      uint32_t afr[4][4];
#pragma unroll
      for (int mt = 0; mt < 4; mt++) {
        int row = warp_m * 64 + mt * 16 + (lane & 15);
        uint32_t saddr =
            as_base + (uint32_t)(cur * F16_ASTW + row * HAPAD + ks * 16 +
                                 ((lane >> 4) << 3)) *
                          2u;
        ldsm4(afr[mt], saddr);
      }
      uint32_t bfr[4][2];
      int kpb = ks * 8;
#pragma unroll
      for (int nt = 0; nt < 4; nt++) {
        int ncol = warp_n * 32 + nt * 8 + gid;
        bfr[nt][0] = Bsp[(kpb + tig) * 136 + ncol];
        bfr[nt][1] = Bsp[(kpb + 4 + tig) * 136 + ncol];
      }
#pragma unroll
      for (int mt = 0; mt < 4; mt++)
#pragma unroll
        for (int nt = 0; nt < 4; nt++) mma_f16(acc[mt][nt], afr[mt], bfr[nt]);
    }
    cur = (cur + 1) & (F16_STAGES - 1);
  }

  if (p.mode == FM_GU) {
#pragma unroll
    for (int mt = 0; mt < 4; mt++) {
#pragma unroll
      for (int q = 0; q < 2; q++) {
#pragma unroll
        for (int half_e = 0; half_e < 2; half_e++) {
          int gm = m0 + warp_m * 64 + mt * 16 + gid + half_e * 8;
          if (gm >= Meff) continue;
          float g0 = acc[mt][2 * q][half_e * 2 + 0];
          float g1 = acc[mt][2 * q][half_e * 2 + 1];
          float u0 = acc[mt][2 * q + 1][half_e * 2 + 0];
          float u1 = acc[mt][2 * q + 1][half_e * 2 + 1];
          float a0 = (g0 / (1.f + expf(-g0))) * u0;
          float a1 = (g1 / (1.f + expf(-g1))) * u1;
          int cc = n0g + (2 * warp_n + q) * 8 + tig * 2;
          __half2 h = __floats2half2_rn(a0, a1);
          *(__half2*)&Chb[(size_t)gm * p.ldc + cc] = h;
        }
      }
    }
  } else if (p.mode == FM_DN) {
#pragma unroll
    for (int mt = 0; mt < 4; mt++) {
#pragma unroll
      for (int nt = 0; nt < 4; nt++) {
#pragma unroll
        for (int ee = 0; ee < 4; ee++) {
          int gm = m0 + warp_m * 64 + mt * 16 + gid + (ee >= 2 ? 8 : 0);
          if (gm >= Meff) continue;
          int gn = n0 + warp_n * 32 + nt * 8 + tig * 2 + (ee & 1);
          int t = tokz[gm];
          float w = wz[gm];
          atomicAdd(&Cf[(size_t)t * p.ldc + gn], acc[mt][nt][ee] * w);
        }
      }
    }
  } else if (p.mode == FM_AV) {
#pragma unroll
    for (int mt = 0; mt < 4; mt++) {
#pragma unroll
      for (int nt = 0; nt < 4; nt++) {
#pragma unroll
        for (int he = 0; he < 2; he++) {
          int gm = m0 + warp_m * 64 + mt * 16 + gid + he * 8;
          if (gm >= Meff) continue;
          int gn = n0 + warp_n * 32 + nt * 8 + tig * 2;
          __half2 h =
              __floats2half2_rn(acc[mt][nt][he * 2], acc[mt][nt][he * 2 + 1]);
          *(__half2*)&Chb[(size_t)gm * p.ldc + gn] = h;
        }
      }
    }
  } else {
#pragma unroll
    for (int mt = 0; mt < 4; mt++) {
#pragma unroll
      for (int nt = 0; nt < 4; nt++) {
#pragma unroll
        for (int ee = 0; ee < 4; ee++) {
          int gm = m0 + warp_m * 64 + mt * 16 + gid + (ee >= 2 ? 8 : 0);
          if (gm >= Meff) continue;
          int gn = n0 + warp_n * 32 + nt * 8 + tig * 2 + (ee & 1);
          float v = acc[mt][nt][ee];
          if (p.mode == FM_QKV)
            v += p.bias[gn];
          else if (p.mode == FM_WO)
            v += p.resid[(size_t)gm * p.ldc + gn];
          else if (p.mode == FM_SC) {
            if (gn > gm) continue;
            v *= SCALE;
          }
          Cf[(size_t)gm * p.ldc + gn] = v;
        }
      }
    }
  }
}

// ---------------------------------------------------------------------------
// fp32 SIMT GEMM (tiny gate GEMM -> exact routing inputs)
// ---------------------------------------------------------------------------
struct GemmP {
  const float* A;
  const float* Bm;
  float* C;
  int M, N, K, lda, ldb, ldc;
};

__global__ __launch_bounds__(256) void gemm_kernel(GemmP p) {
  const float* Ab = p.A;
  const float* Bb = p.Bm;
  float* Cb = p.C;
  int Meff = p.M;

  int m0 = blockIdx.y * 64, n0 = blockIdx.x * 64;
  if (m0 >= Meff) return;

  __shared__ float As[16][68];
  __shared__ float Bs[16][68];
  int tid = threadIdx.x, tx = tid & 15, ty = tid >> 4;
  float acc[4][4] = {};

  for (int k0 = 0; k0 < p.K; k0 += 16) {
#pragma unroll
    for (int l = 0; l < 4; l++) {
      int i = tid + l * 256;
      int row = i >> 4, col = i & 15;
      int gm = m0 + row;
      float v = 0.f;
      if (gm < Meff) v = Ab[(size_t)gm * p.lda + k0 + col];
      As[col][row] = v;
    }
#pragma unroll
    for (int l = 0; l < 4; l++) {
      int i = tid + l * 256;
      int col = i >> 4, kk = i & 15;
      Bs[kk][col] = Bb[(size_t)(n0 + col) * p.ldb + (k0 + kk)];
    }
    __syncthreads();
#pragma unroll
    for (int kk = 0; kk < 16; kk++) {
      float4 a4 = *(const float4*)(&As[kk][ty * 4]);
      float4 b4 = *(const float4*)(&Bs[kk][tx * 4]);
      float av[4] = {a4.x, a4.y, a4.z, a4.w};
      float bv[4] = {b4.x, b4.y, b4.z, b4.w};
#pragma unroll
      for (int i = 0; i < 4; i++)
#pragma unroll
        for (int j = 0; j < 4; j++) acc[i][j] += av[i] * bv[j];
    }
    __syncthreads();
  }

#pragma unroll
  for (int i = 0; i < 4; i++) {
    int gm = m0 + ty * 4 + i;
    if (gm >= Meff) continue;
#pragma unroll
    for (int j = 0; j < 4; j++) {
      int gn = n0 + tx * 4 + j;
      Cb[(size_t)gm * p.ldc + gn] = acc[i][j];
    }
  }
}

// ---------------------------------------------------------------------------
// Row softmax: read fp32 scores, write fp16 probs (causal-aware fill)
// ---------------------------------------------------------------------------
__global__ void softmax_kernel(const float* __restrict__ sc,
                               __half* __restrict__ pr) {
  size_t row = blockIdx.x;
  int q = (int)(row & (S - 1));
  int len = q + 1;
  int fill_end = ((q >> 7) + 1) << 7;
  const float* p = sc + row * (size_t)S;
  __half* po = pr + row * (size_t)S;
  __shared__ float red[8];
  float mx = -INFINITY;
  for (int i = threadIdx.x; i < len; i += 256) mx = fmaxf(mx, p[i]);
  for (int o = 16; o; o >>= 1) mx = fmaxf(mx, __shfl_xor_sync(~0u, mx, o));
  if ((threadIdx.x & 31) == 0) red[threadIdx.x >> 5] = mx;
  __syncthreads();
  if (threadIdx.x == 0) {
    float m = red[0];
    for (int i = 1; i < 8; i++) m = fmaxf(m, red[i]);
    red[0] = m;
  }
  __syncthreads();
  mx = red[0];
  __syncthreads();
  float sum = 0.f;
  for (int i = threadIdx.x; i < len; i += 256) sum += expf(p[i] - mx);
  for (int o = 16; o; o >>= 1) sum += __shfl_xor_sync(~0u, sum, o);
  if ((threadIdx.x & 31) == 0) red[threadIdx.x >> 5] = sum;
  __syncthreads();
  if (threadIdx.x == 0) {
    float t = 0.f;
    for (int i = 0; i < 8; i++) t += red[i];
    red[0] = t;
  }
  __syncthreads();
  float inv = 1.f / red[0];
  for (int i = threadIdx.x; i < len; i += 256)
    po[i] = __float2half(expf(p[i] - mx) * inv);
  for (int i = len + threadIdx.x; i < fill_end; i += 256)
    po[i] = __float2half(0.f);
}

// ---------------------------------------------------------------------------
// Routing
// ---------------------------------------------------------------------------
__global__ void route_kernel(const float* __restrict__ logits,
                             const float* __restrict__ gate_b,
                             int* __restrict__ topi, float* __restrict__ fw) {
  int t = blockIdx.x * blockDim.x + threadIdx.x;
  if (t >= T) return;
  float corr[E];
  const float* lg = logits + (size_t)t * E;
  for (int e = 0; e < E; e++) {
    float s = 1.f / (1.f + expf(-lg[e]));
    corr[e] = s + gate_b[e];
  }
  float grp[NG];
  for (int g = 0; g < NG; g++) {
    float m1 = -INFINITY, m2 = -INFINITY;
    for (int i = 0; i < E / NG; i++) {
      float v = corr[g * (E / NG) + i];
      if (v > m1) {
        m2 = m1;
        m1 = v;
      } else if (v > m2) {
        m2 = v;
      }
    }
    grp[g] = m1 + m2;
  }
  unsigned gsel = 0;
  for (int it = 0; it < TG; it++) {
    float best = -INFINITY;
    int bi = 0;
    for (int g = 0; g < NG; g++)
      if (!((gsel >> g) & 1u) && grp[g] > best) {
        best = grp[g];
        bi = g;
      }
    gsel |= 1u << bi;
  }
  unsigned long long esel = 0ull;
  int sel[TK];
  float ws[TK];
  float wsum = 0.f;
  for (int it = 0; it < TK; it++) {
    float best = -INFINITY;
    int bi = 0;
    for (int e = 0; e < E; e++) {
      if (!((gsel >> (e >> 3)) & 1u)) continue;
      if ((esel >> e) & 1ull) continue;
      if (corr[e] > best) {
        best = corr[e];
        bi = e;
      }
    }
    esel |= 1ull << bi;
    sel[it] = bi;
    float s = corr[bi] - gate_b[bi];
    ws[it] = s;
    wsum += s;
  }
  float inv = 1.f / wsum;
  for (int j = 0; j < TK; j++) {
    topi[t * TK + j] = sel[j];
    fw[t * TK + j] = ws[j] * inv;
  }
}

__global__ void zero_cnt_kernel(int* __restrict__ cnt) {
  if (threadIdx.x < E) cnt[threadIdx.x] = 0;
}

__global__ void assign_kernel(const int* __restrict__ topi,
                              const float* __restrict__ fw,
                              int* __restrict__ cnt, int* __restrict__ tok,
                              float* __restrict__ wslot) {
  int i = blockIdx.x * blockDim.x + threadIdx.x;
  if (i >= T * TK) return;
  int e = topi[i];
  int p = atomicAdd(&cnt[e], 1);
  if (p < CAP) {
    tok[e * CAP + p] = i / TK;
    wslot[e * CAP + p] = fw[i];
  }
}

// ---------------------------------------------------------------------------
// Host launcher (multi-stream: packs + shared expert overlap the main pass)
// ---------------------------------------------------------------------------
extern "C" void kernel_launch(void* const* d_in, const int* in_sizes, int n_in,
                              void* d_out, int out_size) {
  const float* x = (const float*)d_in[0];
  const int* positions = (const int*)d_in[1];
  const float* ln1_w = (const float*)d_in[2];
  const float* ln2_w = (const float*)d_in[3];
  const float* wqkv = (const float*)d_in[4];
  const float* bqkv = (const float*)d_in[5];
  const float* qn_w = (const float*)d_in[6];
  const float* kn_w = (const float*)d_in[7];
  const float* wo = (const float*)d_in[8];
  const float* gate_w = (const float*)d_in[9];
  const float* gate_b = (const float*)d_in[10];
  const float* w_gu = (const float*)d_in[11];
  const float* w_dn = (const float*)d_in[12];
  const float* sw_gu = (const float*)d_in[13];
  const float* sw_dn = (const float*)d_in[14];
  float* out = (float*)d_out;

  static bool init_done = false;
  static cudaStream_t s_side = nullptr;
  static cudaEvent_t ev_fork, ev_wo, ev_moe, ev_xt, ev_shdone;
  if (!init_done) {
    cudaFuncSetAttribute(gemm_f16, cudaFuncAttributeMaxDynamicSharedMemorySize,
                         F16_DSMEM);
    cudaStreamCreateWithFlags(&s_side, cudaStreamNonBlocking);
    cudaEventCreateWithFlags(&ev_fork, cudaEventDisableTiming);
    cudaEventCreateWithFlags(&ev_wo, cudaEventDisableTiming);
    cudaEventCreateWithFlags(&ev_moe, cudaEventDisableTiming);
    cudaEventCreateWithFlags(&ev_xt, cudaEventDisableTiming);
    cudaEventCreateWithFlags(&ev_shdone, cudaEventDisableTiming);
    init_done = true;
  }

  float* scr = nullptr;
  cudaGetSymbolAddress((void**)&scr, g_scratch);
  int* topi = nullptr;
  cudaGetSymbolAddress((void**)&topi, g_topi);
  int* cnt = nullptr;
  cudaGetSymbolAddress((void**)&cnt, g_cnt);
  int* tok = nullptr;
  cudaGetSymbolAddress((void**)&tok, g_tok);
  float* wslot = nullptr;
  cudaGetSymbolAddress((void**)&wslot, g_wslot);
  __half* xt16 = nullptr;
  cudaGetSymbolAddress((void**)&xt16, g_xt16);
  __half* bh16 = nullptr;
  cudaGetSymbolAddress((void**)&bh16, g_bh16);
  __half* q16 = nullptr;
  cudaGetSymbolAddress((void**)&q16, g_q16);
  __half* aout16 = nullptr;
  cudaGetSymbolAddress((void**)&aout16, g_aout16);
  __half* shact16 = nullptr;
  cudaGetSymbolAddress((void**)&shact16, g_shact16);
  __half* act16 = nullptr;
  cudaGetSymbolAddress((void**)&act16, g_act16);
  __half* sc16 = nullptr;
  cudaGetSymbolAddress((void**)&sc16, g_sc16);
  uint32_t* k16p = nullptr;
  cudaGetSymbolAddress((void**)&k16p, g_k16p);
  uint32_t* v16p = nullptr;
  cudaGetSymbolAddress((void**)&v16p, g_v16p);
  uint32_t* wgu16 = nullptr;
  cudaGetSymbolAddress((void**)&wgu16, g_wgu16);
  uint32_t* wdn16 = nullptr;
  cudaGetSymbolAddress((void**)&wdn16, g_wdn16);
  uint32_t* wqkv16 = nullptr;
  cudaGetSymbolAddress((void**)&wqkv16, g_wqkv16);
  uint32_t* wo16 = nullptr;
  cudaGetSymbolAddress((void**)&wo16, g_wo16);
  uint32_t* sgu16 = nullptr;
  cudaGetSymbolAddress((void**)&sgu16, g_sgu16);
  uint32_t* sdn16 = nullptr;
  cudaGetSymbolAddress((void**)&sdn16, g_sdn16);

  float* bqkvb = scr + OFF_QKV;
  float* bsc = scr + OFF_SC;
  float* bh2 = scr + OFF_H2;
  float* bxt = scr + OFF_XT;
  float* blog = scr + OFF_LOG;
  float* bfw = scr + OFF_FW;

  // ---- fork: side stream packs non-immediate weights, then shared expert ----
  cudaEventRecord(ev_fork, 0);
  cudaStreamWaitEvent(s_side, ev_fork, 0);
  pack_tr<<<dim3(H / 32, (NH * D) / 64), 256, 0, s_side>>>(wo, wo16, H,
                                                           NH * D);
  cudaEventRecord(ev_wo, s_side);
  pack_nn4<<<dim3((2 * FSH) / 1024, H / 2, 1), 256, 0, s_side>>>(
      sw_gu, sgu16, 2 * FSH, H);
  pack_nn4<<<dim3(H / 1024, FSH / 2, 1), 256, 0, s_side>>>(sw_dn, sdn16, H,
                                                           FSH);
  pack_nn4<<<dim3((2 * FI) / 1024, H / 2, E), 256, 0, s_side>>>(w_gu, wgu16,
                                                                2 * FI, H);
  pack_nn4<<<dim3(H / 1024, FI / 2, E), 256, 0, s_side>>>(w_dn, wdn16, H, FI);
  cudaEventRecord(ev_moe, s_side);

  // ---- main stream ----
  pack_tr<<<dim3(QKVW / 32, H / 64), 256>>>(wqkv, wqkv16, QKVW, H);

  // 1. rmsnorm1 (fp16 only)
  rmsnorm_kernel<<<T, 256>>>(x, ln1_w, nullptr, bh16, H);

  // 2. qkv (fp16)
  {
    F16P p{};
    p.mode = FM_QKV;
    p.A = bh16; p.Bw = wqkv16; p.Cf = bqkvb; p.bias = bqkv;
    p.lda = H; p.ldbw = QKVW; p.ldc = QKVW; p.K = H; p.M = T;
    gemm_f16<<<dim3(QKVW / 128, T / 128, 1), 256, F16_DSMEM>>>(p);
  }

  // 3. q/k rmsnorm + rope -> q16, k16p ; pack v
  qknorm_rope_kernel<<<dim3(T, NH + NKV), 128>>>(bqkvb, positions, qn_w, kn_w,
                                                 q16, k16p);
  pack_v<<<dim3(S / 2, B * NKV), 128>>>(bqkvb, v16p);

  // 4. scores (fp16) -> fp32 bsc
  {
    F16P p{};
    p.mode = FM_SC;
    p.A = q16; p.Bw = k16p; p.Cf = bsc;
    p.lda = NH * D; p.ldbw = S; p.ldc = S; p.K = D; p.M = S;
    gemm_f16<<<dim3(S / 128, S / 128, B * NH), 256, F16_DSMEM>>>(p);
  }

  // 5. softmax -> fp16 probs
  softmax_kernel<<<B * NH * S, 256>>>(bsc, sc16);

  // 6. attn @ v (fp16) -> aout16
  {
    F16P p{};
    p.mode = FM_AV;
    p.A = sc16; p.Bw = v16p; p.Ch = aout16;
    p.lda = S; p.ldbw = D; p.ldc = NH * D; p.K = S; p.M = S;
    gemm_f16<<<dim3(1, S / 128, B * NH), 256, F16_DSMEM>>>(p);
  }

  // 7. h2 = x + aout @ wo^T  (needs wo16)
  cudaStreamWaitEvent(0, ev_wo, 0);
  {
    F16P p{};
    p.mode = FM_WO;
    p.A = aout16; p.Bw = wo16; p.Cf = bh2; p.resid = x;
    p.lda = NH * D; p.ldbw = H; p.ldc = H; p.K = NH * D; p.M = T;
    gemm_f16<<<dim3(H / 128, T / 128, 1), 256, F16_DSMEM>>>(p);
  }

  // 8. rmsnorm2 (fp32 + fp16)
  rmsnorm_kernel<<<T, 256>>>(bh2, ln2_w, bxt, xt16, H);
  cudaEventRecord(ev_xt, 0);

  // ---- side stream: shared expert (after its packs, in-order) ----
  cudaStreamWaitEvent(s_side, ev_xt, 0);
  {
    F16P p{};
    p.mode = FM_GU;
    p.A = xt16; p.Bw = sgu16; p.Ch = shact16;
    p.lda = H; p.ldbw = 2 * FSH; p.ldc = FSH; p.K = H; p.M = T;
    gemm_f16<<<dim3(FSH / 64, T / 128, 1), 256, F16_DSMEM, s_side>>>(p);
  }
  {
    F16P p{};
    p.mode = FM_WO;
    p.A = shact16; p.Bw = sdn16; p.Cf = out; p.resid = bh2;
    p.lda = FSH; p.ldbw = H; p.ldc = H; p.K = FSH; p.M = T;
    gemm_f16<<<dim3(H / 128, T / 128, 1), 256, F16_DSMEM, s_side>>>(p);
  }
  cudaEventRecord(ev_shdone, s_side);

  // ---- main stream: gate + routing + MoE ----
  // 9. gate logits (exact fp32)
  {
    GemmP p{};
    p.A = bxt; p.Bm = gate_w; p.C = blog;
    p.M = T; p.N = E; p.K = H;
    p.lda = H; p.ldb = H; p.ldc = E;
    gemm_kernel<<<dim3(1, T / 64, 1), 256>>>(p);
  }

  // 10. routing
  route_kernel<<<T / 256, 256>>>(blog, gate_b, topi, bfw);
  zero_cnt_kernel<<<1, 64>>>(cnt);
  assign_kernel<<<(T * TK) / 256, 256>>>(topi, bfw, cnt, tok, wslot);

  // 12. MoE up-gate (needs wgu16) fused SiLU -> act16
  cudaStreamWaitEvent(0, ev_moe, 0);
  {
    F16P p{};
    p.mode = FM_GU;
    p.A = xt16; p.Bw = wgu16; p.Ch = act16;
    p.gidx = tok; p.cnt = cnt;
    p.lda = H; p.ldbw = 2 * FI; p.ldc = FI; p.K = H; p.M = CAP;
    p.a_zs = 0; p.b_zs = (long long)(H / 2) * (2 * FI);
    p.c_zs = (long long)CAP * FI;
    gemm_f16<<<dim3(FI / 64, CAP / 128, E), 256, F16_DSMEM>>>(p);
  }

  // 13. MoE down (after shared expert wrote `out`), scatter into out
  cudaStreamWaitEvent(0, ev_shdone, 0);
  {
    F16P p{};
    p.mode = FM_DN;
    p.A = act16; p.Bw = wdn16; p.Cf = out;
    p.gidx = tok; p.cnt = cnt; p.wslot = wslot;
    p.lda = FI; p.ldbw = H; p.ldc = H; p.K = FI; p.M = CAP;
    p.a_zs = (long long)CAP * FI; p.b_zs = (long long)(FI / 2) * H; p.c_zs = 0;
    gemm_f16<<<dim3(H / 128, CAP / 128, E), 256, F16_DSMEM>>>(p);
  }
}